// round 6
// baseline (speedup 1.0000x reference)
#include <cuda_runtime.h>
#include <cuda_bf16.h>
#include <math.h>

#define HID   768
#define INTER 1536
#define DK    128
#define BATCH 4
#define SEQ   2048
#define MTOT  (BATCH*SEQ)          // 8192
#define NCOLS (2*INTER+DK)         // 3200
#define LOG512F 6.2383246250395075f
#define GEMM_SMEM (3*4*512*16)     // 96 KB: 3 stages x 4 tiles x 8KB

typedef unsigned short u16;

// ---------------- scratch (device globals) ---------------------------------
__device__ u16   g_Hh[(size_t)MTOT*HID],   g_Hl[(size_t)MTOT*HID];
__device__ u16   g_Wih[(size_t)HID*NCOLS], g_Wil[(size_t)HID*NCOLS];
__device__ u16   g_Woh[(size_t)INTER*HID], g_Wol[(size_t)INTER*HID];
__device__ float g_u[(size_t)MTOT*INTER];
__device__ u16   g_vh[(size_t)MTOT*INTER], g_vl[(size_t)MTOT*INTER];
__device__ u16   g_qh[(size_t)MTOT*DK],    g_ql[(size_t)MTOT*DK];
__device__ u16   g_kh[(size_t)MTOT*DK],    g_kl[(size_t)MTOT*DK];
__device__ float g_A [(size_t)BATCH*SEQ*SEQ];
__device__ u16   g_Ah[(size_t)BATCH*SEQ*SEQ], g_Al[(size_t)BATCH*SEQ*SEQ];
__device__ u16   g_th[(size_t)MTOT*INTER], g_tl[(size_t)MTOT*INTER];

// ---------------- PTX helpers ----------------------------------------------
__device__ __forceinline__ void mma16816(float c[4], const unsigned a[4], const unsigned b[2]) {
    asm volatile(
        "mma.sync.aligned.m16n8k16.row.col.f32.bf16.bf16.f32 "
        "{%0,%1,%2,%3}, {%4,%5,%6,%7}, {%8,%9}, {%0,%1,%2,%3};\n"
        : "+f"(c[0]), "+f"(c[1]), "+f"(c[2]), "+f"(c[3])
        : "r"(a[0]), "r"(a[1]), "r"(a[2]), "r"(a[3]), "r"(b[0]), "r"(b[1]));
}
__device__ __forceinline__ void ldsm4(unsigned r[4], unsigned addr) {
    asm volatile("ldmatrix.sync.aligned.m8n8.x4.shared.b16 {%0,%1,%2,%3}, [%4];\n"
        : "=r"(r[0]), "=r"(r[1]), "=r"(r[2]), "=r"(r[3]) : "r"(addr));
}
__device__ __forceinline__ void ldsm4t(unsigned r[4], unsigned addr) {
    asm volatile("ldmatrix.sync.aligned.m8n8.x4.trans.shared.b16 {%0,%1,%2,%3}, [%4];\n"
        : "=r"(r[0]), "=r"(r[1]), "=r"(r[2]), "=r"(r[3]) : "r"(addr));
}
__device__ __forceinline__ void cp16(void* dst, const void* src) {
    unsigned d = (unsigned)__cvta_generic_to_shared(dst);
    asm volatile("cp.async.cg.shared.global [%0], [%1], 16;\n" :: "r"(d), "l"(src));
}
__device__ __forceinline__ void splitf(float x, u16& h, u16& l) {
    __nv_bfloat16 hb = __float2bfloat16(x);
    h = __bfloat16_as_ushort(hb);
    l = __bfloat16_as_ushort(__float2bfloat16(x - __bfloat162float(hb)));
}

// ---------------- input pre-split kernel ------------------------------------
__global__ __launch_bounds__(256)
void k_splitsel(const float4* __restrict__ src, int which, int n4)
{
    int i = blockIdx.x * 256 + threadIdx.x;
    if (i >= n4) return;
    ushort4* h4; ushort4* l4;
    if (which == 0)      { h4 = (ushort4*)g_Hh;  l4 = (ushort4*)g_Hl;  }
    else if (which == 1) { h4 = (ushort4*)g_Wih; l4 = (ushort4*)g_Wil; }
    else                 { h4 = (ushort4*)g_Woh; l4 = (ushort4*)g_Wol; }
    float4 f = src[i];
    ushort4 H, L;
    splitf(f.x, H.x, L.x); splitf(f.y, H.y, L.y);
    splitf(f.z, H.z, L.z); splitf(f.w, H.w, L.w);
    h4[i] = H; l4[i] = L;
}

// ---------------- tile stagers (cp.async, 128 threads) ----------------------
// A-style tile: 128 rows x 32 k, bf16, row stride 64B (4 chunks), swizzle c^=(row>>1)&3
__device__ __forceinline__ void stage_tileA(uint4* dst, const u16* __restrict__ g,
                                            int ld, int tid) {
    #pragma unroll
    for (int r = 0; r < 4; r++) {
        int c = tid + r * 128;
        int row = c >> 2, kc = c & 3;
        cp16(dst + row * 4 + (kc ^ ((row >> 1) & 3)),
             g + (size_t)row * ld + kc * 8);
    }
}
// B-style tile: 32 k-rows x 128 n, bf16, row stride 256B (16 chunks), swizzle c^=k&7
__device__ __forceinline__ void stage_tileB(uint4* dst, const u16* __restrict__ g,
                                            int ld, int tid) {
    #pragma unroll
    for (int r = 0; r < 4; r++) {
        int c = tid + r * 128;
        int k = c >> 4, nc = c & 15;
        cp16(dst + k * 16 + (nc ^ (k & 7)),
             g + (size_t)k * ld + nc * 8);
    }
}

// ---------------- bf16x3 tensor-core GEMM body (pre-split operands) ---------
// 128x128 CTA tile, BK=32, 128 threads, warps 2(m) x 2(n), warp tile 64x64.
// 3-stage cp.async pipeline, prefetch distance 2, ONE __syncthreads per chunk.
// BT=true: B stored [N][K] (Q@K^T).
template<bool BT>
__device__ __forceinline__ void mma_gemm_pk(const u16* __restrict__ Ah, const u16* __restrict__ Al, int lda,
                                            const u16* __restrict__ Bh, const u16* __restrict__ Bl, int ldb,
                                            int K, int rowBase, int colBase,
                                            float acc[4][8][4])
{
    extern __shared__ __align__(16) uint4 smdyn[];
    const int tid = threadIdx.x;
    const int lane = tid & 31, w = tid >> 5;
    const int wm = w >> 1, wn = w & 1;
    const int g = lane >> 3, i = lane & 7;
    const int nsteps = K / 32;

    auto issue = [&](int step) {
        uint4* st = smdyn + (step % 3) * 2048;
        int k0 = step * 32;
        stage_tileA(st,        Ah + (size_t)rowBase * lda + k0, lda, tid);
        stage_tileA(st + 512,  Al + (size_t)rowBase * lda + k0, lda, tid);
        if (BT) {
            stage_tileA(st + 1024, Bh + (size_t)colBase * ldb + k0, ldb, tid);
            stage_tileA(st + 1536, Bl + (size_t)colBase * ldb + k0, ldb, tid);
        } else {
            stage_tileB(st + 1024, Bh + (size_t)k0 * ldb + colBase, ldb, tid);
            stage_tileB(st + 1536, Bl + (size_t)k0 * ldb + colBase, ldb, tid);
        }
        asm volatile("cp.async.commit_group;\n");
    };

    issue(0);
    issue(1);
    for (int step = 0; step < nsteps; step++) {
        if (step + 1 < nsteps)
            asm volatile("cp.async.wait_group 1;\n");
        else
            asm volatile("cp.async.wait_group 0;\n");
        __syncthreads();

        const uint4* st = smdyn + (step % 3) * 2048;
        const unsigned bAh = (unsigned)__cvta_generic_to_shared(st);
        const unsigned bAl = bAh + 8192;
        const unsigned bBh = bAh + 16384;
        const unsigned bBl = bAh + 24576;

        #pragma unroll
        for (int ks = 0; ks < 32; ks += 16) {
            unsigned aH[4][4], aL[4][4];
            #pragma unroll
            for (int mi = 0; mi < 4; mi++) {
                int mrow = wm * 64 + mi * 16 + (g & 1) * 8 + i;
                int ch = (ks >> 3) + (g >> 1);
                int off = mrow * 64 + ((ch ^ ((mrow >> 1) & 3)) << 4);
                ldsm4(aH[mi], bAh + off);
                ldsm4(aL[mi], bAl + off);
            }
            unsigned bH[8][2], bL[8][2];
            #pragma unroll
            for (int p = 0; p < 4; p++) {
                unsigned rh[4], rl[4];
                if (BT) {
                    int nrow = wn * 64 + p * 16 + (g >> 1) * 8 + i;
                    int ch = (ks >> 3) + (g & 1);
                    int off = nrow * 64 + ((ch ^ ((nrow >> 1) & 3)) << 4);
                    ldsm4(rh, bBh + off);
                    ldsm4(rl, bBl + off);
                } else {
                    int kr = ks + (g & 1) * 8 + i;
                    int nl = wn * 64 + p * 16 + (g >> 1) * 8;
                    int off = kr * 256 + ((((nl >> 3) ^ (kr & 7))) << 4);
                    ldsm4t(rh, bBh + off);
                    ldsm4t(rl, bBl + off);
                }
                bH[2*p][0] = rh[0]; bH[2*p][1] = rh[1];
                bH[2*p+1][0] = rh[2]; bH[2*p+1][1] = rh[3];
                bL[2*p][0] = rl[0]; bL[2*p][1] = rl[1];
                bL[2*p+1][0] = rl[2]; bL[2*p+1][1] = rl[3];
            }
            #pragma unroll
            for (int mi = 0; mi < 4; mi++)
                #pragma unroll
                for (int ng = 0; ng < 8; ng++) {
                    mma16816(acc[mi][ng], aH[mi], bH[ng]);
                    mma16816(acc[mi][ng], aH[mi], bL[ng]);
                    mma16816(acc[mi][ng], aL[mi], bH[ng]);
                }
        }
        // refill the slot we just finished reading (guarded by next iter's sync)
        if (step + 2 < nsteps) issue(step + 2);
    }
}

#define EPI_SETUP() \
    const int lane = threadIdx.x & 31, w = threadIdx.x >> 5; \
    const int wm = w >> 1, wn = w & 1; \
    const int er = lane >> 2, ec = (lane & 3) * 2;

// ---------------- kernel 1: GEMM1 + SiLU + split ---------------------------
__global__ __launch_bounds__(128)
void k_gemm1(const float* __restrict__ qg, const float* __restrict__ kg)
{
    float acc[4][8][4] = {};
    const int rowBase = blockIdx.y * 128, colBase = blockIdx.x * 128;
    mma_gemm_pk<false>(g_Hh, g_Hl, HID, g_Wih, g_Wil, NCOLS, HID, rowBase, colBase, acc);
    EPI_SETUP();
    #pragma unroll
    for (int mi = 0; mi < 4; mi++)
        #pragma unroll
        for (int ng = 0; ng < 8; ng++) {
            int r0 = rowBase + wm * 64 + mi * 16 + er;
            int c0 = colBase + wn * 64 + ng * 8 + ec;
            #pragma unroll
            for (int h = 0; h < 2; h++) {
                int row = r0 + h * 8;
                #pragma unroll
                for (int j = 0; j < 2; j++) {
                    int col = c0 + j;
                    float x = acc[mi][ng][h * 2 + j];
                    float v = x / (1.0f + __expf(-x));  // SiLU
                    if (col < INTER) {
                        g_u[(size_t)row * INTER + col] = v;
                    } else if (col < 2 * INTER) {
                        size_t idx = (size_t)row * INTER + (col - INTER);
                        splitf(v, g_vh[idx], g_vl[idx]);
                    } else {
                        int c = col - 2 * INTER;
                        size_t idx = (size_t)row * DK + c;
                        splitf(v * qg[c], g_qh[idx], g_ql[idx]);
                        splitf(v * kg[c], g_kh[idx], g_kl[idx]);
                    }
                }
            }
        }
}

// ---------------- kernel 2: Q @ K^T / sqrt(DK) -----------------------------
__global__ __launch_bounds__(128)
void k_qk()
{
    float acc[4][8][4] = {};
    const int b = blockIdx.z;
    const int rowBase = blockIdx.y * 128, colBase = blockIdx.x * 128;
    const size_t o = (size_t)b * SEQ * DK;
    mma_gemm_pk<true>(g_qh + o, g_ql + o, DK, g_kh + o, g_kl + o, DK,
                      DK, rowBase, colBase, acc);
    float* Ab = g_A + (size_t)b * SEQ * SEQ;
    const float sc = 0.08838834764831845f;  // 1/sqrt(128)
    EPI_SETUP();
    #pragma unroll
    for (int mi = 0; mi < 4; mi++)
        #pragma unroll
        for (int ng = 0; ng < 8; ng++) {
            int r0 = rowBase + wm * 64 + mi * 16 + er;
            int c0 = colBase + wn * 64 + ng * 8 + ec;
            *(float2*)&Ab[(size_t)r0 * SEQ + c0] =
                make_float2(acc[mi][ng][0] * sc, acc[mi][ng][1] * sc);
            *(float2*)&Ab[(size_t)(r0 + 8) * SEQ + c0] =
                make_float2(acc[mi][ng][2] * sc, acc[mi][ng][3] * sc);
        }
}

// ---------------- kernel 3: masked softmax, writes split bf16 --------------
__global__ __launch_bounds__(256)
void k_softmax(const int* __restrict__ mask)
{
    const int bm = blockIdx.x;
    const int b = bm >> 11;
    const int m = bm & (SEQ - 1);
    const int tid = threadIdx.x;

    __shared__ float sdata[SEQ];
    __shared__ float red[256];

    float ls = 0.f;
    for (int n = tid; n < SEQ; n += 256) ls += (float)mask[b * SEQ + n];
    red[tid] = ls; __syncthreads();
    for (int s = 128; s > 0; s >>= 1) {
        if (tid < s) red[tid] += red[tid + s];
        __syncthreads();
    }
    const float l = red[0];
    __syncthreads();
    const float scale = logf(fmaxf(l, 1.0f)) * (1.0f / LOG512F);

    const size_t rowoff = (size_t)b * SEQ * SEQ + (size_t)m * SEQ;
    const float* row = g_A + rowoff;

    float mx = -3.4e38f;
    for (int n = tid; n < SEQ; n += 256) {
        float a = row[n];
        if (mask[b * SEQ + n] == 0) a = -1e12f;
        a *= scale;
        sdata[n] = a;
        mx = fmaxf(mx, a);
    }
    red[tid] = mx; __syncthreads();
    for (int s = 128; s > 0; s >>= 1) {
        if (tid < s) red[tid] = fmaxf(red[tid], red[tid + s]);
        __syncthreads();
    }
    mx = red[0]; __syncthreads();

    float sm = 0.f;
    for (int n = tid; n < SEQ; n += 256) {
        float e = __expf(sdata[n] - mx);
        sdata[n] = e;
        sm += e;
    }
    red[tid] = sm; __syncthreads();
    for (int s = 128; s > 0; s >>= 1) {
        if (tid < s) red[tid] += red[tid + s];
        __syncthreads();
    }
    const float inv = 1.0f / red[0];
    __syncthreads();

    for (int n = tid; n < SEQ; n += 256)
        splitf(sdata[n] * inv, g_Ah[rowoff + n], g_Al[rowoff + n]);
}

// ---------------- kernel 4: (A @ V) * u, writes split t --------------------
__global__ __launch_bounds__(128)
void k_av()
{
    float acc[4][8][4] = {};
    const int b = blockIdx.z;
    const int rowBase = blockIdx.y * 128, colBase = blockIdx.x * 128;
    const size_t oa = (size_t)b * SEQ * SEQ;
    const size_t ov = (size_t)b * SEQ * INTER;
    mma_gemm_pk<false>(g_Ah + oa, g_Al + oa, SEQ, g_vh + ov, g_vl + ov, INTER,
                       SEQ, rowBase, colBase, acc);
    EPI_SETUP();
    #pragma unroll
    for (int mi = 0; mi < 4; mi++)
        #pragma unroll
        for (int ng = 0; ng < 8; ng++) {
            int r0 = rowBase + wm * 64 + mi * 16 + er;
            int c0 = colBase + wn * 64 + ng * 8 + ec;
            #pragma unroll
            for (int h = 0; h < 2; h++) {
                int row = r0 + h * 8;
                size_t base = ((size_t)(b * SEQ + row)) * INTER + c0;
                float2 u2 = *(const float2*)&g_u[base];
                splitf(u2.x * acc[mi][ng][h * 2],     g_th[base],     g_tl[base]);
                splitf(u2.y * acc[mi][ng][h * 2 + 1], g_th[base + 1], g_tl[base + 1]);
            }
        }
}

// ---------------- kernel 5: t @ Wo -> out ----------------------------------
__global__ __launch_bounds__(128)
void k_out(float* __restrict__ out)
{
    float acc[4][8][4] = {};
    const int rowBase = blockIdx.y * 128, colBase = blockIdx.x * 128;
    mma_gemm_pk<false>(g_th, g_tl, INTER, g_Woh, g_Wol, HID,
                       INTER, rowBase, colBase, acc);
    EPI_SETUP();
    #pragma unroll
    for (int mi = 0; mi < 4; mi++)
        #pragma unroll
        for (int ng = 0; ng < 8; ng++) {
            int r0 = rowBase + wm * 64 + mi * 16 + er;
            int c0 = colBase + wn * 64 + ng * 8 + ec;
            *(float2*)&out[(size_t)r0 * HID + c0] =
                make_float2(acc[mi][ng][0], acc[mi][ng][1]);
            *(float2*)&out[(size_t)(r0 + 8) * HID + c0] =
                make_float2(acc[mi][ng][2], acc[mi][ng][3]);
        }
}

// ---------------- launch ----------------------------------------------------
extern "C" void kernel_launch(void* const* d_in, const int* in_sizes, int n_in,
                              void* d_out, int out_size)
{
    const float* h    = (const float*)d_in[0];
    const float* Wi   = (const float*)d_in[1];
    const float* Wo   = (const float*)d_in[2];
    const float* qg   = (const float*)d_in[3];
    const float* kg   = (const float*)d_in[4];
    const int*   mask = (const int*)d_in[5];
    float*       out  = (float*)d_out;

    cudaFuncSetAttribute(k_gemm1, cudaFuncAttributeMaxDynamicSharedMemorySize, GEMM_SMEM);
    cudaFuncSetAttribute(k_qk,    cudaFuncAttributeMaxDynamicSharedMemorySize, GEMM_SMEM);
    cudaFuncSetAttribute(k_av,    cudaFuncAttributeMaxDynamicSharedMemorySize, GEMM_SMEM);
    cudaFuncSetAttribute(k_out,   cudaFuncAttributeMaxDynamicSharedMemorySize, GEMM_SMEM);

    int n4h  = MTOT * HID / 4;
    int n4wi = HID * NCOLS / 4;
    int n4wo = INTER * HID / 4;
    k_splitsel<<<(n4h  + 255) / 256, 256>>>((const float4*)h,  0, n4h);
    k_splitsel<<<(n4wi + 255) / 256, 256>>>((const float4*)Wi, 1, n4wi);
    k_splitsel<<<(n4wo + 255) / 256, 256>>>((const float4*)Wo, 2, n4wo);

    k_gemm1<<<dim3(NCOLS / 128, MTOT / 128), 128, GEMM_SMEM>>>(qg, kg);
    k_qk<<<dim3(SEQ / 128, SEQ / 128, BATCH), 128, GEMM_SMEM>>>();
    k_softmax<<<BATCH * SEQ, 256>>>(mask);
    k_av<<<dim3(INTER / 128, SEQ / 128, BATCH), 128, GEMM_SMEM>>>();
    k_out<<<dim3(HID / 128, MTOT / 128), 128, GEMM_SMEM>>>(out);
}

// round 7
// speedup vs baseline: 1.2008x; 1.2008x over previous
#include <cuda_runtime.h>
#include <cuda_bf16.h>
#include <math.h>

#define HID   768
#define INTER 1536
#define DK    128
#define BATCH 4
#define SEQ   2048
#define MTOT  (BATCH*SEQ)          // 8192
#define NCOLS (2*INTER+DK)         // 3200
#define LOG512F 6.2383246250395075f
#define GEMM_SMEM (3*4*512*16)     // 96 KB: 3 stages x 4 tiles x 8KB

typedef unsigned short u16;

// ---------------- scratch (device globals) ---------------------------------
__device__ u16   g_Hh[(size_t)MTOT*HID],   g_Hl[(size_t)MTOT*HID];
__device__ u16   g_Wih[(size_t)HID*NCOLS], g_Wil[(size_t)HID*NCOLS];
__device__ u16   g_Woh[(size_t)INTER*HID], g_Wol[(size_t)INTER*HID];
__device__ float g_u[(size_t)MTOT*INTER];
__device__ u16   g_vh[(size_t)MTOT*INTER], g_vl[(size_t)MTOT*INTER];
__device__ u16   g_qh[(size_t)MTOT*DK],    g_ql[(size_t)MTOT*DK];
__device__ u16   g_kh[(size_t)MTOT*DK],    g_kl[(size_t)MTOT*DK];
__device__ float g_A [(size_t)BATCH*SEQ*SEQ];
__device__ u16   g_Ah[(size_t)BATCH*SEQ*SEQ], g_Al[(size_t)BATCH*SEQ*SEQ];
__device__ u16   g_th[(size_t)MTOT*INTER], g_tl[(size_t)MTOT*INTER];
__device__ float g_scale[BATCH];

// ---------------- PTX helpers ----------------------------------------------
__device__ __forceinline__ void mma16816(float c[4], const unsigned a[4], const unsigned b[2]) {
    asm volatile(
        "mma.sync.aligned.m16n8k16.row.col.f32.bf16.bf16.f32 "
        "{%0,%1,%2,%3}, {%4,%5,%6,%7}, {%8,%9}, {%0,%1,%2,%3};\n"
        : "+f"(c[0]), "+f"(c[1]), "+f"(c[2]), "+f"(c[3])
        : "r"(a[0]), "r"(a[1]), "r"(a[2]), "r"(a[3]), "r"(b[0]), "r"(b[1]));
}
__device__ __forceinline__ void ldsm4(unsigned r[4], unsigned addr) {
    asm volatile("ldmatrix.sync.aligned.m8n8.x4.shared.b16 {%0,%1,%2,%3}, [%4];\n"
        : "=r"(r[0]), "=r"(r[1]), "=r"(r[2]), "=r"(r[3]) : "r"(addr));
}
__device__ __forceinline__ void ldsm4t(unsigned r[4], unsigned addr) {
    asm volatile("ldmatrix.sync.aligned.m8n8.x4.trans.shared.b16 {%0,%1,%2,%3}, [%4];\n"
        : "=r"(r[0]), "=r"(r[1]), "=r"(r[2]), "=r"(r[3]) : "r"(addr));
}
__device__ __forceinline__ void cp16(void* dst, const void* src) {
    unsigned d = (unsigned)__cvta_generic_to_shared(dst);
    asm volatile("cp.async.cg.shared.global [%0], [%1], 16;\n" :: "r"(d), "l"(src));
}
__device__ __forceinline__ void splitf(float x, u16& h, u16& l) {
    __nv_bfloat16 hb = __float2bfloat16(x);
    h = __bfloat16_as_ushort(hb);
    l = __bfloat16_as_ushort(__float2bfloat16(x - __bfloat162float(hb)));
}

// ---------------- input pre-split kernel ------------------------------------
__global__ __launch_bounds__(256)
void k_splitsel(const float4* __restrict__ src, int which, int n4)
{
    int i = blockIdx.x * 256 + threadIdx.x;
    if (i >= n4) return;
    ushort4* h4; ushort4* l4;
    if (which == 0)      { h4 = (ushort4*)g_Hh;  l4 = (ushort4*)g_Hl;  }
    else if (which == 1) { h4 = (ushort4*)g_Wih; l4 = (ushort4*)g_Wil; }
    else                 { h4 = (ushort4*)g_Woh; l4 = (ushort4*)g_Wol; }
    float4 f = src[i];
    ushort4 H, L;
    splitf(f.x, H.x, L.x); splitf(f.y, H.y, L.y);
    splitf(f.z, H.z, L.z); splitf(f.w, H.w, L.w);
    h4[i] = H; l4[i] = L;
}

// ---------------- tile stagers (cp.async, 256 threads) ----------------------
// A-style tile: 128 rows x 32 k, bf16, row stride 64B (4 chunks), swizzle c^=(row>>1)&3
__device__ __forceinline__ void stage_tileA(uint4* dst, const u16* __restrict__ g,
                                            int ld, int tid) {
    #pragma unroll
    for (int r = 0; r < 2; r++) {
        int c = tid + r * 256;
        int row = c >> 2, kc = c & 3;
        cp16(dst + row * 4 + (kc ^ ((row >> 1) & 3)),
             g + (size_t)row * ld + kc * 8);
    }
}
// B-style tile: 32 k-rows x 128 n, bf16, row stride 256B (16 chunks), swizzle c^=k&7
__device__ __forceinline__ void stage_tileB(uint4* dst, const u16* __restrict__ g,
                                            int ld, int tid) {
    #pragma unroll
    for (int r = 0; r < 2; r++) {
        int c = tid + r * 256;
        int k = c >> 4, nc = c & 15;
        cp16(dst + k * 16 + (nc ^ (k & 7)),
             g + (size_t)k * ld + nc * 8);
    }
}

// ---------------- bf16x3 tensor-core GEMM body (pre-split operands) ---------
// 128x128 CTA tile, BK=32, 256 threads, warps 2(m) x 4(n), warp tile 64x32.
// 3-stage cp.async pipeline, prefetch distance 2, ONE __syncthreads per chunk.
// BT=true: B stored [N][K] (Q@K^T).
template<bool BT>
__device__ __forceinline__ void mma_gemm_pk(const u16* __restrict__ Ah, const u16* __restrict__ Al, int lda,
                                            const u16* __restrict__ Bh, const u16* __restrict__ Bl, int ldb,
                                            int K, int rowBase, int colBase,
                                            float acc[4][4][4])
{
    extern __shared__ __align__(16) uint4 smdyn[];
    const int tid = threadIdx.x;
    const int lane = tid & 31, w = tid >> 5;
    const int wm = w >> 2, wn = w & 3;
    const int g = lane >> 3, i = lane & 7;
    const int nsteps = K / 32;

    auto issue = [&](int step) {
        uint4* st = smdyn + (step % 3) * 2048;
        int k0 = step * 32;
        stage_tileA(st,        Ah + (size_t)rowBase * lda + k0, lda, tid);
        stage_tileA(st + 512,  Al + (size_t)rowBase * lda + k0, lda, tid);
        if (BT) {
            stage_tileA(st + 1024, Bh + (size_t)colBase * ldb + k0, ldb, tid);
            stage_tileA(st + 1536, Bl + (size_t)colBase * ldb + k0, ldb, tid);
        } else {
            stage_tileB(st + 1024, Bh + (size_t)k0 * ldb + colBase, ldb, tid);
            stage_tileB(st + 1536, Bl + (size_t)k0 * ldb + colBase, ldb, tid);
        }
        asm volatile("cp.async.commit_group;\n");
    };

    issue(0);
    issue(1);
    for (int step = 0; step < nsteps; step++) {
        if (step + 1 < nsteps)
            asm volatile("cp.async.wait_group 1;\n");
        else
            asm volatile("cp.async.wait_group 0;\n");
        __syncthreads();

        const uint4* st = smdyn + (step % 3) * 2048;
        const unsigned bAh = (unsigned)__cvta_generic_to_shared(st);
        const unsigned bAl = bAh + 8192;
        const unsigned bBh = bAh + 16384;
        const unsigned bBl = bAh + 24576;

        #pragma unroll
        for (int ks = 0; ks < 32; ks += 16) {
            unsigned aH[4][4], aL[4][4];
            #pragma unroll
            for (int mi = 0; mi < 4; mi++) {
                int mrow = wm * 64 + mi * 16 + (g & 1) * 8 + i;
                int ch = (ks >> 3) + (g >> 1);
                int off = mrow * 64 + ((ch ^ ((mrow >> 1) & 3)) << 4);
                ldsm4(aH[mi], bAh + off);
                ldsm4(aL[mi], bAl + off);
            }
            unsigned bH[4][2], bL[4][2];
            #pragma unroll
            for (int p = 0; p < 2; p++) {
                unsigned rh[4], rl[4];
                if (BT) {
                    int nrow = wn * 32 + p * 16 + (g >> 1) * 8 + i;
                    int ch = (ks >> 3) + (g & 1);
                    int off = nrow * 64 + ((ch ^ ((nrow >> 1) & 3)) << 4);
                    ldsm4(rh, bBh + off);
                    ldsm4(rl, bBl + off);
                } else {
                    int kr = ks + (g & 1) * 8 + i;
                    int nl = wn * 32 + p * 16 + (g >> 1) * 8;
                    int off = kr * 256 + ((((nl >> 3) ^ (kr & 7))) << 4);
                    ldsm4t(rh, bBh + off);
                    ldsm4t(rl, bBl + off);
                }
                bH[2*p][0] = rh[0]; bH[2*p][1] = rh[1];
                bH[2*p+1][0] = rh[2]; bH[2*p+1][1] = rh[3];
                bL[2*p][0] = rl[0]; bL[2*p][1] = rl[1];
                bL[2*p+1][0] = rl[2]; bL[2*p+1][1] = rl[3];
            }
            // term-major ordering: 16 independent MMAs between accumulator reuses
            #pragma unroll
            for (int mi = 0; mi < 4; mi++)
                #pragma unroll
                for (int ng = 0; ng < 4; ng++)
                    mma16816(acc[mi][ng], aH[mi], bH[ng]);
            #pragma unroll
            for (int mi = 0; mi < 4; mi++)
                #pragma unroll
                for (int ng = 0; ng < 4; ng++)
                    mma16816(acc[mi][ng], aH[mi], bL[ng]);
            #pragma unroll
            for (int mi = 0; mi < 4; mi++)
                #pragma unroll
                for (int ng = 0; ng < 4; ng++)
                    mma16816(acc[mi][ng], aL[mi], bH[ng]);
        }
        // refill the slot we just finished reading (guarded by next iter's sync)
        if (step + 2 < nsteps) issue(step + 2);
    }
}

#define EPI_SETUP() \
    const int lane = threadIdx.x & 31, w = threadIdx.x >> 5; \
    const int wm = w >> 2, wn = w & 3; \
    const int er = lane >> 2, ec = (lane & 3) * 2;

// ---------------- kernel 1: GEMM1 + SiLU + split ---------------------------
// q' = silu(x) * qg*kg/sqrt(DK)   (scale folded here),  k' = silu(x)
__global__ __launch_bounds__(256, 2)
void k_gemm1(const float* __restrict__ qg, const float* __restrict__ kg)
{
    float acc[4][4][4] = {};
    const int rowBase = blockIdx.y * 128, colBase = blockIdx.x * 128;
    mma_gemm_pk<false>(g_Hh, g_Hl, HID, g_Wih, g_Wil, NCOLS, HID, rowBase, colBase, acc);
    EPI_SETUP();
    #pragma unroll
    for (int mi = 0; mi < 4; mi++)
        #pragma unroll
        for (int ng = 0; ng < 4; ng++) {
            int r0 = rowBase + wm * 64 + mi * 16 + er;
            int c0 = colBase + wn * 32 + ng * 8 + ec;
            #pragma unroll
            for (int h = 0; h < 2; h++) {
                int row = r0 + h * 8;
                #pragma unroll
                for (int j = 0; j < 2; j++) {
                    int col = c0 + j;
                    float x = acc[mi][ng][h * 2 + j];
                    float v = x / (1.0f + __expf(-x));  // SiLU
                    if (col < INTER) {
                        g_u[(size_t)row * INTER + col] = v;
                    } else if (col < 2 * INTER) {
                        size_t idx = (size_t)row * INTER + (col - INTER);
                        splitf(v, g_vh[idx], g_vl[idx]);
                    } else {
                        int c = col - 2 * INTER;
                        size_t idx = (size_t)row * DK + c;
                        float sq = qg[c] * kg[c] * 0.08838834764831845f;
                        splitf(v * sq, g_qh[idx], g_ql[idx]);
                        splitf(v,      g_kh[idx], g_kl[idx]);
                    }
                }
            }
        }
}

// ---------------- kernel 2: Q' @ K'^T (scale pre-folded) --------------------
__global__ __launch_bounds__(256, 2)
void k_qk()
{
    float acc[4][4][4] = {};
    const int b = blockIdx.z;
    const int rowBase = blockIdx.y * 128, colBase = blockIdx.x * 128;
    const size_t o = (size_t)b * SEQ * DK;
    mma_gemm_pk<true>(g_qh + o, g_ql + o, DK, g_kh + o, g_kl + o, DK,
                      DK, rowBase, colBase, acc);
    float* Ab = g_A + (size_t)b * SEQ * SEQ;
    EPI_SETUP();
    #pragma unroll
    for (int mi = 0; mi < 4; mi++)
        #pragma unroll
        for (int ng = 0; ng < 4; ng++) {
            int r0 = rowBase + wm * 64 + mi * 16 + er;
            int c0 = colBase + wn * 32 + ng * 8 + ec;
            *(float2*)&Ab[(size_t)r0 * SEQ + c0] =
                make_float2(acc[mi][ng][0], acc[mi][ng][1]);
            *(float2*)&Ab[(size_t)(r0 + 8) * SEQ + c0] =
                make_float2(acc[mi][ng][2], acc[mi][ng][3]);
        }
}

// ---------------- kernel 2b: per-batch softmax scale ------------------------
__global__ __launch_bounds__(256)
void k_scale(const int* __restrict__ mask)
{
    __shared__ float red[256];
    const int b = blockIdx.x, tid = threadIdx.x;
    float ls = 0.f;
    for (int n = tid; n < SEQ; n += 256) ls += (float)mask[b * SEQ + n];
    red[tid] = ls; __syncthreads();
    for (int s = 128; s > 0; s >>= 1) {
        if (tid < s) red[tid] += red[tid + s];
        __syncthreads();
    }
    if (tid == 0) g_scale[b] = logf(fmaxf(red[0], 1.0f)) * (1.0f / LOG512F);
}

// ---------------- kernel 3: masked softmax (register-resident row) ----------
__global__ __launch_bounds__(256)
void k_softmax(const int* __restrict__ mask)
{
    const int bm = blockIdx.x;
    const int b = bm >> 11;
    const int m = bm & (SEQ - 1);
    const int tid = threadIdx.x;
    const int lane = tid & 31, wrp = tid >> 5;

    __shared__ float red[8];
    const float scale = g_scale[b];
    const size_t rowoff = (size_t)b * SEQ * SEQ + (size_t)m * SEQ;
    const float* row = g_A + rowoff;

    float a[8];
    float mx = -3.4e38f;
    #pragma unroll
    for (int k2 = 0; k2 < 8; k2++) {
        int n = tid + k2 * 256;
        float x = row[n];
        if (mask[b * SEQ + n] == 0) x = -1e12f;
        x *= scale;
        a[k2] = x;
        mx = fmaxf(mx, x);
    }
    #pragma unroll
    for (int s = 16; s > 0; s >>= 1)
        mx = fmaxf(mx, __shfl_xor_sync(0xffffffffu, mx, s));
    if (lane == 0) red[wrp] = mx;
    __syncthreads();
    mx = red[lane & 7];
    #pragma unroll
    for (int s = 4; s > 0; s >>= 1)
        mx = fmaxf(mx, __shfl_xor_sync(0xffffffffu, mx, s));

    float sm = 0.f;
    #pragma unroll
    for (int k2 = 0; k2 < 8; k2++) {
        float e = __expf(a[k2] - mx);
        a[k2] = e;
        sm += e;
    }
    #pragma unroll
    for (int s = 16; s > 0; s >>= 1)
        sm += __shfl_xor_sync(0xffffffffu, sm, s);
    __syncthreads();
    if (lane == 0) red[wrp] = sm;
    __syncthreads();
    sm = red[lane & 7];
    #pragma unroll
    for (int s = 4; s > 0; s >>= 1)
        sm += __shfl_xor_sync(0xffffffffu, sm, s);
    const float inv = 1.0f / sm;

    #pragma unroll
    for (int k2 = 0; k2 < 8; k2++) {
        int n = tid + k2 * 256;
        splitf(a[k2] * inv, g_Ah[rowoff + n], g_Al[rowoff + n]);
    }
}

// ---------------- kernel 4: (A @ V) * u, writes split t --------------------
__global__ __launch_bounds__(256, 2)
void k_av()
{
    float acc[4][4][4] = {};
    const int b = blockIdx.z;
    const int rowBase = blockIdx.y * 128, colBase = blockIdx.x * 128;
    const size_t oa = (size_t)b * SEQ * SEQ;
    const size_t ov = (size_t)b * SEQ * INTER;
    mma_gemm_pk<false>(g_Ah + oa, g_Al + oa, SEQ, g_vh + ov, g_vl + ov, INTER,
                       SEQ, rowBase, colBase, acc);
    EPI_SETUP();
    #pragma unroll
    for (int mi = 0; mi < 4; mi++)
        #pragma unroll
        for (int ng = 0; ng < 4; ng++) {
            int r0 = rowBase + wm * 64 + mi * 16 + er;
            int c0 = colBase + wn * 32 + ng * 8 + ec;
            #pragma unroll
            for (int h = 0; h < 2; h++) {
                int row = r0 + h * 8;
                size_t base = ((size_t)(b * SEQ + row)) * INTER + c0;
                float2 u2 = *(const float2*)&g_u[base];
                splitf(u2.x * acc[mi][ng][h * 2],     g_th[base],     g_tl[base]);
                splitf(u2.y * acc[mi][ng][h * 2 + 1], g_th[base + 1], g_tl[base + 1]);
            }
        }
}

// ---------------- kernel 5: t @ Wo -> out ----------------------------------
__global__ __launch_bounds__(256, 2)
void k_out(float* __restrict__ out)
{
    float acc[4][4][4] = {};
    const int rowBase = blockIdx.y * 128, colBase = blockIdx.x * 128;
    mma_gemm_pk<false>(g_th, g_tl, INTER, g_Woh, g_Wol, HID,
                       INTER, rowBase, colBase, acc);
    EPI_SETUP();
    #pragma unroll
    for (int mi = 0; mi < 4; mi++)
        #pragma unroll
        for (int ng = 0; ng < 4; ng++) {
            int r0 = rowBase + wm * 64 + mi * 16 + er;
            int c0 = colBase + wn * 32 + ng * 8 + ec;
            *(float2*)&out[(size_t)r0 * HID + c0] =
                make_float2(acc[mi][ng][0], acc[mi][ng][1]);
            *(float2*)&out[(size_t)(r0 + 8) * HID + c0] =
                make_float2(acc[mi][ng][2], acc[mi][ng][3]);
        }
}

// ---------------- launch ----------------------------------------------------
extern "C" void kernel_launch(void* const* d_in, const int* in_sizes, int n_in,
                              void* d_out, int out_size)
{
    const float* h    = (const float*)d_in[0];
    const float* Wi   = (const float*)d_in[1];
    const float* Wo   = (const float*)d_in[2];
    const float* qg   = (const float*)d_in[3];
    const float* kg   = (const float*)d_in[4];
    const int*   mask = (const int*)d_in[5];
    float*       out  = (float*)d_out;

    cudaFuncSetAttribute(k_gemm1, cudaFuncAttributeMaxDynamicSharedMemorySize, GEMM_SMEM);
    cudaFuncSetAttribute(k_qk,    cudaFuncAttributeMaxDynamicSharedMemorySize, GEMM_SMEM);
    cudaFuncSetAttribute(k_av,    cudaFuncAttributeMaxDynamicSharedMemorySize, GEMM_SMEM);
    cudaFuncSetAttribute(k_out,   cudaFuncAttributeMaxDynamicSharedMemorySize, GEMM_SMEM);

    int n4h  = MTOT * HID / 4;
    int n4wi = HID * NCOLS / 4;
    int n4wo = INTER * HID / 4;
    k_splitsel<<<(n4h  + 255) / 256, 256>>>((const float4*)h,  0, n4h);
    k_splitsel<<<(n4wi + 255) / 256, 256>>>((const float4*)Wi, 1, n4wi);
    k_splitsel<<<(n4wo + 255) / 256, 256>>>((const float4*)Wo, 2, n4wo);
    k_scale<<<BATCH, 256>>>(mask);

    k_gemm1<<<dim3(NCOLS / 128, MTOT / 128), 256, GEMM_SMEM>>>(qg, kg);
    k_qk<<<dim3(SEQ / 128, SEQ / 128, BATCH), 256, GEMM_SMEM>>>();
    k_softmax<<<BATCH * SEQ, 256>>>(mask);
    k_av<<<dim3(INTER / 128, SEQ / 128, BATCH), 256, GEMM_SMEM>>>();
    k_out<<<dim3(HID / 128, MTOT / 128), 256, GEMM_SMEM>>>(out);
}

// round 8
// speedup vs baseline: 1.4995x; 1.2488x over previous
#include <cuda_runtime.h>
#include <cuda_bf16.h>
#include <cuda_fp16.h>
#include <math.h>

#define HID   768
#define INTER 1536
#define DK    128
#define BATCH 4
#define SEQ   2048
#define MTOT  (BATCH*SEQ)          // 8192
#define NCOLS (2*INTER+DK)         // 3200
#define LOG512F 6.2383246250395075f
#define GEMM_SMEM  (3*4*512*16)    // 96 KB: 3 stages x 4 tiles (bf16x3 path)
#define GEMM_SMEM2 (3*3*512*16)    // 72 KB: 3 stages x 3 tiles (fp16x2 path)

typedef unsigned short u16;

// ---------------- scratch (device globals) ---------------------------------
__device__ u16   g_Hh[(size_t)MTOT*HID],   g_Hl[(size_t)MTOT*HID];     // bf16
__device__ u16   g_Wih[(size_t)HID*NCOLS], g_Wil[(size_t)HID*NCOLS];   // bf16
__device__ u16   g_Woh[(size_t)INTER*HID], g_Wol[(size_t)INTER*HID];   // fp16
__device__ float g_u[(size_t)MTOT*INTER];
__device__ u16   g_vh[(size_t)MTOT*INTER], g_vl[(size_t)MTOT*INTER];   // fp16
__device__ u16   g_qh[(size_t)MTOT*DK],    g_ql[(size_t)MTOT*DK];      // bf16
__device__ u16   g_kh[(size_t)MTOT*DK],    g_kl[(size_t)MTOT*DK];      // bf16
__device__ float g_A [(size_t)BATCH*SEQ*SEQ];
__device__ u16   g_A16[(size_t)BATCH*SEQ*SEQ];                          // fp16 probs
__device__ u16   g_t16[(size_t)MTOT*INTER];                             // fp16 gated
__device__ float g_scale[BATCH];

// ---------------- PTX helpers ----------------------------------------------
__device__ __forceinline__ void mma_bf16(float c[4], const unsigned a[4], const unsigned b[2]) {
    asm volatile(
        "mma.sync.aligned.m16n8k16.row.col.f32.bf16.bf16.f32 "
        "{%0,%1,%2,%3}, {%4,%5,%6,%7}, {%8,%9}, {%0,%1,%2,%3};\n"
        : "+f"(c[0]), "+f"(c[1]), "+f"(c[2]), "+f"(c[3])
        : "r"(a[0]), "r"(a[1]), "r"(a[2]), "r"(a[3]), "r"(b[0]), "r"(b[1]));
}
__device__ __forceinline__ void mma_f16(float c[4], const unsigned a[4], const unsigned b[2]) {
    asm volatile(
        "mma.sync.aligned.m16n8k16.row.col.f32.f16.f16.f32 "
        "{%0,%1,%2,%3}, {%4,%5,%6,%7}, {%8,%9}, {%0,%1,%2,%3};\n"
        : "+f"(c[0]), "+f"(c[1]), "+f"(c[2]), "+f"(c[3])
        : "r"(a[0]), "r"(a[1]), "r"(a[2]), "r"(a[3]), "r"(b[0]), "r"(b[1]));
}
__device__ __forceinline__ void ldsm4(unsigned r[4], unsigned addr) {
    asm volatile("ldmatrix.sync.aligned.m8n8.x4.shared.b16 {%0,%1,%2,%3}, [%4];\n"
        : "=r"(r[0]), "=r"(r[1]), "=r"(r[2]), "=r"(r[3]) : "r"(addr));
}
__device__ __forceinline__ void ldsm4t(unsigned r[4], unsigned addr) {
    asm volatile("ldmatrix.sync.aligned.m8n8.x4.trans.shared.b16 {%0,%1,%2,%3}, [%4];\n"
        : "=r"(r[0]), "=r"(r[1]), "=r"(r[2]), "=r"(r[3]) : "r"(addr));
}
__device__ __forceinline__ void cp16(void* dst, const void* src) {
    unsigned d = (unsigned)__cvta_generic_to_shared(dst);
    asm volatile("cp.async.cg.shared.global [%0], [%1], 16;\n" :: "r"(d), "l"(src));
}
__device__ __forceinline__ void splitf(float x, u16& h, u16& l) {     // bf16 hi/lo
    __nv_bfloat16 hb = __float2bfloat16(x);
    h = __bfloat16_as_ushort(hb);
    l = __bfloat16_as_ushort(__float2bfloat16(x - __bfloat162float(hb)));
}
__device__ __forceinline__ void splith(float x, u16& h, u16& l) {     // fp16 hi/lo
    __half hb = __float2half_rn(x);
    h = __half_as_ushort(hb);
    l = __half_as_ushort(__float2half_rn(x - __half2float(hb)));
}

// ---------------- input pre-split kernel ------------------------------------
__global__ __launch_bounds__(256)
void k_splitsel(const float4* __restrict__ src, int which, int n4)
{
    int i = blockIdx.x * 256 + threadIdx.x;
    if (i >= n4) return;
    float4 f = src[i];
    ushort4 H, L;
    if (which == 2) {   // Wo -> fp16 hi/lo
        splith(f.x, H.x, L.x); splith(f.y, H.y, L.y);
        splith(f.z, H.z, L.z); splith(f.w, H.w, L.w);
        ((ushort4*)g_Woh)[i] = H; ((ushort4*)g_Wol)[i] = L;
    } else {
        splitf(f.x, H.x, L.x); splitf(f.y, H.y, L.y);
        splitf(f.z, H.z, L.z); splitf(f.w, H.w, L.w);
        if (which == 0) { ((ushort4*)g_Hh)[i]  = H; ((ushort4*)g_Hl)[i]  = L; }
        else            { ((ushort4*)g_Wih)[i] = H; ((ushort4*)g_Wil)[i] = L; }
    }
}

// ---------------- tile stagers (cp.async, 256 threads) ----------------------
__device__ __forceinline__ void stage_tileA(uint4* dst, const u16* __restrict__ g,
                                            int ld, int tid) {
    #pragma unroll
    for (int r = 0; r < 2; r++) {
        int c = tid + r * 256;
        int row = c >> 2, kc = c & 3;
        cp16(dst + row * 4 + (kc ^ ((row >> 1) & 3)),
             g + (size_t)row * ld + kc * 8);
    }
}
__device__ __forceinline__ void stage_tileB(uint4* dst, const u16* __restrict__ g,
                                            int ld, int tid) {
    #pragma unroll
    for (int r = 0; r < 2; r++) {
        int c = tid + r * 256;
        int k = c >> 4, nc = c & 15;
        cp16(dst + k * 16 + (nc ^ (k & 7)),
             g + (size_t)k * ld + nc * 8);
    }
}

// ---------------- bf16x3 GEMM body (score path) -----------------------------
template<bool BT>
__device__ __forceinline__ void mma_gemm_pk(const u16* __restrict__ Ah, const u16* __restrict__ Al, int lda,
                                            const u16* __restrict__ Bh, const u16* __restrict__ Bl, int ldb,
                                            int K, int rowBase, int colBase,
                                            float acc[4][4][4])
{
    extern __shared__ __align__(16) uint4 smdyn[];
    const int tid = threadIdx.x;
    const int lane = tid & 31, w = tid >> 5;
    const int wm = w >> 2, wn = w & 3;
    const int g = lane >> 3, i = lane & 7;
    const int nsteps = K / 32;

    auto issue = [&](int step) {
        uint4* st = smdyn + (step % 3) * 2048;
        int k0 = step * 32;
        stage_tileA(st,        Ah + (size_t)rowBase * lda + k0, lda, tid);
        stage_tileA(st + 512,  Al + (size_t)rowBase * lda + k0, lda, tid);
        if (BT) {
            stage_tileA(st + 1024, Bh + (size_t)colBase * ldb + k0, ldb, tid);
            stage_tileA(st + 1536, Bl + (size_t)colBase * ldb + k0, ldb, tid);
        } else {
            stage_tileB(st + 1024, Bh + (size_t)k0 * ldb + colBase, ldb, tid);
            stage_tileB(st + 1536, Bl + (size_t)k0 * ldb + colBase, ldb, tid);
        }
        asm volatile("cp.async.commit_group;\n");
    };

    issue(0);
    issue(1);
    for (int step = 0; step < nsteps; step++) {
        if (step + 1 < nsteps)
            asm volatile("cp.async.wait_group 1;\n");
        else
            asm volatile("cp.async.wait_group 0;\n");
        __syncthreads();

        const uint4* st = smdyn + (step % 3) * 2048;
        const unsigned bAh = (unsigned)__cvta_generic_to_shared(st);
        const unsigned bAl = bAh + 8192;
        const unsigned bBh = bAh + 16384;
        const unsigned bBl = bAh + 24576;

        #pragma unroll
        for (int ks = 0; ks < 32; ks += 16) {
            unsigned aH[4][4], aL[4][4];
            #pragma unroll
            for (int mi = 0; mi < 4; mi++) {
                int mrow = wm * 64 + mi * 16 + (g & 1) * 8 + i;
                int ch = (ks >> 3) + (g >> 1);
                int off = mrow * 64 + ((ch ^ ((mrow >> 1) & 3)) << 4);
                ldsm4(aH[mi], bAh + off);
                ldsm4(aL[mi], bAl + off);
            }
            unsigned bH[4][2], bL[4][2];
            #pragma unroll
            for (int p = 0; p < 2; p++) {
                unsigned rh[4], rl[4];
                if (BT) {
                    int nrow = wn * 32 + p * 16 + (g >> 1) * 8 + i;
                    int ch = (ks >> 3) + (g & 1);
                    int off = nrow * 64 + ((ch ^ ((nrow >> 1) & 3)) << 4);
                    ldsm4(rh, bBh + off);
                    ldsm4(rl, bBl + off);
                } else {
                    int kr = ks + (g & 1) * 8 + i;
                    int nl = wn * 32 + p * 16 + (g >> 1) * 8;
                    int off = kr * 256 + ((((nl >> 3) ^ (kr & 7))) << 4);
                    ldsm4t(rh, bBh + off);
                    ldsm4t(rl, bBl + off);
                }
                bH[2*p][0] = rh[0]; bH[2*p][1] = rh[1];
                bH[2*p+1][0] = rh[2]; bH[2*p+1][1] = rh[3];
                bL[2*p][0] = rl[0]; bL[2*p][1] = rl[1];
                bL[2*p+1][0] = rl[2]; bL[2*p+1][1] = rl[3];
            }
            #pragma unroll
            for (int mi = 0; mi < 4; mi++)
                #pragma unroll
                for (int ng = 0; ng < 4; ng++)
                    mma_bf16(acc[mi][ng], aH[mi], bH[ng]);
            #pragma unroll
            for (int mi = 0; mi < 4; mi++)
                #pragma unroll
                for (int ng = 0; ng < 4; ng++)
                    mma_bf16(acc[mi][ng], aH[mi], bL[ng]);
            #pragma unroll
            for (int mi = 0; mi < 4; mi++)
                #pragma unroll
                for (int ng = 0; ng < 4; ng++)
                    mma_bf16(acc[mi][ng], aL[mi], bH[ng]);
        }
        if (step + 2 < nsteps) issue(step + 2);
    }
}

// ---------------- fp16 2-term GEMM body (value path) ------------------------
// A single fp16 [M][K]; B split hi/lo fp16 [K][N]. C = A*(Bh+Bl).
__device__ __forceinline__ void mma_gemm_2t(const u16* __restrict__ Aa, int lda,
                                            const u16* __restrict__ Bh, const u16* __restrict__ Bl, int ldb,
                                            int K, int rowBase, int colBase,
                                            float acc[4][4][4])
{
    extern __shared__ __align__(16) uint4 smdyn[];
    const int tid = threadIdx.x;
    const int lane = tid & 31, w = tid >> 5;
    const int wm = w >> 2, wn = w & 3;
    const int g = lane >> 3, i = lane & 7;
    const int nsteps = K / 32;

    auto issue = [&](int step) {
        uint4* st = smdyn + (step % 3) * 1536;
        int k0 = step * 32;
        stage_tileA(st,        Aa + (size_t)rowBase * lda + k0, lda, tid);
        stage_tileB(st + 512,  Bh + (size_t)k0 * ldb + colBase, ldb, tid);
        stage_tileB(st + 1024, Bl + (size_t)k0 * ldb + colBase, ldb, tid);
        asm volatile("cp.async.commit_group;\n");
    };

    issue(0);
    issue(1);
    for (int step = 0; step < nsteps; step++) {
        if (step + 1 < nsteps)
            asm volatile("cp.async.wait_group 1;\n");
        else
            asm volatile("cp.async.wait_group 0;\n");
        __syncthreads();

        const uint4* st = smdyn + (step % 3) * 1536;
        const unsigned bA  = (unsigned)__cvta_generic_to_shared(st);
        const unsigned bBh = bA + 8192;
        const unsigned bBl = bA + 16384;

        #pragma unroll
        for (int ks = 0; ks < 32; ks += 16) {
            unsigned aF[4][4];
            #pragma unroll
            for (int mi = 0; mi < 4; mi++) {
                int mrow = wm * 64 + mi * 16 + (g & 1) * 8 + i;
                int ch = (ks >> 3) + (g >> 1);
                int off = mrow * 64 + ((ch ^ ((mrow >> 1) & 3)) << 4);
                ldsm4(aF[mi], bA + off);
            }
            unsigned bH[4][2], bL[4][2];
            #pragma unroll
            for (int p = 0; p < 2; p++) {
                unsigned rh[4], rl[4];
                int kr = ks + (g & 1) * 8 + i;
                int nl = wn * 32 + p * 16 + (g >> 1) * 8;
                int off = kr * 256 + ((((nl >> 3) ^ (kr & 7))) << 4);
                ldsm4t(rh, bBh + off);
                ldsm4t(rl, bBl + off);
                bH[2*p][0] = rh[0]; bH[2*p][1] = rh[1];
                bH[2*p+1][0] = rh[2]; bH[2*p+1][1] = rh[3];
                bL[2*p][0] = rl[0]; bL[2*p][1] = rl[1];
                bL[2*p+1][0] = rl[2]; bL[2*p+1][1] = rl[3];
            }
            #pragma unroll
            for (int mi = 0; mi < 4; mi++)
                #pragma unroll
                for (int ng = 0; ng < 4; ng++)
                    mma_f16(acc[mi][ng], aF[mi], bH[ng]);
            #pragma unroll
            for (int mi = 0; mi < 4; mi++)
                #pragma unroll
                for (int ng = 0; ng < 4; ng++)
                    mma_f16(acc[mi][ng], aF[mi], bL[ng]);
        }
        if (step + 2 < nsteps) issue(step + 2);
    }
}

#define EPI_SETUP() \
    const int lane = threadIdx.x & 31, w = threadIdx.x >> 5; \
    const int wm = w >> 2, wn = w & 3; \
    const int er = lane >> 2, ec = (lane & 3) * 2;

// ---------------- kernel 1: GEMM1 + SiLU + split ---------------------------
__global__ __launch_bounds__(256, 2)
void k_gemm1(const float* __restrict__ qg, const float* __restrict__ kg)
{
    float acc[4][4][4] = {};
    const int rowBase = blockIdx.y * 128, colBase = blockIdx.x * 128;
    mma_gemm_pk<false>(g_Hh, g_Hl, HID, g_Wih, g_Wil, NCOLS, HID, rowBase, colBase, acc);
    EPI_SETUP();
    #pragma unroll
    for (int mi = 0; mi < 4; mi++)
        #pragma unroll
        for (int ng = 0; ng < 4; ng++) {
            int r0 = rowBase + wm * 64 + mi * 16 + er;
            int c0 = colBase + wn * 32 + ng * 8 + ec;
            #pragma unroll
            for (int h = 0; h < 2; h++) {
                int row = r0 + h * 8;
                #pragma unroll
                for (int j = 0; j < 2; j++) {
                    int col = c0 + j;
                    float x = acc[mi][ng][h * 2 + j];
                    float v = x / (1.0f + __expf(-x));  // SiLU
                    if (col < INTER) {
                        g_u[(size_t)row * INTER + col] = v;
                    } else if (col < 2 * INTER) {
                        size_t idx = (size_t)row * INTER + (col - INTER);
                        splith(v, g_vh[idx], g_vl[idx]);        // fp16 hi/lo
                    } else {
                        int c = col - 2 * INTER;
                        size_t idx = (size_t)row * DK + c;
                        float sq = qg[c] * kg[c] * 0.08838834764831845f;
                        splitf(v * sq, g_qh[idx], g_ql[idx]);
                        splitf(v,      g_kh[idx], g_kl[idx]);
                    }
                }
            }
        }
}

// ---------------- kernel 2: Q' @ K'^T (scale pre-folded) --------------------
__global__ __launch_bounds__(256, 2)
void k_qk()
{
    float acc[4][4][4] = {};
    const int b = blockIdx.z;
    const int rowBase = blockIdx.y * 128, colBase = blockIdx.x * 128;
    const size_t o = (size_t)b * SEQ * DK;
    mma_gemm_pk<true>(g_qh + o, g_ql + o, DK, g_kh + o, g_kl + o, DK,
                      DK, rowBase, colBase, acc);
    float* Ab = g_A + (size_t)b * SEQ * SEQ;
    EPI_SETUP();
    #pragma unroll
    for (int mi = 0; mi < 4; mi++)
        #pragma unroll
        for (int ng = 0; ng < 4; ng++) {
            int r0 = rowBase + wm * 64 + mi * 16 + er;
            int c0 = colBase + wn * 32 + ng * 8 + ec;
            *(float2*)&Ab[(size_t)r0 * SEQ + c0] =
                make_float2(acc[mi][ng][0], acc[mi][ng][1]);
            *(float2*)&Ab[(size_t)(r0 + 8) * SEQ + c0] =
                make_float2(acc[mi][ng][2], acc[mi][ng][3]);
        }
}

// ---------------- kernel 2b: per-batch softmax scale ------------------------
__global__ __launch_bounds__(256)
void k_scale(const int* __restrict__ mask)
{
    __shared__ float red[256];
    const int b = blockIdx.x, tid = threadIdx.x;
    float ls = 0.f;
    for (int n = tid; n < SEQ; n += 256) ls += (float)mask[b * SEQ + n];
    red[tid] = ls; __syncthreads();
    for (int s = 128; s > 0; s >>= 1) {
        if (tid < s) red[tid] += red[tid + s];
        __syncthreads();
    }
    if (tid == 0) g_scale[b] = logf(fmaxf(red[0], 1.0f)) * (1.0f / LOG512F);
}

// ---------------- kernel 3: masked softmax (register-resident row) ----------
__global__ __launch_bounds__(256)
void k_softmax(const int* __restrict__ mask)
{
    const int bm = blockIdx.x;
    const int b = bm >> 11;
    const int m = bm & (SEQ - 1);
    const int tid = threadIdx.x;
    const int lane = tid & 31, wrp = tid >> 5;

    __shared__ float red[8];
    const float scale = g_scale[b];
    const size_t rowoff = (size_t)b * SEQ * SEQ + (size_t)m * SEQ;
    const float* row = g_A + rowoff;

    float a[8];
    float mx = -3.4e38f;
    #pragma unroll
    for (int k2 = 0; k2 < 8; k2++) {
        int n = tid + k2 * 256;
        float x = row[n];
        if (mask[b * SEQ + n] == 0) x = -1e12f;
        x *= scale;
        a[k2] = x;
        mx = fmaxf(mx, x);
    }
    #pragma unroll
    for (int s = 16; s > 0; s >>= 1)
        mx = fmaxf(mx, __shfl_xor_sync(0xffffffffu, mx, s));
    if (lane == 0) red[wrp] = mx;
    __syncthreads();
    mx = red[lane & 7];
    #pragma unroll
    for (int s = 4; s > 0; s >>= 1)
        mx = fmaxf(mx, __shfl_xor_sync(0xffffffffu, mx, s));

    float sm = 0.f;
    #pragma unroll
    for (int k2 = 0; k2 < 8; k2++) {
        float e = __expf(a[k2] - mx);
        a[k2] = e;
        sm += e;
    }
    #pragma unroll
    for (int s = 16; s > 0; s >>= 1)
        sm += __shfl_xor_sync(0xffffffffu, sm, s);
    __syncthreads();
    if (lane == 0) red[wrp] = sm;
    __syncthreads();
    sm = red[lane & 7];
    #pragma unroll
    for (int s = 4; s > 0; s >>= 1)
        sm += __shfl_xor_sync(0xffffffffu, sm, s);
    const float inv = 1.0f / sm;

    #pragma unroll
    for (int k2 = 0; k2 < 8; k2++) {
        int n = tid + k2 * 256;
        g_A16[rowoff + n] = __half_as_ushort(__float2half_rn(a[k2] * inv));
    }
}

// ---------------- kernel 4: (A @ V) * u  (fp16 2-term) ----------------------
__global__ __launch_bounds__(256, 2)
void k_av()
{
    float acc[4][4][4] = {};
    const int b = blockIdx.z;
    const int rowBase = blockIdx.y * 128, colBase = blockIdx.x * 128;
    const size_t oa = (size_t)b * SEQ * SEQ;
    const size_t ov = (size_t)b * SEQ * INTER;
    mma_gemm_2t(g_A16 + oa, SEQ, g_vh + ov, g_vl + ov, INTER,
                SEQ, rowBase, colBase, acc);
    EPI_SETUP();
    #pragma unroll
    for (int mi = 0; mi < 4; mi++)
        #pragma unroll
        for (int ng = 0; ng < 4; ng++) {
            int r0 = rowBase + wm * 64 + mi * 16 + er;
            int c0 = colBase + wn * 32 + ng * 8 + ec;
            #pragma unroll
            for (int h = 0; h < 2; h++) {
                int row = r0 + h * 8;
                size_t base = ((size_t)(b * SEQ + row)) * INTER + c0;
                float2 u2 = *(const float2*)&g_u[base];
                g_t16[base]     = __half_as_ushort(__float2half_rn(u2.x * acc[mi][ng][h * 2]));
                g_t16[base + 1] = __half_as_ushort(__float2half_rn(u2.y * acc[mi][ng][h * 2 + 1]));
            }
        }
}

// ---------------- kernel 5: t @ Wo -> out  (fp16 2-term) --------------------
__global__ __launch_bounds__(256, 2)
void k_out(float* __restrict__ out)
{
    float acc[4][4][4] = {};
    const int rowBase = blockIdx.y * 128, colBase = blockIdx.x * 128;
    mma_gemm_2t(g_t16, INTER, g_Woh, g_Wol, HID,
                INTER, rowBase, colBase, acc);
    EPI_SETUP();
    #pragma unroll
    for (int mi = 0; mi < 4; mi++)
        #pragma unroll
        for (int ng = 0; ng < 4; ng++) {
            int r0 = rowBase + wm * 64 + mi * 16 + er;
            int c0 = colBase + wn * 32 + ng * 8 + ec;
            *(float2*)&out[(size_t)r0 * HID + c0] =
                make_float2(acc[mi][ng][0], acc[mi][ng][1]);
            *(float2*)&out[(size_t)(r0 + 8) * HID + c0] =
                make_float2(acc[mi][ng][2], acc[mi][ng][3]);
        }
}

// ---------------- launch ----------------------------------------------------
extern "C" void kernel_launch(void* const* d_in, const int* in_sizes, int n_in,
                              void* d_out, int out_size)
{
    const float* h    = (const float*)d_in[0];
    const float* Wi   = (const float*)d_in[1];
    const float* Wo   = (const float*)d_in[2];
    const float* qg   = (const float*)d_in[3];
    const float* kg   = (const float*)d_in[4];
    const int*   mask = (const int*)d_in[5];
    float*       out  = (float*)d_out;

    cudaFuncSetAttribute(k_gemm1, cudaFuncAttributeMaxDynamicSharedMemorySize, GEMM_SMEM);
    cudaFuncSetAttribute(k_qk,    cudaFuncAttributeMaxDynamicSharedMemorySize, GEMM_SMEM);
    cudaFuncSetAttribute(k_av,    cudaFuncAttributeMaxDynamicSharedMemorySize, GEMM_SMEM2);
    cudaFuncSetAttribute(k_out,   cudaFuncAttributeMaxDynamicSharedMemorySize, GEMM_SMEM2);

    int n4h  = MTOT * HID / 4;
    int n4wi = HID * NCOLS / 4;
    int n4wo = INTER * HID / 4;
    k_splitsel<<<(n4h  + 255) / 256, 256>>>((const float4*)h,  0, n4h);
    k_splitsel<<<(n4wi + 255) / 256, 256>>>((const float4*)Wi, 1, n4wi);
    k_splitsel<<<(n4wo + 255) / 256, 256>>>((const float4*)Wo, 2, n4wo);
    k_scale<<<BATCH, 256>>>(mask);

    k_gemm1<<<dim3(NCOLS / 128, MTOT / 128), 256, GEMM_SMEM>>>(qg, kg);
    k_qk<<<dim3(SEQ / 128, SEQ / 128, BATCH), 256, GEMM_SMEM>>>();
    k_softmax<<<BATCH * SEQ, 256>>>(mask);
    k_av<<<dim3(INTER / 128, SEQ / 128, BATCH), 256, GEMM_SMEM2>>>();
    k_out<<<dim3(HID / 128, MTOT / 128), 256, GEMM_SMEM2>>>(out);
}

// round 10
// speedup vs baseline: 1.5124x; 1.0086x over previous
#include <cuda_runtime.h>
#include <cuda_bf16.h>
#include <cuda_fp16.h>
#include <math.h>

#define HID   768
#define INTER 1536
#define DK    128
#define BATCH 4
#define SEQ   2048
#define MTOT  (BATCH*SEQ)          // 8192
#define NCOLS (2*INTER+DK)         // 3200
#define LOG512F 6.2383246250395075f
#define GEMM_SMEM  (3*4*512*16)    // 96 KB: 3 stages x 4 tiles (bf16x3 path)
#define GEMM_SMEM2 (4*3*512*16)    // 96 KB: 4 stages x 3 tiles (fp16x2 path)

#define N4H  (MTOT*HID/4)          // 1572864
#define N4WI (HID*NCOLS/4)         // 614400
#define N4WO (INTER*HID/4)         // 294912
#define N4TOT (N4H+N4WI+N4WO)

typedef unsigned short u16;

// ---------------- scratch (device globals) ---------------------------------
__device__ u16   g_Hh[(size_t)MTOT*HID],   g_Hl[(size_t)MTOT*HID];     // bf16
__device__ u16   g_Wih[(size_t)HID*NCOLS], g_Wil[(size_t)HID*NCOLS];   // bf16
__device__ u16   g_Woh[(size_t)INTER*HID], g_Wol[(size_t)INTER*HID];   // fp16
__device__ u16   g_u16[(size_t)MTOT*INTER];                             // fp16 gate
__device__ u16   g_vh[(size_t)MTOT*INTER], g_vl[(size_t)MTOT*INTER];   // fp16
__device__ u16   g_qh[(size_t)MTOT*DK],    g_ql[(size_t)MTOT*DK];      // bf16
__device__ u16   g_kh[(size_t)MTOT*DK],    g_kl[(size_t)MTOT*DK];      // bf16
__device__ float g_A [(size_t)BATCH*SEQ*SEQ];
__device__ u16   g_A16[(size_t)BATCH*SEQ*SEQ];                          // fp16 probs
__device__ u16   g_t16[(size_t)MTOT*INTER];                             // fp16 gated

// ---------------- PTX helpers ----------------------------------------------
__device__ __forceinline__ void mma_bf16(float c[4], const unsigned a[4], const unsigned b[2]) {
    asm volatile(
        "mma.sync.aligned.m16n8k16.row.col.f32.bf16.bf16.f32 "
        "{%0,%1,%2,%3}, {%4,%5,%6,%7}, {%8,%9}, {%0,%1,%2,%3};\n"
        : "+f"(c[0]), "+f"(c[1]), "+f"(c[2]), "+f"(c[3])
        : "r"(a[0]), "r"(a[1]), "r"(a[2]), "r"(a[3]), "r"(b[0]), "r"(b[1]));
}
__device__ __forceinline__ void mma_f16(float c[4], const unsigned a[4], const unsigned b[2]) {
    asm volatile(
        "mma.sync.aligned.m16n8k16.row.col.f32.f16.f16.f32 "
        "{%0,%1,%2,%3}, {%4,%5,%6,%7}, {%8,%9}, {%0,%1,%2,%3};\n"
        : "+f"(c[0]), "+f"(c[1]), "+f"(c[2]), "+f"(c[3])
        : "r"(a[0]), "r"(a[1]), "r"(a[2]), "r"(a[3]), "r"(b[0]), "r"(b[1]));
}
__device__ __forceinline__ void ldsm4(unsigned r[4], unsigned addr) {
    asm volatile("ldmatrix.sync.aligned.m8n8.x4.shared.b16 {%0,%1,%2,%3}, [%4];\n"
        : "=r"(r[0]), "=r"(r[1]), "=r"(r[2]), "=r"(r[3]) : "r"(addr));
}
__device__ __forceinline__ void ldsm4t(unsigned r[4], unsigned addr) {
    asm volatile("ldmatrix.sync.aligned.m8n8.x4.trans.shared.b16 {%0,%1,%2,%3}, [%4];\n"
        : "=r"(r[0]), "=r"(r[1]), "=r"(r[2]), "=r"(r[3]) : "r"(addr));
}
__device__ __forceinline__ void cp16(void* dst, const void* src) {
    unsigned d = (unsigned)__cvta_generic_to_shared(dst);
    asm volatile("cp.async.cg.shared.global [%0], [%1], 16;\n" :: "r"(d), "l"(src));
}
__device__ __forceinline__ void splitf(float x, u16& h, u16& l) {     // bf16 hi/lo
    __nv_bfloat16 hb = __float2bfloat16(x);
    h = __bfloat16_as_ushort(hb);
    l = __bfloat16_as_ushort(__float2bfloat16(x - __bfloat162float(hb)));
}
__device__ __forceinline__ void splith(float x, u16& h, u16& l) {     // fp16 hi/lo
    __half hb = __float2half_rn(x);
    h = __half_as_ushort(hb);
    l = __half_as_ushort(__float2half_rn(x - __half2float(hb)));
}

// ---------------- fused input split kernel ----------------------------------
__global__ __launch_bounds__(256)
void k_split(const float4* __restrict__ H, const float4* __restrict__ Wi,
             const float4* __restrict__ Wo)
{
    int i = blockIdx.x * 256 + threadIdx.x;
    if (i >= N4TOT) return;
    ushort4 Hh, Ll;
    if (i < N4H) {
        float4 f = H[i];
        splitf(f.x, Hh.x, Ll.x); splitf(f.y, Hh.y, Ll.y);
        splitf(f.z, Hh.z, Ll.z); splitf(f.w, Hh.w, Ll.w);
        ((ushort4*)g_Hh)[i] = Hh; ((ushort4*)g_Hl)[i] = Ll;
    } else if (i < N4H + N4WI) {
        int j = i - N4H;
        float4 f = Wi[j];
        splitf(f.x, Hh.x, Ll.x); splitf(f.y, Hh.y, Ll.y);
        splitf(f.z, Hh.z, Ll.z); splitf(f.w, Hh.w, Ll.w);
        ((ushort4*)g_Wih)[j] = Hh; ((ushort4*)g_Wil)[j] = Ll;
    } else {
        int j = i - N4H - N4WI;
        float4 f = Wo[j];
        splith(f.x, Hh.x, Ll.x); splith(f.y, Hh.y, Ll.y);
        splith(f.z, Hh.z, Ll.z); splith(f.w, Hh.w, Ll.w);
        ((ushort4*)g_Woh)[j] = Hh; ((ushort4*)g_Wol)[j] = Ll;
    }
}

// ---------------- tile stagers (cp.async, 256 threads) ----------------------
__device__ __forceinline__ void stage_tileA(uint4* dst, const u16* __restrict__ g,
                                            int ld, int tid) {
    #pragma unroll
    for (int r = 0; r < 2; r++) {
        int c = tid + r * 256;
        int row = c >> 2, kc = c & 3;
        cp16(dst + row * 4 + (kc ^ ((row >> 1) & 3)),
             g + (size_t)row * ld + kc * 8);
    }
}
__device__ __forceinline__ void stage_tileB(uint4* dst, const u16* __restrict__ g,
                                            int ld, int tid) {
    #pragma unroll
    for (int r = 0; r < 2; r++) {
        int c = tid + r * 256;
        int k = c >> 4, nc = c & 15;
        cp16(dst + k * 16 + (nc ^ (k & 7)),
             g + (size_t)k * ld + nc * 8);
    }
}

// ---------------- bf16x3 GEMM body (score path, 3-stage) --------------------
template<bool BT>
__device__ __forceinline__ void mma_gemm_pk(const u16* __restrict__ Ah, const u16* __restrict__ Al, int lda,
                                            const u16* __restrict__ Bh, const u16* __restrict__ Bl, int ldb,
                                            int K, int rowBase, int colBase,
                                            float acc[4][4][4])
{
    extern __shared__ __align__(16) uint4 smdyn[];
    const int tid = threadIdx.x;
    const int lane = tid & 31, w = tid >> 5;
    const int wm = w >> 2, wn = w & 3;
    const int g = lane >> 3, i = lane & 7;
    const int nsteps = K / 32;

    auto issue = [&](int step) {
        uint4* st = smdyn + (step % 3) * 2048;
        int k0 = step * 32;
        stage_tileA(st,        Ah + (size_t)rowBase * lda + k0, lda, tid);
        stage_tileA(st + 512,  Al + (size_t)rowBase * lda + k0, lda, tid);
        if (BT) {
            stage_tileA(st + 1024, Bh + (size_t)colBase * ldb + k0, ldb, tid);
            stage_tileA(st + 1536, Bl + (size_t)colBase * ldb + k0, ldb, tid);
        } else {
            stage_tileB(st + 1024, Bh + (size_t)k0 * ldb + colBase, ldb, tid);
            stage_tileB(st + 1536, Bl + (size_t)k0 * ldb + colBase, ldb, tid);
        }
        asm volatile("cp.async.commit_group;\n");
    };

    issue(0);
    if (nsteps > 1) issue(1);
    for (int step = 0; step < nsteps; step++) {
        if (step + 1 < nsteps)
            asm volatile("cp.async.wait_group 1;\n");
        else
            asm volatile("cp.async.wait_group 0;\n");
        __syncthreads();

        const uint4* st = smdyn + (step % 3) * 2048;
        const unsigned bAh = (unsigned)__cvta_generic_to_shared(st);
        const unsigned bAl = bAh + 8192;
        const unsigned bBh = bAh + 16384;
        const unsigned bBl = bAh + 24576;

        #pragma unroll
        for (int ks = 0; ks < 32; ks += 16) {
            unsigned aH[4][4], aL[4][4];
            #pragma unroll
            for (int mi = 0; mi < 4; mi++) {
                int mrow = wm * 64 + mi * 16 + (g & 1) * 8 + i;
                int ch = (ks >> 3) + (g >> 1);
                int off = mrow * 64 + ((ch ^ ((mrow >> 1) & 3)) << 4);
                ldsm4(aH[mi], bAh + off);
                ldsm4(aL[mi], bAl + off);
            }
            unsigned bH[4][2], bL[4][2];
            #pragma unroll
            for (int p = 0; p < 2; p++) {
                unsigned rh[4], rl[4];
                if (BT) {
                    int nrow = wn * 32 + p * 16 + (g >> 1) * 8 + i;
                    int ch = (ks >> 3) + (g & 1);
                    int off = nrow * 64 + ((ch ^ ((nrow >> 1) & 3)) << 4);
                    ldsm4(rh, bBh + off);
                    ldsm4(rl, bBl + off);
                } else {
                    int kr = ks + (g & 1) * 8 + i;
                    int nl = wn * 32 + p * 16 + (g >> 1) * 8;
                    int off = kr * 256 + ((((nl >> 3) ^ (kr & 7))) << 4);
                    ldsm4t(rh, bBh + off);
                    ldsm4t(rl, bBl + off);
                }
                bH[2*p][0] = rh[0]; bH[2*p][1] = rh[1];
                bH[2*p+1][0] = rh[2]; bH[2*p+1][1] = rh[3];
                bL[2*p][0] = rl[0]; bL[2*p][1] = rl[1];
                bL[2*p+1][0] = rl[2]; bL[2*p+1][1] = rl[3];
            }
            #pragma unroll
            for (int mi = 0; mi < 4; mi++)
                #pragma unroll
                for (int ng = 0; ng < 4; ng++)
                    mma_bf16(acc[mi][ng], aH[mi], bH[ng]);
            #pragma unroll
            for (int mi = 0; mi < 4; mi++)
                #pragma unroll
                for (int ng = 0; ng < 4; ng++)
                    mma_bf16(acc[mi][ng], aH[mi], bL[ng]);
            #pragma unroll
            for (int mi = 0; mi < 4; mi++)
                #pragma unroll
                for (int ng = 0; ng < 4; ng++)
                    mma_bf16(acc[mi][ng], aL[mi], bH[ng]);
        }
        if (step + 2 < nsteps) issue(step + 2);
    }
}

// ---------------- fp16 2-term GEMM body (value path, 4-stage) ---------------
__device__ __forceinline__ void mma_gemm_2t(const u16* __restrict__ Aa, int lda,
                                            const u16* __restrict__ Bh, const u16* __restrict__ Bl, int ldb,
                                            int K, int rowBase, int colBase,
                                            float acc[4][4][4])
{
    extern __shared__ __align__(16) uint4 smdyn[];
    const int tid = threadIdx.x;
    const int lane = tid & 31, w = tid >> 5;
    const int wm = w >> 2, wn = w & 3;
    const int g = lane >> 3, i = lane & 7;
    const int nsteps = K / 32;

    auto issue = [&](int step) {
        uint4* st = smdyn + (step & 3) * 1536;
        int k0 = step * 32;
        stage_tileA(st,        Aa + (size_t)rowBase * lda + k0, lda, tid);
        stage_tileB(st + 512,  Bh + (size_t)k0 * ldb + colBase, ldb, tid);
        stage_tileB(st + 1024, Bl + (size_t)k0 * ldb + colBase, ldb, tid);
        asm volatile("cp.async.commit_group;\n");
    };

    issue(0);
    if (nsteps > 1) issue(1);
    if (nsteps > 2) issue(2);
    for (int step = 0; step < nsteps; step++) {
        if (step + 2 < nsteps)
            asm volatile("cp.async.wait_group 2;\n");
        else if (step + 1 < nsteps)
            asm volatile("cp.async.wait_group 1;\n");
        else
            asm volatile("cp.async.wait_group 0;\n");
        __syncthreads();

        const uint4* st = smdyn + (step & 3) * 1536;
        const unsigned bA  = (unsigned)__cvta_generic_to_shared(st);
        const unsigned bBh = bA + 8192;
        const unsigned bBl = bA + 16384;

        #pragma unroll
        for (int ks = 0; ks < 32; ks += 16) {
            unsigned aF[4][4];
            #pragma unroll
            for (int mi = 0; mi < 4; mi++) {
                int mrow = wm * 64 + mi * 16 + (g & 1) * 8 + i;
                int ch = (ks >> 3) + (g >> 1);
                int off = mrow * 64 + ((ch ^ ((mrow >> 1) & 3)) << 4);
                ldsm4(aF[mi], bA + off);
            }
            unsigned bH[4][2], bL[4][2];
            #pragma unroll
            for (int p = 0; p < 2; p++) {
                unsigned rh[4], rl[4];
                int kr = ks + (g & 1) * 8 + i;
                int nl = wn * 32 + p * 16 + (g >> 1) * 8;
                int off = kr * 256 + ((((nl >> 3) ^ (kr & 7))) << 4);
                ldsm4t(rh, bBh + off);
                ldsm4t(rl, bBl + off);
                bH[2*p][0] = rh[0]; bH[2*p][1] = rh[1];
                bH[2*p+1][0] = rh[2]; bH[2*p+1][1] = rh[3];
                bL[2*p][0] = rl[0]; bL[2*p][1] = rl[1];
                bL[2*p+1][0] = rl[2]; bL[2*p+1][1] = rl[3];
            }
            #pragma unroll
            for (int mi = 0; mi < 4; mi++)
                #pragma unroll
                for (int ng = 0; ng < 4; ng++)
                    mma_f16(acc[mi][ng], aF[mi], bH[ng]);
            #pragma unroll
            for (int mi = 0; mi < 4; mi++)
                #pragma unroll
                for (int ng = 0; ng < 4; ng++)
                    mma_f16(acc[mi][ng], aF[mi], bL[ng]);
        }
        if (step + 3 < nsteps) issue(step + 3);
    }
}

#define EPI_SETUP() \
    const int lane = threadIdx.x & 31, w = threadIdx.x >> 5; \
    const int wm = w >> 2, wn = w & 3; \
    const int er = lane >> 2, ec = (lane & 3) * 2;

// ---------------- kernel 1: GEMM1 + SiLU + split ---------------------------
__global__ __launch_bounds__(256, 2)
void k_gemm1(const float* __restrict__ qg, const float* __restrict__ kg)
{
    float acc[4][4][4] = {};
    const int rowBase = blockIdx.y * 128, colBase = blockIdx.x * 128;
    mma_gemm_pk<false>(g_Hh, g_Hl, HID, g_Wih, g_Wil, NCOLS, HID, rowBase, colBase, acc);
    EPI_SETUP();
    #pragma unroll
    for (int mi = 0; mi < 4; mi++)
        #pragma unroll
        for (int ng = 0; ng < 4; ng++) {
            int r0 = rowBase + wm * 64 + mi * 16 + er;
            int c0 = colBase + wn * 32 + ng * 8 + ec;
            #pragma unroll
            for (int h = 0; h < 2; h++) {
                int row = r0 + h * 8;
                #pragma unroll
                for (int j = 0; j < 2; j++) {
                    int col = c0 + j;
                    float x = acc[mi][ng][h * 2 + j];
                    float v = x / (1.0f + __expf(-x));  // SiLU
                    if (col < INTER) {
                        g_u16[(size_t)row * INTER + col] =
                            __half_as_ushort(__float2half_rn(v));
                    } else if (col < 2 * INTER) {
                        size_t idx = (size_t)row * INTER + (col - INTER);
                        splith(v, g_vh[idx], g_vl[idx]);
                    } else {
                        int c = col - 2 * INTER;
                        size_t idx = (size_t)row * DK + c;
                        float sq = qg[c] * kg[c] * 0.08838834764831845f;
                        splitf(v * sq, g_qh[idx], g_ql[idx]);
                        splitf(v,      g_kh[idx], g_kl[idx]);
                    }
                }
            }
        }
}

// ---------------- kernel 2: Q' @ K'^T, symmetric (lower triangle) -----------
__global__ __launch_bounds__(256, 2)
void k_qk()
{
    extern __shared__ __align__(16) uint4 smdyn[];
    float acc[4][4][4] = {};
    const int b = blockIdx.z;
    // map linear tile id -> (ty >= tx) lower-triangle pair
    int t = blockIdx.x;
    int ty = (int)((__fsqrt_rn(8.f * t + 1.f) - 1.f) * 0.5f);
    while ((ty + 1) * (ty + 2) / 2 <= t) ty++;
    while (ty * (ty + 1) / 2 > t) ty--;
    int tx = t - ty * (ty + 1) / 2;
    const int rowBase = ty * 128, colBase = tx * 128;

    const size_t o = (size_t)b * SEQ * DK;
    mma_gemm_pk<true>(g_qh + o, g_ql + o, DK, g_kh + o, g_kl + o, DK,
                      DK, rowBase, colBase, acc);
    float* Ab = g_A + (size_t)b * SEQ * SEQ;

    // stage accumulators to smem (pitch 129 floats) for coalesced + mirrored writes
    __syncthreads();
    float* sT = (float*)smdyn;
    EPI_SETUP();
    #pragma unroll
    for (int mi = 0; mi < 4; mi++)
        #pragma unroll
        for (int ng = 0; ng < 4; ng++) {
            int r = wm * 64 + mi * 16 + er;
            int c = wn * 32 + ng * 8 + ec;
            sT[r * 129 + c]           = acc[mi][ng][0];
            sT[r * 129 + c + 1]       = acc[mi][ng][1];
            sT[(r + 8) * 129 + c]     = acc[mi][ng][2];
            sT[(r + 8) * 129 + c + 1] = acc[mi][ng][3];
        }
    __syncthreads();

    const int tid = threadIdx.x;
    const int r2 = tid >> 1, half = tid & 1;
    #pragma unroll
    for (int cc = 0; cc < 16; cc++) {
        int c = half * 64 + cc * 4;
        float4 v;
        v.x = sT[r2 * 129 + c];     v.y = sT[r2 * 129 + c + 1];
        v.z = sT[r2 * 129 + c + 2]; v.w = sT[r2 * 129 + c + 3];
        *(float4*)&Ab[(size_t)(rowBase + r2) * SEQ + colBase + c] = v;
    }
    if (ty != tx) {
        #pragma unroll
        for (int cc = 0; cc < 16; cc++) {
            int c = half * 64 + cc * 4;
            float4 v;
            v.x = sT[c * 129 + r2];       v.y = sT[(c + 1) * 129 + r2];
            v.z = sT[(c + 2) * 129 + r2]; v.w = sT[(c + 3) * 129 + r2];
            *(float4*)&Ab[(size_t)(colBase + r2) * SEQ + rowBase + c] = v;
        }
    }
}

// ---------------- kernel 3: masked softmax (inline mask count) --------------
__global__ __launch_bounds__(256)
void k_softmax(const int* __restrict__ mask)
{
    const int bm = blockIdx.x;
    const int b = bm >> 11;
    const int m = bm & (SEQ - 1);
    const int tid = threadIdx.x;
    const int lane = tid & 31, wrp = tid >> 5;

    __shared__ float redm[8], redc[8], reds[8];
    const size_t rowoff = (size_t)b * SEQ * SEQ + (size_t)m * SEQ;
    const float* row = g_A + rowoff;

    float a[8];
    float mx = -3.4e38f, cnt = 0.f;
    #pragma unroll
    for (int k2 = 0; k2 < 8; k2++) {
        int n = tid + k2 * 256;
        float x = row[n];
        int mv = mask[b * SEQ + n];
        cnt += (float)mv;
        if (mv == 0) x = -1e12f;
        a[k2] = x;
        mx = fmaxf(mx, x);
    }
    #pragma unroll
    for (int s = 16; s > 0; s >>= 1) {
        mx = fmaxf(mx, __shfl_xor_sync(0xffffffffu, mx, s));
        cnt += __shfl_xor_sync(0xffffffffu, cnt, s);
    }
    if (lane == 0) { redm[wrp] = mx; redc[wrp] = cnt; }
    __syncthreads();
    mx = redm[lane & 7]; cnt = redc[lane & 7];
    #pragma unroll
    for (int s = 4; s > 0; s >>= 1) {
        mx = fmaxf(mx, __shfl_xor_sync(0xffffffffu, mx, s));
        cnt += __shfl_xor_sync(0xffffffffu, cnt, s);
    }
    const float scale = logf(fmaxf(cnt, 1.0f)) * (1.0f / LOG512F);
    const float mxs = mx * scale;

    float sm = 0.f;
    #pragma unroll
    for (int k2 = 0; k2 < 8; k2++) {
        float e = __expf(a[k2] * scale - mxs);
        a[k2] = e;
        sm += e;
    }
    #pragma unroll
    for (int s = 16; s > 0; s >>= 1)
        sm += __shfl_xor_sync(0xffffffffu, sm, s);
    if (lane == 0) reds[wrp] = sm;
    __syncthreads();
    sm = reds[lane & 7];
    #pragma unroll
    for (int s = 4; s > 0; s >>= 1)
        sm += __shfl_xor_sync(0xffffffffu, sm, s);
    const float inv = 1.0f / sm;

    #pragma unroll
    for (int k2 = 0; k2 < 8; k2++) {
        int n = tid + k2 * 256;
        g_A16[rowoff + n] = __half_as_ushort(__float2half_rn(a[k2] * inv));
    }
}

// ---------------- kernel 4: (A @ V) * u  (fp16 2-term) ----------------------
__global__ __launch_bounds__(256, 2)
void k_av()
{
    float acc[4][4][4] = {};
    const int b = blockIdx.z;
    const int rowBase = blockIdx.y * 128, colBase = blockIdx.x * 128;
    const size_t oa = (size_t)b * SEQ * SEQ;
    const size_t ov = (size_t)b * SEQ * INTER;
    mma_gemm_2t(g_A16 + oa, SEQ, g_vh + ov, g_vl + ov, INTER,
                SEQ, rowBase, colBase, acc);
    EPI_SETUP();
    #pragma unroll
    for (int mi = 0; mi < 4; mi++)
        #pragma unroll
        for (int ng = 0; ng < 4; ng++) {
            int r0 = rowBase + wm * 64 + mi * 16 + er;
            int c0 = colBase + wn * 32 + ng * 8 + ec;
            #pragma unroll
            for (int h = 0; h < 2; h++) {
                int row = r0 + h * 8;
                size_t base = ((size_t)(b * SEQ + row)) * INTER + c0;
                __half2 u2 = *(const __half2*)&g_u16[base];
                g_t16[base]     = __half_as_ushort(
                    __float2half_rn(__half2float(__low2half(u2))  * acc[mi][ng][h * 2]));
                g_t16[base + 1] = __half_as_ushort(
                    __float2half_rn(__half2float(__high2half(u2)) * acc[mi][ng][h * 2 + 1]));
            }
        }
}

// ---------------- kernel 5: t @ Wo -> out  (fp16 2-term) --------------------
__global__ __launch_bounds__(256, 2)
void k_out(float* __restrict__ out)
{
    float acc[4][4][4] = {};
    const int rowBase = blockIdx.y * 128, colBase = blockIdx.x * 128;
    mma_gemm_2t(g_t16, INTER, g_Woh, g_Wol, HID,
                INTER, rowBase, colBase, acc);
    EPI_SETUP();
    #pragma unroll
    for (int mi = 0; mi < 4; mi++)
        #pragma unroll
        for (int ng = 0; ng < 4; ng++) {
            int r0 = rowBase + wm * 64 + mi * 16 + er;
            int c0 = colBase + wn * 32 + ng * 8 + ec;
            *(float2*)&out[(size_t)r0 * HID + c0] =
                make_float2(acc[mi][ng][0], acc[mi][ng][1]);
            *(float2*)&out[(size_t)(r0 + 8) * HID + c0] =
                make_float2(acc[mi][ng][2], acc[mi][ng][3]);
        }
}

// ---------------- launch ----------------------------------------------------
extern "C" void kernel_launch(void* const* d_in, const int* in_sizes, int n_in,
                              void* d_out, int out_size)
{
    const float* h    = (const float*)d_in[0];
    const float* Wi   = (const float*)d_in[1];
    const float* Wo   = (const float*)d_in[2];
    const float* qg   = (const float*)d_in[3];
    const float* kg   = (const float*)d_in[4];
    const int*   mask = (const int*)d_in[5];
    float*       out  = (float*)d_out;

    cudaFuncSetAttribute(k_gemm1, cudaFuncAttributeMaxDynamicSharedMemorySize, GEMM_SMEM);
    cudaFuncSetAttribute(k_qk,    cudaFuncAttributeMaxDynamicSharedMemorySize, GEMM_SMEM);
    cudaFuncSetAttribute(k_av,    cudaFuncAttributeMaxDynamicSharedMemorySize, GEMM_SMEM2);
    cudaFuncSetAttribute(k_out,   cudaFuncAttributeMaxDynamicSharedMemorySize, GEMM_SMEM2);

    k_split<<<(N4TOT + 255) / 256, 256>>>((const float4*)h, (const float4*)Wi,
                                          (const float4*)Wo);

    k_gemm1<<<dim3(NCOLS / 128, MTOT / 128), 256, GEMM_SMEM>>>(qg, kg);
    k_qk<<<dim3(136, 1, BATCH), 256, GEMM_SMEM>>>();
    k_softmax<<<BATCH * SEQ, 256>>>(mask);
    k_av<<<dim3(INTER / 128, SEQ / 128, BATCH), 256, GEMM_SMEM2>>>();
    k_out<<<dim3(HID / 128, MTOT / 128), 256, GEMM_SMEM2>>>(out);
}

// round 11
// speedup vs baseline: 1.9269x; 1.2741x over previous
#include <cuda_runtime.h>
#include <cuda_bf16.h>
#include <cuda_fp16.h>
#include <math.h>

#define HID   768
#define INTER 1536
#define DK    128
#define BATCH 4
#define SEQ   2048
#define MTOT  (BATCH*SEQ)          // 8192
#define NCOLS (2*INTER+DK)         // 3200
#define LOG512F 6.2383246250395075f
#define GEMM_SMEM  (3*4*512*16)    // 96 KB: 3 stages x 4 tiles (bf16x3 path)
#define GEMM_SMEM2 (4*3*512*16)    // 96 KB: 4 stages x 3 tiles (fp16 2-term)
#define GEMM_SMEM1 (4*2*512*16)    // 64 KB: 4 stages x 2 tiles (fp16 1-term)

#define N4H  (MTOT*HID/4)
#define N4WI (HID*NCOLS/4)
#define N4WO (INTER*HID/4)
#define N4TOT (N4H+N4WI+N4WO)

typedef unsigned short u16;

// ---------------- scratch (device globals) ---------------------------------
__device__ u16   g_H16[(size_t)MTOT*HID];                               // fp16
__device__ u16   g_Hh[(size_t)MTOT*HID],   g_Hl[(size_t)MTOT*HID];     // bf16 (qk path)
__device__ u16   g_Wifh[(size_t)HID*NCOLS], g_Wifl[(size_t)HID*NCOLS]; // fp16 hi/lo
__device__ u16   g_Wih[(size_t)HID*NCOLS], g_Wil[(size_t)HID*NCOLS];   // bf16 hi/lo
__device__ u16   g_Woh[(size_t)INTER*HID], g_Wol[(size_t)INTER*HID];   // fp16 hi/lo
__device__ u16   g_u16[(size_t)MTOT*INTER];                             // fp16 gate
__device__ u16   g_v16[(size_t)MTOT*INTER];                             // fp16 value
__device__ u16   g_qh[(size_t)MTOT*DK],    g_ql[(size_t)MTOT*DK];      // bf16
__device__ u16   g_kh[(size_t)MTOT*DK],    g_kl[(size_t)MTOT*DK];      // bf16
__device__ float g_A [(size_t)BATCH*SEQ*SEQ];
__device__ u16   g_A16[(size_t)BATCH*SEQ*SEQ];                          // fp16 probs
__device__ u16   g_t16[(size_t)MTOT*INTER];                             // fp16 gated

// ---------------- PTX helpers ----------------------------------------------
__device__ __forceinline__ void mma_bf16(float c[4], const unsigned a[4], const unsigned b[2]) {
    asm volatile(
        "mma.sync.aligned.m16n8k16.row.col.f32.bf16.bf16.f32 "
        "{%0,%1,%2,%3}, {%4,%5,%6,%7}, {%8,%9}, {%0,%1,%2,%3};\n"
        : "+f"(c[0]), "+f"(c[1]), "+f"(c[2]), "+f"(c[3])
        : "r"(a[0]), "r"(a[1]), "r"(a[2]), "r"(a[3]), "r"(b[0]), "r"(b[1]));
}
__device__ __forceinline__ void mma_f16(float c[4], const unsigned a[4], const unsigned b[2]) {
    asm volatile(
        "mma.sync.aligned.m16n8k16.row.col.f32.f16.f16.f32 "
        "{%0,%1,%2,%3}, {%4,%5,%6,%7}, {%8,%9}, {%0,%1,%2,%3};\n"
        : "+f"(c[0]), "+f"(c[1]), "+f"(c[2]), "+f"(c[3])
        : "r"(a[0]), "r"(a[1]), "r"(a[2]), "r"(a[3]), "r"(b[0]), "r"(b[1]));
}
__device__ __forceinline__ void ldsm4(unsigned r[4], unsigned addr) {
    asm volatile("ldmatrix.sync.aligned.m8n8.x4.shared.b16 {%0,%1,%2,%3}, [%4];\n"
        : "=r"(r[0]), "=r"(r[1]), "=r"(r[2]), "=r"(r[3]) : "r"(addr));
}
__device__ __forceinline__ void ldsm4t(unsigned r[4], unsigned addr) {
    asm volatile("ldmatrix.sync.aligned.m8n8.x4.trans.shared.b16 {%0,%1,%2,%3}, [%4];\n"
        : "=r"(r[0]), "=r"(r[1]), "=r"(r[2]), "=r"(r[3]) : "r"(addr));
}
__device__ __forceinline__ void cp16(void* dst, const void* src) {
    unsigned d = (unsigned)__cvta_generic_to_shared(dst);
    asm volatile("cp.async.cg.shared.global [%0], [%1], 16;\n" :: "r"(d), "l"(src));
}
__device__ __forceinline__ void splitf(float x, u16& h, u16& l) {     // bf16 hi/lo
    __nv_bfloat16 hb = __float2bfloat16(x);
    h = __bfloat16_as_ushort(hb);
    l = __bfloat16_as_ushort(__float2bfloat16(x - __bfloat162float(hb)));
}
__device__ __forceinline__ void splith(float x, u16& h, u16& l) {     // fp16 hi/lo
    __half hb = __float2half_rn(x);
    h = __half_as_ushort(hb);
    l = __half_as_ushort(__float2half_rn(x - __half2float(hb)));
}

// ---------------- fused input split kernel ----------------------------------
__global__ __launch_bounds__(256)
void k_split(const float4* __restrict__ H, const float4* __restrict__ Wi,
             const float4* __restrict__ Wo)
{
    int i = blockIdx.x * 256 + threadIdx.x;
    if (i >= N4TOT) return;
    ushort4 Hh, Ll;
    if (i < N4H) {
        float4 f = H[i];
        // fp16 single
        ushort4 F;
        F.x = __half_as_ushort(__float2half_rn(f.x));
        F.y = __half_as_ushort(__float2half_rn(f.y));
        F.z = __half_as_ushort(__float2half_rn(f.z));
        F.w = __half_as_ushort(__float2half_rn(f.w));
        ((ushort4*)g_H16)[i] = F;
        // bf16 hi/lo (qk path)
        splitf(f.x, Hh.x, Ll.x); splitf(f.y, Hh.y, Ll.y);
        splitf(f.z, Hh.z, Ll.z); splitf(f.w, Hh.w, Ll.w);
        ((ushort4*)g_Hh)[i] = Hh; ((ushort4*)g_Hl)[i] = Ll;
    } else if (i < N4H + N4WI) {
        int j = i - N4H;
        float4 f = Wi[j];
        // fp16 hi/lo (uv path)
        splith(f.x, Hh.x, Ll.x); splith(f.y, Hh.y, Ll.y);
        splith(f.z, Hh.z, Ll.z); splith(f.w, Hh.w, Ll.w);
        ((ushort4*)g_Wifh)[j] = Hh; ((ushort4*)g_Wifl)[j] = Ll;
        // bf16 hi/lo (qk path)
        splitf(f.x, Hh.x, Ll.x); splitf(f.y, Hh.y, Ll.y);
        splitf(f.z, Hh.z, Ll.z); splitf(f.w, Hh.w, Ll.w);
        ((ushort4*)g_Wih)[j] = Hh; ((ushort4*)g_Wil)[j] = Ll;
    } else {
        int j = i - N4H - N4WI;
        float4 f = Wo[j];
        splith(f.x, Hh.x, Ll.x); splith(f.y, Hh.y, Ll.y);
        splith(f.z, Hh.z, Ll.z); splith(f.w, Hh.w, Ll.w);
        ((ushort4*)g_Woh)[j] = Hh; ((ushort4*)g_Wol)[j] = Ll;
    }
}

// ---------------- tile stagers (cp.async, 256 threads) ----------------------
__device__ __forceinline__ void stage_tileA(uint4* dst, const u16* __restrict__ g,
                                            int ld, int tid) {
    #pragma unroll
    for (int r = 0; r < 2; r++) {
        int c = tid + r * 256;
        int row = c >> 2, kc = c & 3;
        cp16(dst + row * 4 + (kc ^ ((row >> 1) & 3)),
             g + (size_t)row * ld + kc * 8);
    }
}
__device__ __forceinline__ void stage_tileB(uint4* dst, const u16* __restrict__ g,
                                            int ld, int tid) {
    #pragma unroll
    for (int r = 0; r < 2; r++) {
        int c = tid + r * 256;
        int k = c >> 4, nc = c & 15;
        cp16(dst + k * 16 + (nc ^ (k & 7)),
             g + (size_t)k * ld + nc * 8);
    }
}

// ---------------- bf16x3 GEMM body (score path, 3-stage) --------------------
template<bool BT>
__device__ __forceinline__ void mma_gemm_pk(const u16* __restrict__ Ah, const u16* __restrict__ Al, int lda,
                                            const u16* __restrict__ Bh, const u16* __restrict__ Bl, int ldb,
                                            int K, int rowBase, int colBase,
                                            float acc[4][4][4])
{
    extern __shared__ __align__(16) uint4 smdyn[];
    const int tid = threadIdx.x;
    const int lane = tid & 31, w = tid >> 5;
    const int wm = w >> 2, wn = w & 3;
    const int g = lane >> 3, i = lane & 7;
    const int nsteps = K / 32;

    auto issue = [&](int step) {
        uint4* st = smdyn + (step % 3) * 2048;
        int k0 = step * 32;
        stage_tileA(st,        Ah + (size_t)rowBase * lda + k0, lda, tid);
        stage_tileA(st + 512,  Al + (size_t)rowBase * lda + k0, lda, tid);
        if (BT) {
            stage_tileA(st + 1024, Bh + (size_t)colBase * ldb + k0, ldb, tid);
            stage_tileA(st + 1536, Bl + (size_t)colBase * ldb + k0, ldb, tid);
        } else {
            stage_tileB(st + 1024, Bh + (size_t)k0 * ldb + colBase, ldb, tid);
            stage_tileB(st + 1536, Bl + (size_t)k0 * ldb + colBase, ldb, tid);
        }
        asm volatile("cp.async.commit_group;\n");
    };

    issue(0);
    if (nsteps > 1) issue(1);
    for (int step = 0; step < nsteps; step++) {
        if (step + 1 < nsteps)
            asm volatile("cp.async.wait_group 1;\n");
        else
            asm volatile("cp.async.wait_group 0;\n");
        __syncthreads();

        const uint4* st = smdyn + (step % 3) * 2048;
        const unsigned bAh = (unsigned)__cvta_generic_to_shared(st);
        const unsigned bAl = bAh + 8192;
        const unsigned bBh = bAh + 16384;
        const unsigned bBl = bAh + 24576;

        #pragma unroll
        for (int ks = 0; ks < 32; ks += 16) {
            unsigned aH[4][4], aL[4][4];
            #pragma unroll
            for (int mi = 0; mi < 4; mi++) {
                int mrow = wm * 64 + mi * 16 + (g & 1) * 8 + i;
                int ch = (ks >> 3) + (g >> 1);
                int off = mrow * 64 + ((ch ^ ((mrow >> 1) & 3)) << 4);
                ldsm4(aH[mi], bAh + off);
                ldsm4(aL[mi], bAl + off);
            }
            unsigned bH[4][2], bL[4][2];
            #pragma unroll
            for (int p = 0; p < 2; p++) {
                unsigned rh[4], rl[4];
                if (BT) {
                    int nrow = wn * 32 + p * 16 + (g >> 1) * 8 + i;
                    int ch = (ks >> 3) + (g & 1);
                    int off = nrow * 64 + ((ch ^ ((nrow >> 1) & 3)) << 4);
                    ldsm4(rh, bBh + off);
                    ldsm4(rl, bBl + off);
                } else {
                    int kr = ks + (g & 1) * 8 + i;
                    int nl = wn * 32 + p * 16 + (g >> 1) * 8;
                    int off = kr * 256 + ((((nl >> 3) ^ (kr & 7))) << 4);
                    ldsm4t(rh, bBh + off);
                    ldsm4t(rl, bBl + off);
                }
                bH[2*p][0] = rh[0]; bH[2*p][1] = rh[1];
                bH[2*p+1][0] = rh[2]; bH[2*p+1][1] = rh[3];
                bL[2*p][0] = rl[0]; bL[2*p][1] = rl[1];
                bL[2*p+1][0] = rl[2]; bL[2*p+1][1] = rl[3];
            }
            #pragma unroll
            for (int mi = 0; mi < 4; mi++)
                #pragma unroll
                for (int ng = 0; ng < 4; ng++)
                    mma_bf16(acc[mi][ng], aH[mi], bH[ng]);
            #pragma unroll
            for (int mi = 0; mi < 4; mi++)
                #pragma unroll
                for (int ng = 0; ng < 4; ng++)
                    mma_bf16(acc[mi][ng], aH[mi], bL[ng]);
            #pragma unroll
            for (int mi = 0; mi < 4; mi++)
                #pragma unroll
                for (int ng = 0; ng < 4; ng++)
                    mma_bf16(acc[mi][ng], aL[mi], bH[ng]);
        }
        if (step + 2 < nsteps) issue(step + 2);
    }
}

// ---------------- fp16 2-term GEMM body (4-stage) ---------------------------
__device__ __forceinline__ void mma_gemm_2t(const u16* __restrict__ Aa, int lda,
                                            const u16* __restrict__ Bh, const u16* __restrict__ Bl, int ldb,
                                            int K, int rowBase, int colBase,
                                            float acc[4][4][4])
{
    extern __shared__ __align__(16) uint4 smdyn[];
    const int tid = threadIdx.x;
    const int lane = tid & 31, w = tid >> 5;
    const int wm = w >> 2, wn = w & 3;
    const int g = lane >> 3, i = lane & 7;
    const int nsteps = K / 32;

    auto issue = [&](int step) {
        uint4* st = smdyn + (step & 3) * 1536;
        int k0 = step * 32;
        stage_tileA(st,        Aa + (size_t)rowBase * lda + k0, lda, tid);
        stage_tileB(st + 512,  Bh + (size_t)k0 * ldb + colBase, ldb, tid);
        stage_tileB(st + 1024, Bl + (size_t)k0 * ldb + colBase, ldb, tid);
        asm volatile("cp.async.commit_group;\n");
    };

    issue(0);
    if (nsteps > 1) issue(1);
    if (nsteps > 2) issue(2);
    for (int step = 0; step < nsteps; step++) {
        if (step + 2 < nsteps)
            asm volatile("cp.async.wait_group 2;\n");
        else if (step + 1 < nsteps)
            asm volatile("cp.async.wait_group 1;\n");
        else
            asm volatile("cp.async.wait_group 0;\n");
        __syncthreads();

        const uint4* st = smdyn + (step & 3) * 1536;
        const unsigned bA  = (unsigned)__cvta_generic_to_shared(st);
        const unsigned bBh = bA + 8192;
        const unsigned bBl = bA + 16384;

        #pragma unroll
        for (int ks = 0; ks < 32; ks += 16) {
            unsigned aF[4][4];
            #pragma unroll
            for (int mi = 0; mi < 4; mi++) {
                int mrow = wm * 64 + mi * 16 + (g & 1) * 8 + i;
                int ch = (ks >> 3) + (g >> 1);
                int off = mrow * 64 + ((ch ^ ((mrow >> 1) & 3)) << 4);
                ldsm4(aF[mi], bA + off);
            }
            unsigned bH[4][2], bL[4][2];
            #pragma unroll
            for (int p = 0; p < 2; p++) {
                unsigned rh[4], rl[4];
                int kr = ks + (g & 1) * 8 + i;
                int nl = wn * 32 + p * 16 + (g >> 1) * 8;
                int off = kr * 256 + ((((nl >> 3) ^ (kr & 7))) << 4);
                ldsm4t(rh, bBh + off);
                ldsm4t(rl, bBl + off);
                bH[2*p][0] = rh[0]; bH[2*p][1] = rh[1];
                bH[2*p+1][0] = rh[2]; bH[2*p+1][1] = rh[3];
                bL[2*p][0] = rl[0]; bL[2*p][1] = rl[1];
                bL[2*p+1][0] = rl[2]; bL[2*p+1][1] = rl[3];
            }
            #pragma unroll
            for (int mi = 0; mi < 4; mi++)
                #pragma unroll
                for (int ng = 0; ng < 4; ng++)
                    mma_f16(acc[mi][ng], aF[mi], bH[ng]);
            #pragma unroll
            for (int mi = 0; mi < 4; mi++)
                #pragma unroll
                for (int ng = 0; ng < 4; ng++)
                    mma_f16(acc[mi][ng], aF[mi], bL[ng]);
        }
        if (step + 3 < nsteps) issue(step + 3);
    }
}

// ---------------- fp16 single-term GEMM body (4-stage) ----------------------
__device__ __forceinline__ void mma_gemm_1t(const u16* __restrict__ Aa, int lda,
                                            const u16* __restrict__ Bb, int ldb,
                                            int K, int rowBase, int colBase,
                                            float acc[4][4][4])
{
    extern __shared__ __align__(16) uint4 smdyn[];
    const int tid = threadIdx.x;
    const int lane = tid & 31, w = tid >> 5;
    const int wm = w >> 2, wn = w & 3;
    const int g = lane >> 3, i = lane & 7;
    const int nsteps = K / 32;

    auto issue = [&](int step) {
        uint4* st = smdyn + (step & 3) * 1024;
        int k0 = step * 32;
        stage_tileA(st,       Aa + (size_t)rowBase * lda + k0, lda, tid);
        stage_tileB(st + 512, Bb + (size_t)k0 * ldb + colBase, ldb, tid);
        asm volatile("cp.async.commit_group;\n");
    };

    issue(0);
    if (nsteps > 1) issue(1);
    if (nsteps > 2) issue(2);
    for (int step = 0; step < nsteps; step++) {
        if (step + 2 < nsteps)
            asm volatile("cp.async.wait_group 2;\n");
        else if (step + 1 < nsteps)
            asm volatile("cp.async.wait_group 1;\n");
        else
            asm volatile("cp.async.wait_group 0;\n");
        __syncthreads();

        const uint4* st = smdyn + (step & 3) * 1024;
        const unsigned bA = (unsigned)__cvta_generic_to_shared(st);
        const unsigned bB = bA + 8192;

        #pragma unroll
        for (int ks = 0; ks < 32; ks += 16) {
            unsigned aF[4][4];
            #pragma unroll
            for (int mi = 0; mi < 4; mi++) {
                int mrow = wm * 64 + mi * 16 + (g & 1) * 8 + i;
                int ch = (ks >> 3) + (g >> 1);
                int off = mrow * 64 + ((ch ^ ((mrow >> 1) & 3)) << 4);
                ldsm4(aF[mi], bA + off);
            }
            unsigned bF[4][2];
            #pragma unroll
            for (int p = 0; p < 2; p++) {
                unsigned rh[4];
                int kr = ks + (g & 1) * 8 + i;
                int nl = wn * 32 + p * 16 + (g >> 1) * 8;
                int off = kr * 256 + ((((nl >> 3) ^ (kr & 7))) << 4);
                ldsm4t(rh, bB + off);
                bF[2*p][0] = rh[0]; bF[2*p][1] = rh[1];
                bF[2*p+1][0] = rh[2]; bF[2*p+1][1] = rh[3];
            }
            #pragma unroll
            for (int mi = 0; mi < 4; mi++)
                #pragma unroll
                for (int ng = 0; ng < 4; ng++)
                    mma_f16(acc[mi][ng], aF[mi], bF[ng]);
        }
        if (step + 3 < nsteps) issue(step + 3);
    }
}

#define EPI_SETUP() \
    const int lane = threadIdx.x & 31, w = threadIdx.x >> 5; \
    const int wm = w >> 2, wn = w & 3; \
    const int er = lane >> 2, ec = (lane & 3) * 2;

// ---------------- kernel 1a: GEMM1 u/v columns (fp16 2-term) ----------------
__global__ __launch_bounds__(256, 2)
void k_gemm1uv()
{
    float acc[4][4][4] = {};
    const int rowBase = blockIdx.y * 128, colBase = blockIdx.x * 128;
    mma_gemm_2t(g_H16, HID, g_Wifh, g_Wifl, NCOLS, HID, rowBase, colBase, acc);
    EPI_SETUP();
    #pragma unroll
    for (int mi = 0; mi < 4; mi++)
        #pragma unroll
        for (int ng = 0; ng < 4; ng++) {
            int r0 = rowBase + wm * 64 + mi * 16 + er;
            int c0 = colBase + wn * 32 + ng * 8 + ec;
            #pragma unroll
            for (int h = 0; h < 2; h++) {
                int row = r0 + h * 8;
                #pragma unroll
                for (int j = 0; j < 2; j++) {
                    int col = c0 + j;
                    float x = acc[mi][ng][h * 2 + j];
                    float v = x / (1.0f + __expf(-x));  // SiLU
                    if (col < INTER)
                        g_u16[(size_t)row * INTER + col] =
                            __half_as_ushort(__float2half_rn(v));
                    else
                        g_v16[(size_t)row * INTER + (col - INTER)] =
                            __half_as_ushort(__float2half_rn(v));
                }
            }
        }
}

// ---------------- kernel 1b: GEMM1 qk columns (bf16x3) ----------------------
__global__ __launch_bounds__(256, 2)
void k_gemm1qk(const float* __restrict__ qg, const float* __restrict__ kg)
{
    float acc[4][4][4] = {};
    const int rowBase = blockIdx.y * 128, colBase = 2 * INTER;
    mma_gemm_pk<false>(g_Hh, g_Hl, HID, g_Wih, g_Wil, NCOLS, HID, rowBase, colBase, acc);
    EPI_SETUP();
    #pragma unroll
    for (int mi = 0; mi < 4; mi++)
        #pragma unroll
        for (int ng = 0; ng < 4; ng++) {
            int r0 = rowBase + wm * 64 + mi * 16 + er;
            int c0 = wn * 32 + ng * 8 + ec;
            #pragma unroll
            for (int h = 0; h < 2; h++) {
                int row = r0 + h * 8;
                #pragma unroll
                for (int j = 0; j < 2; j++) {
                    int c = c0 + j;
                    float x = acc[mi][ng][h * 2 + j];
                    float v = x / (1.0f + __expf(-x));  // SiLU
                    size_t idx = (size_t)row * DK + c;
                    float sq = qg[c] * kg[c] * 0.08838834764831845f;
                    splitf(v * sq, g_qh[idx], g_ql[idx]);
                    splitf(v,      g_kh[idx], g_kl[idx]);
                }
            }
        }
}

// ---------------- kernel 2: Q' @ K'^T, symmetric (lower triangle) -----------
__global__ __launch_bounds__(256, 2)
void k_qk()
{
    extern __shared__ __align__(16) uint4 smdyn[];
    float acc[4][4][4] = {};
    const int b = blockIdx.z;
    int t = blockIdx.x;
    int ty = (int)((__fsqrt_rn(8.f * t + 1.f) - 1.f) * 0.5f);
    while ((ty + 1) * (ty + 2) / 2 <= t) ty++;
    while (ty * (ty + 1) / 2 > t) ty--;
    int tx = t - ty * (ty + 1) / 2;
    const int rowBase = ty * 128, colBase = tx * 128;

    const size_t o = (size_t)b * SEQ * DK;
    mma_gemm_pk<true>(g_qh + o, g_ql + o, DK, g_kh + o, g_kl + o, DK,
                      DK, rowBase, colBase, acc);
    float* Ab = g_A + (size_t)b * SEQ * SEQ;

    __syncthreads();
    float* sT = (float*)smdyn;
    EPI_SETUP();
    #pragma unroll
    for (int mi = 0; mi < 4; mi++)
        #pragma unroll
        for (int ng = 0; ng < 4; ng++) {
            int r = wm * 64 + mi * 16 + er;
            int c = wn * 32 + ng * 8 + ec;
            sT[r * 129 + c]           = acc[mi][ng][0];
            sT[r * 129 + c + 1]       = acc[mi][ng][1];
            sT[(r + 8) * 129 + c]     = acc[mi][ng][2];
            sT[(r + 8) * 129 + c + 1] = acc[mi][ng][3];
        }
    __syncthreads();

    const int tid = threadIdx.x;
    const int r2 = tid >> 1, half = tid & 1;
    #pragma unroll
    for (int cc = 0; cc < 16; cc++) {
        int c = half * 64 + cc * 4;
        float4 v;
        v.x = sT[r2 * 129 + c];     v.y = sT[r2 * 129 + c + 1];
        v.z = sT[r2 * 129 + c + 2]; v.w = sT[r2 * 129 + c + 3];
        *(float4*)&Ab[(size_t)(rowBase + r2) * SEQ + colBase + c] = v;
    }
    if (ty != tx) {
        #pragma unroll
        for (int cc = 0; cc < 16; cc++) {
            int c = half * 64 + cc * 4;
            float4 v;
            v.x = sT[c * 129 + r2];       v.y = sT[(c + 1) * 129 + r2];
            v.z = sT[(c + 2) * 129 + r2]; v.w = sT[(c + 3) * 129 + r2];
            *(float4*)&Ab[(size_t)(colBase + r2) * SEQ + rowBase + c] = v;
        }
    }
}

// ---------------- kernel 3: masked softmax (inline mask count) --------------
__global__ __launch_bounds__(256)
void k_softmax(const int* __restrict__ mask)
{
    const int bm = blockIdx.x;
    const int b = bm >> 11;
    const int m = bm & (SEQ - 1);
    const int tid = threadIdx.x;
    const int lane = tid & 31, wrp = tid >> 5;

    __shared__ float redm[8], redc[8], reds[8];
    const size_t rowoff = (size_t)b * SEQ * SEQ + (size_t)m * SEQ;
    const float* row = g_A + rowoff;

    float a[8];
    float mx = -3.4e38f, cnt = 0.f;
    #pragma unroll
    for (int k2 = 0; k2 < 8; k2++) {
        int n = tid + k2 * 256;
        float x = row[n];
        int mv = mask[b * SEQ + n];
        cnt += (float)mv;
        if (mv == 0) x = -1e12f;
        a[k2] = x;
        mx = fmaxf(mx, x);
    }
    #pragma unroll
    for (int s = 16; s > 0; s >>= 1) {
        mx = fmaxf(mx, __shfl_xor_sync(0xffffffffu, mx, s));
        cnt += __shfl_xor_sync(0xffffffffu, cnt, s);
    }
    if (lane == 0) { redm[wrp] = mx; redc[wrp] = cnt; }
    __syncthreads();
    mx = redm[lane & 7]; cnt = redc[lane & 7];
    #pragma unroll
    for (int s = 4; s > 0; s >>= 1) {
        mx = fmaxf(mx, __shfl_xor_sync(0xffffffffu, mx, s));
        cnt += __shfl_xor_sync(0xffffffffu, cnt, s);
    }
    const float scale = logf(fmaxf(cnt, 1.0f)) * (1.0f / LOG512F);
    const float mxs = mx * scale;

    float sm = 0.f;
    #pragma unroll
    for (int k2 = 0; k2 < 8; k2++) {
        float e = __expf(a[k2] * scale - mxs);
        a[k2] = e;
        sm += e;
    }
    #pragma unroll
    for (int s = 16; s > 0; s >>= 1)
        sm += __shfl_xor_sync(0xffffffffu, sm, s);
    if (lane == 0) reds[wrp] = sm;
    __syncthreads();
    sm = reds[lane & 7];
    #pragma unroll
    for (int s = 4; s > 0; s >>= 1)
        sm += __shfl_xor_sync(0xffffffffu, sm, s);
    const float inv = 1.0f / sm;

    #pragma unroll
    for (int k2 = 0; k2 < 8; k2++) {
        int n = tid + k2 * 256;
        g_A16[rowoff + n] = __half_as_ushort(__float2half_rn(a[k2] * inv));
    }
}

// ---------------- kernel 4: (A @ V) * u  (fp16 single-term) -----------------
__global__ __launch_bounds__(256, 2)
void k_av()
{
    float acc[4][4][4] = {};
    const int b = blockIdx.z;
    const int rowBase = blockIdx.y * 128, colBase = blockIdx.x * 128;
    const size_t oa = (size_t)b * SEQ * SEQ;
    const size_t ov = (size_t)b * SEQ * INTER;
    mma_gemm_1t(g_A16 + oa, SEQ, g_v16 + ov, INTER,
                SEQ, rowBase, colBase, acc);
    EPI_SETUP();
    #pragma unroll
    for (int mi = 0; mi < 4; mi++)
        #pragma unroll
        for (int ng = 0; ng < 4; ng++) {
            int r0 = rowBase + wm * 64 + mi * 16 + er;
            int c0 = colBase + wn * 32 + ng * 8 + ec;
            #pragma unroll
            for (int h = 0; h < 2; h++) {
                int row = r0 + h * 8;
                size_t base = ((size_t)(b * SEQ + row)) * INTER + c0;
                __half2 u2 = *(const __half2*)&g_u16[base];
                g_t16[base]     = __half_as_ushort(
                    __float2half_rn(__half2float(__low2half(u2))  * acc[mi][ng][h * 2]));
                g_t16[base + 1] = __half_as_ushort(
                    __float2half_rn(__half2float(__high2half(u2)) * acc[mi][ng][h * 2 + 1]));
            }
        }
}

// ---------------- kernel 5: t @ Wo -> out  (fp16 2-term) --------------------
__global__ __launch_bounds__(256, 2)
void k_out(float* __restrict__ out)
{
    float acc[4][4][4] = {};
    const int rowBase = blockIdx.y * 128, colBase = blockIdx.x * 128;
    mma_gemm_2t(g_t16, INTER, g_Woh, g_Wol, HID,
                INTER, rowBase, colBase, acc);
    EPI_SETUP();
    #pragma unroll
    for (int mi = 0; mi < 4; mi++)
        #pragma unroll
        for (int ng = 0; ng < 4; ng++) {
            int r0 = rowBase + wm * 64 + mi * 16 + er;
            int c0 = colBase + wn * 32 + ng * 8 + ec;
            *(float2*)&out[(size_t)r0 * HID + c0] =
                make_float2(acc[mi][ng][0], acc[mi][ng][1]);
            *(float2*)&out[(size_t)(r0 + 8) * HID + c0] =
                make_float2(acc[mi][ng][2], acc[mi][ng][3]);
        }
}

// ---------------- launch ----------------------------------------------------
extern "C" void kernel_launch(void* const* d_in, const int* in_sizes, int n_in,
                              void* d_out, int out_size)
{
    const float* h    = (const float*)d_in[0];
    const float* Wi   = (const float*)d_in[1];
    const float* Wo   = (const float*)d_in[2];
    const float* qg   = (const float*)d_in[3];
    const float* kg   = (const float*)d_in[4];
    const int*   mask = (const int*)d_in[5];
    float*       out  = (float*)d_out;

    cudaFuncSetAttribute(k_gemm1uv, cudaFuncAttributeMaxDynamicSharedMemorySize, GEMM_SMEM2);
    cudaFuncSetAttribute(k_gemm1qk, cudaFuncAttributeMaxDynamicSharedMemorySize, GEMM_SMEM);
    cudaFuncSetAttribute(k_qk,      cudaFuncAttributeMaxDynamicSharedMemorySize, GEMM_SMEM);
    cudaFuncSetAttribute(k_av,      cudaFuncAttributeMaxDynamicSharedMemorySize, GEMM_SMEM1);
    cudaFuncSetAttribute(k_out,     cudaFuncAttributeMaxDynamicSharedMemorySize, GEMM_SMEM2);

    k_split<<<(N4TOT + 255) / 256, 256>>>((const float4*)h, (const float4*)Wi,
                                          (const float4*)Wo);

    k_gemm1uv<<<dim3(2 * INTER / 128, MTOT / 128), 256, GEMM_SMEM2>>>();
    k_gemm1qk<<<dim3(1, MTOT / 128), 256, GEMM_SMEM>>>(qg, kg);
    k_qk<<<dim3(136, 1, BATCH), 256, GEMM_SMEM>>>();
    k_softmax<<<BATCH * SEQ, 256>>>(mask);
    k_av<<<dim3(INTER / 128, SEQ / 128, BATCH), 256, GEMM_SMEM1>>>();
    k_out<<<dim3(HID / 128, MTOT / 128), 256, GEMM_SMEM2>>>(out);
}

// round 12
// speedup vs baseline: 2.3333x; 1.2109x over previous
#include <cuda_runtime.h>
#include <cuda_bf16.h>
#include <cuda_fp16.h>
#include <math.h>

#define HID   768
#define INTER 1536
#define DK    128
#define BATCH 4
#define SEQ   2048
#define MTOT  (BATCH*SEQ)          // 8192
#define NCOLS (2*INTER+DK)         // 3200
#define LOG512F 6.2383246250395075f
#define GEMM_SMEM  (3*4*512*16)    // 96 KB: 3 stages x 4 tiles (bf16x3 path)
#define GEMM_SMEM1 (4*2*512*16)    // 64 KB: 4 stages x 2 tiles (fp16 1-term)

#define N4H  (MTOT*HID/4)
#define N4WI (HID*NCOLS/4)
#define N4WO (INTER*HID/4)
#define N4TOT (N4H+N4WI+N4WO)

typedef unsigned short u16;

// ---------------- scratch (device globals) ---------------------------------
__device__ u16   g_H16[(size_t)MTOT*HID];                               // fp16
__device__ u16   g_Hh[(size_t)MTOT*HID],   g_Hl[(size_t)MTOT*HID];     // bf16 (qk path)
__device__ u16   g_Wi16[(size_t)HID*NCOLS];                             // fp16 (uv path)
__device__ u16   g_Wih[(size_t)HID*NCOLS], g_Wil[(size_t)HID*NCOLS];   // bf16 hi/lo (qk path)
__device__ u16   g_Wo16[(size_t)INTER*HID];                             // fp16
__device__ u16   g_u16[(size_t)MTOT*INTER];                             // fp16 gate
__device__ u16   g_v16[(size_t)MTOT*INTER];                             // fp16 value
__device__ u16   g_qh[(size_t)MTOT*DK],    g_ql[(size_t)MTOT*DK];      // bf16
__device__ u16   g_kh[(size_t)MTOT*DK],    g_kl[(size_t)MTOT*DK];      // bf16
__device__ float g_A [(size_t)BATCH*SEQ*SEQ];
__device__ u16   g_A16[(size_t)BATCH*SEQ*SEQ];                          // fp16 probs
__device__ u16   g_t16[(size_t)MTOT*INTER];                             // fp16 gated

// ---------------- PTX helpers ----------------------------------------------
__device__ __forceinline__ void mma_bf16(float c[4], const unsigned a[4], const unsigned b[2]) {
    asm volatile(
        "mma.sync.aligned.m16n8k16.row.col.f32.bf16.bf16.f32 "
        "{%0,%1,%2,%3}, {%4,%5,%6,%7}, {%8,%9}, {%0,%1,%2,%3};\n"
        : "+f"(c[0]), "+f"(c[1]), "+f"(c[2]), "+f"(c[3])
        : "r"(a[0]), "r"(a[1]), "r"(a[2]), "r"(a[3]), "r"(b[0]), "r"(b[1]));
}
__device__ __forceinline__ void mma_f16(float c[4], const unsigned a[4], const unsigned b[2]) {
    asm volatile(
        "mma.sync.aligned.m16n8k16.row.col.f32.f16.f16.f32 "
        "{%0,%1,%2,%3}, {%4,%5,%6,%7}, {%8,%9}, {%0,%1,%2,%3};\n"
        : "+f"(c[0]), "+f"(c[1]), "+f"(c[2]), "+f"(c[3])
        : "r"(a[0]), "r"(a[1]), "r"(a[2]), "r"(a[3]), "r"(b[0]), "r"(b[1]));
}
__device__ __forceinline__ void ldsm4(unsigned r[4], unsigned addr) {
    asm volatile("ldmatrix.sync.aligned.m8n8.x4.shared.b16 {%0,%1,%2,%3}, [%4];\n"
        : "=r"(r[0]), "=r"(r[1]), "=r"(r[2]), "=r"(r[3]) : "r"(addr));
}
__device__ __forceinline__ void ldsm4t(unsigned r[4], unsigned addr) {
    asm volatile("ldmatrix.sync.aligned.m8n8.x4.trans.shared.b16 {%0,%1,%2,%3}, [%4];\n"
        : "=r"(r[0]), "=r"(r[1]), "=r"(r[2]), "=r"(r[3]) : "r"(addr));
}
__device__ __forceinline__ void cp16(void* dst, const void* src) {
    unsigned d = (unsigned)__cvta_generic_to_shared(dst);
    asm volatile("cp.async.cg.shared.global [%0], [%1], 16;\n" :: "r"(d), "l"(src));
}
__device__ __forceinline__ void splitf(float x, u16& h, u16& l) {     // bf16 hi/lo
    __nv_bfloat16 hb = __float2bfloat16(x);
    h = __bfloat16_as_ushort(hb);
    l = __bfloat16_as_ushort(__float2bfloat16(x - __bfloat162float(hb)));
}

// ---------------- fused input split kernel ----------------------------------
__global__ __launch_bounds__(256)
void k_split(const float4* __restrict__ H, const float4* __restrict__ Wi,
             const float4* __restrict__ Wo)
{
    int i = blockIdx.x * 256 + threadIdx.x;
    if (i >= N4TOT) return;
    ushort4 Hh, Ll, F;
    if (i < N4H) {
        float4 f = H[i];
        F.x = __half_as_ushort(__float2half_rn(f.x));
        F.y = __half_as_ushort(__float2half_rn(f.y));
        F.z = __half_as_ushort(__float2half_rn(f.z));
        F.w = __half_as_ushort(__float2half_rn(f.w));
        ((ushort4*)g_H16)[i] = F;
        splitf(f.x, Hh.x, Ll.x); splitf(f.y, Hh.y, Ll.y);
        splitf(f.z, Hh.z, Ll.z); splitf(f.w, Hh.w, Ll.w);
        ((ushort4*)g_Hh)[i] = Hh; ((ushort4*)g_Hl)[i] = Ll;
    } else if (i < N4H + N4WI) {
        int j = i - N4H;
        float4 f = Wi[j];
        F.x = __half_as_ushort(__float2half_rn(f.x));
        F.y = __half_as_ushort(__float2half_rn(f.y));
        F.z = __half_as_ushort(__float2half_rn(f.z));
        F.w = __half_as_ushort(__float2half_rn(f.w));
        ((ushort4*)g_Wi16)[j] = F;
        splitf(f.x, Hh.x, Ll.x); splitf(f.y, Hh.y, Ll.y);
        splitf(f.z, Hh.z, Ll.z); splitf(f.w, Hh.w, Ll.w);
        ((ushort4*)g_Wih)[j] = Hh; ((ushort4*)g_Wil)[j] = Ll;
    } else {
        int j = i - N4H - N4WI;
        float4 f = Wo[j];
        F.x = __half_as_ushort(__float2half_rn(f.x));
        F.y = __half_as_ushort(__float2half_rn(f.y));
        F.z = __half_as_ushort(__float2half_rn(f.z));
        F.w = __half_as_ushort(__float2half_rn(f.w));
        ((ushort4*)g_Wo16)[j] = F;
    }
}

// ---------------- tile stagers (cp.async, 256 threads) ----------------------
__device__ __forceinline__ void stage_tileA(uint4* dst, const u16* __restrict__ g,
                                            int ld, int tid) {
    #pragma unroll
    for (int r = 0; r < 2; r++) {
        int c = tid + r * 256;
        int row = c >> 2, kc = c & 3;
        cp16(dst + row * 4 + (kc ^ ((row >> 1) & 3)),
             g + (size_t)row * ld + kc * 8);
    }
}
__device__ __forceinline__ void stage_tileB(uint4* dst, const u16* __restrict__ g,
                                            int ld, int tid) {
    #pragma unroll
    for (int r = 0; r < 2; r++) {
        int c = tid + r * 256;
        int k = c >> 4, nc = c & 15;
        cp16(dst + k * 16 + (nc ^ (k & 7)),
             g + (size_t)k * ld + nc * 8);
    }
}

// ---------------- bf16x3 GEMM body (score path, 3-stage) --------------------
template<bool BT>
__device__ __forceinline__ void mma_gemm_pk(const u16* __restrict__ Ah, const u16* __restrict__ Al, int lda,
                                            const u16* __restrict__ Bh, const u16* __restrict__ Bl, int ldb,
                                            int K, int rowBase, int colBase,
                                            float acc[4][4][4])
{
    extern __shared__ __align__(16) uint4 smdyn[];
    const int tid = threadIdx.x;
    const int lane = tid & 31, w = tid >> 5;
    const int wm = w >> 2, wn = w & 3;
    const int g = lane >> 3, i = lane & 7;
    const int nsteps = K / 32;

    auto issue = [&](int step) {
        uint4* st = smdyn + (step % 3) * 2048;
        int k0 = step * 32;
        stage_tileA(st,        Ah + (size_t)rowBase * lda + k0, lda, tid);
        stage_tileA(st + 512,  Al + (size_t)rowBase * lda + k0, lda, tid);
        if (BT) {
            stage_tileA(st + 1024, Bh + (size_t)colBase * ldb + k0, ldb, tid);
            stage_tileA(st + 1536, Bl + (size_t)colBase * ldb + k0, ldb, tid);
        } else {
            stage_tileB(st + 1024, Bh + (size_t)k0 * ldb + colBase, ldb, tid);
            stage_tileB(st + 1536, Bl + (size_t)k0 * ldb + colBase, ldb, tid);
        }
        asm volatile("cp.async.commit_group;\n");
    };

    issue(0);
    if (nsteps > 1) issue(1);
    for (int step = 0; step < nsteps; step++) {
        if (step + 1 < nsteps)
            asm volatile("cp.async.wait_group 1;\n");
        else
            asm volatile("cp.async.wait_group 0;\n");
        __syncthreads();

        const uint4* st = smdyn + (step % 3) * 2048;
        const unsigned bAh = (unsigned)__cvta_generic_to_shared(st);
        const unsigned bAl = bAh + 8192;
        const unsigned bBh = bAh + 16384;
        const unsigned bBl = bAh + 24576;

        #pragma unroll
        for (int ks = 0; ks < 32; ks += 16) {
            unsigned aH[4][4], aL[4][4];
            #pragma unroll
            for (int mi = 0; mi < 4; mi++) {
                int mrow = wm * 64 + mi * 16 + (g & 1) * 8 + i;
                int ch = (ks >> 3) + (g >> 1);
                int off = mrow * 64 + ((ch ^ ((mrow >> 1) & 3)) << 4);
                ldsm4(aH[mi], bAh + off);
                ldsm4(aL[mi], bAl + off);
            }
            unsigned bH[4][2], bL[4][2];
            #pragma unroll
            for (int p = 0; p < 2; p++) {
                unsigned rh[4], rl[4];
                if (BT) {
                    int nrow = wn * 32 + p * 16 + (g >> 1) * 8 + i;
                    int ch = (ks >> 3) + (g & 1);
                    int off = nrow * 64 + ((ch ^ ((nrow >> 1) & 3)) << 4);
                    ldsm4(rh, bBh + off);
                    ldsm4(rl, bBl + off);
                } else {
                    int kr = ks + (g & 1) * 8 + i;
                    int nl = wn * 32 + p * 16 + (g >> 1) * 8;
                    int off = kr * 256 + ((((nl >> 3) ^ (kr & 7))) << 4);
                    ldsm4t(rh, bBh + off);
                    ldsm4t(rl, bBl + off);
                }
                bH[2*p][0] = rh[0]; bH[2*p][1] = rh[1];
                bH[2*p+1][0] = rh[2]; bH[2*p+1][1] = rh[3];
                bL[2*p][0] = rl[0]; bL[2*p][1] = rl[1];
                bL[2*p+1][0] = rl[2]; bL[2*p+1][1] = rl[3];
            }
            #pragma unroll
            for (int mi = 0; mi < 4; mi++)
                #pragma unroll
                for (int ng = 0; ng < 4; ng++)
                    mma_bf16(acc[mi][ng], aH[mi], bH[ng]);
            #pragma unroll
            for (int mi = 0; mi < 4; mi++)
                #pragma unroll
                for (int ng = 0; ng < 4; ng++)
                    mma_bf16(acc[mi][ng], aH[mi], bL[ng]);
            #pragma unroll
            for (int mi = 0; mi < 4; mi++)
                #pragma unroll
                for (int ng = 0; ng < 4; ng++)
                    mma_bf16(acc[mi][ng], aL[mi], bH[ng]);
        }
        if (step + 2 < nsteps) issue(step + 2);
    }
}

// ---------------- fp16 single-term GEMM body (4-stage) ----------------------
__device__ __forceinline__ void mma_gemm_1t(const u16* __restrict__ Aa, int lda,
                                            const u16* __restrict__ Bb, int ldb,
                                            int K, int rowBase, int colBase,
                                            float acc[4][4][4])
{
    extern __shared__ __align__(16) uint4 smdyn[];
    const int tid = threadIdx.x;
    const int lane = tid & 31, w = tid >> 5;
    const int wm = w >> 2, wn = w & 3;
    const int g = lane >> 3, i = lane & 7;
    const int nsteps = K / 32;

    auto issue = [&](int step) {
        uint4* st = smdyn + (step & 3) * 1024;
        int k0 = step * 32;
        stage_tileA(st,       Aa + (size_t)rowBase * lda + k0, lda, tid);
        stage_tileB(st + 512, Bb + (size_t)k0 * ldb + colBase, ldb, tid);
        asm volatile("cp.async.commit_group;\n");
    };

    issue(0);
    if (nsteps > 1) issue(1);
    if (nsteps > 2) issue(2);
    for (int step = 0; step < nsteps; step++) {
        if (step + 2 < nsteps)
            asm volatile("cp.async.wait_group 2;\n");
        else if (step + 1 < nsteps)
            asm volatile("cp.async.wait_group 1;\n");
        else
            asm volatile("cp.async.wait_group 0;\n");
        __syncthreads();

        const uint4* st = smdyn + (step & 3) * 1024;
        const unsigned bA = (unsigned)__cvta_generic_to_shared(st);
        const unsigned bB = bA + 8192;

        #pragma unroll
        for (int ks = 0; ks < 32; ks += 16) {
            unsigned aF[4][4];
            #pragma unroll
            for (int mi = 0; mi < 4; mi++) {
                int mrow = wm * 64 + mi * 16 + (g & 1) * 8 + i;
                int ch = (ks >> 3) + (g >> 1);
                int off = mrow * 64 + ((ch ^ ((mrow >> 1) & 3)) << 4);
                ldsm4(aF[mi], bA + off);
            }
            unsigned bF[4][2];
            #pragma unroll
            for (int p = 0; p < 2; p++) {
                unsigned rh[4];
                int kr = ks + (g & 1) * 8 + i;
                int nl = wn * 32 + p * 16 + (g >> 1) * 8;
                int off = kr * 256 + ((((nl >> 3) ^ (kr & 7))) << 4);
                ldsm4t(rh, bB + off);
                bF[2*p][0] = rh[0]; bF[2*p][1] = rh[1];
                bF[2*p+1][0] = rh[2]; bF[2*p+1][1] = rh[3];
            }
            #pragma unroll
            for (int mi = 0; mi < 4; mi++)
                #pragma unroll
                for (int ng = 0; ng < 4; ng++)
                    mma_f16(acc[mi][ng], aF[mi], bF[ng]);
        }
        if (step + 3 < nsteps) issue(step + 3);
    }
}

#define EPI_SETUP() \
    const int lane = threadIdx.x & 31, w = threadIdx.x >> 5; \
    const int wm = w >> 2, wn = w & 3; \
    const int er = lane >> 2, ec = (lane & 3) * 2;

// ---------------- kernel 1a: GEMM1 u/v columns (fp16 1-term) ----------------
__global__ __launch_bounds__(256, 2)
void k_gemm1uv()
{
    float acc[4][4][4] = {};
    const int rowBase = blockIdx.y * 128, colBase = blockIdx.x * 128;
    mma_gemm_1t(g_H16, HID, g_Wi16, NCOLS, HID, rowBase, colBase, acc);
    EPI_SETUP();
    #pragma unroll
    for (int mi = 0; mi < 4; mi++)
        #pragma unroll
        for (int ng = 0; ng < 4; ng++) {
            int r0 = rowBase + wm * 64 + mi * 16 + er;
            int c0 = colBase + wn * 32 + ng * 8 + ec;
            #pragma unroll
            for (int h = 0; h < 2; h++) {
                int row = r0 + h * 8;
                #pragma unroll
                for (int j = 0; j < 2; j++) {
                    int col = c0 + j;
                    float x = acc[mi][ng][h * 2 + j];
                    float v = x / (1.0f + __expf(-x));  // SiLU
                    if (col < INTER)
                        g_u16[(size_t)row * INTER + col] =
                            __half_as_ushort(__float2half_rn(v));
                    else
                        g_v16[(size_t)row * INTER + (col - INTER)] =
                            __half_as_ushort(__float2half_rn(v));
                }
            }
        }
}

// ---------------- kernel 1b: GEMM1 qk columns (bf16x3) ----------------------
__global__ __launch_bounds__(256, 2)
void k_gemm1qk(const float* __restrict__ qg, const float* __restrict__ kg)
{
    float acc[4][4][4] = {};
    const int rowBase = blockIdx.y * 128, colBase = 2 * INTER;
    mma_gemm_pk<false>(g_Hh, g_Hl, HID, g_Wih, g_Wil, NCOLS, HID, rowBase, colBase, acc);
    EPI_SETUP();
    #pragma unroll
    for (int mi = 0; mi < 4; mi++)
        #pragma unroll
        for (int ng = 0; ng < 4; ng++) {
            int r0 = rowBase + wm * 64 + mi * 16 + er;
            int c0 = wn * 32 + ng * 8 + ec;
            #pragma unroll
            for (int h = 0; h < 2; h++) {
                int row = r0 + h * 8;
                #pragma unroll
                for (int j = 0; j < 2; j++) {
                    int c = c0 + j;
                    float x = acc[mi][ng][h * 2 + j];
                    float v = x / (1.0f + __expf(-x));  // SiLU
                    size_t idx = (size_t)row * DK + c;
                    float sq = qg[c] * kg[c] * 0.08838834764831845f;
                    splitf(v * sq, g_qh[idx], g_ql[idx]);
                    splitf(v,      g_kh[idx], g_kl[idx]);
                }
            }
        }
}

// ---------------- kernel 2: Q' @ K'^T, symmetric (lower triangle) -----------
__global__ __launch_bounds__(256, 2)
void k_qk()
{
    extern __shared__ __align__(16) uint4 smdyn[];
    float acc[4][4][4] = {};
    const int b = blockIdx.z;
    int t = blockIdx.x;
    int ty = (int)((__fsqrt_rn(8.f * t + 1.f) - 1.f) * 0.5f);
    while ((ty + 1) * (ty + 2) / 2 <= t) ty++;
    while (ty * (ty + 1) / 2 > t) ty--;
    int tx = t - ty * (ty + 1) / 2;
    const int rowBase = ty * 128, colBase = tx * 128;

    const size_t o = (size_t)b * SEQ * DK;
    mma_gemm_pk<true>(g_qh + o, g_ql + o, DK, g_kh + o, g_kl + o, DK,
                      DK, rowBase, colBase, acc);
    float* Ab = g_A + (size_t)b * SEQ * SEQ;

    __syncthreads();
    float* sT = (float*)smdyn;
    EPI_SETUP();
    #pragma unroll
    for (int mi = 0; mi < 4; mi++)
        #pragma unroll
        for (int ng = 0; ng < 4; ng++) {
            int r = wm * 64 + mi * 16 + er;
            int c = wn * 32 + ng * 8 + ec;
            sT[r * 129 + c]           = acc[mi][ng][0];
            sT[r * 129 + c + 1]       = acc[mi][ng][1];
            sT[(r + 8) * 129 + c]     = acc[mi][ng][2];
            sT[(r + 8) * 129 + c + 1] = acc[mi][ng][3];
        }
    __syncthreads();

    const int tid = threadIdx.x;
    const int r2 = tid >> 1, half = tid & 1;
    #pragma unroll
    for (int cc = 0; cc < 16; cc++) {
        int c = half * 64 + cc * 4;
        float4 v;
        v.x = sT[r2 * 129 + c];     v.y = sT[r2 * 129 + c + 1];
        v.z = sT[r2 * 129 + c + 2]; v.w = sT[r2 * 129 + c + 3];
        *(float4*)&Ab[(size_t)(rowBase + r2) * SEQ + colBase + c] = v;
    }
    if (ty != tx) {
        #pragma unroll
        for (int cc = 0; cc < 16; cc++) {
            int c = half * 64 + cc * 4;
            float4 v;
            v.x = sT[c * 129 + r2];       v.y = sT[(c + 1) * 129 + r2];
            v.z = sT[(c + 2) * 129 + r2]; v.w = sT[(c + 3) * 129 + r2];
            *(float4*)&Ab[(size_t)(colBase + r2) * SEQ + rowBase + c] = v;
        }
    }
}

// ---------------- kernel 3: masked softmax (inline mask count) --------------
__global__ __launch_bounds__(256)
void k_softmax(const int* __restrict__ mask)
{
    const int bm = blockIdx.x;
    const int b = bm >> 11;
    const int m = bm & (SEQ - 1);
    const int tid = threadIdx.x;
    const int lane = tid & 31, wrp = tid >> 5;

    __shared__ float redm[8], redc[8], reds[8];
    const size_t rowoff = (size_t)b * SEQ * SEQ + (size_t)m * SEQ;
    const float* row = g_A + rowoff;

    float a[8];
    float mx = -3.4e38f, cnt = 0.f;
    #pragma unroll
    for (int k2 = 0; k2 < 8; k2++) {
        int n = tid + k2 * 256;
        float x = row[n];
        int mv = mask[b * SEQ + n];
        cnt += (float)mv;
        if (mv == 0) x = -1e12f;
        a[k2] = x;
        mx = fmaxf(mx, x);
    }
    #pragma unroll
    for (int s = 16; s > 0; s >>= 1) {
        mx = fmaxf(mx, __shfl_xor_sync(0xffffffffu, mx, s));
        cnt += __shfl_xor_sync(0xffffffffu, cnt, s);
    }
    if (lane == 0) { redm[wrp] = mx; redc[wrp] = cnt; }
    __syncthreads();
    mx = redm[lane & 7]; cnt = redc[lane & 7];
    #pragma unroll
    for (int s = 4; s > 0; s >>= 1) {
        mx = fmaxf(mx, __shfl_xor_sync(0xffffffffu, mx, s));
        cnt += __shfl_xor_sync(0xffffffffu, cnt, s);
    }
    const float scale = logf(fmaxf(cnt, 1.0f)) * (1.0f / LOG512F);
    const float mxs = mx * scale;

    float sm = 0.f;
    #pragma unroll
    for (int k2 = 0; k2 < 8; k2++) {
        float e = __expf(a[k2] * scale - mxs);
        a[k2] = e;
        sm += e;
    }
    #pragma unroll
    for (int s = 16; s > 0; s >>= 1)
        sm += __shfl_xor_sync(0xffffffffu, sm, s);
    if (lane == 0) reds[wrp] = sm;
    __syncthreads();
    sm = reds[lane & 7];
    #pragma unroll
    for (int s = 4; s > 0; s >>= 1)
        sm += __shfl_xor_sync(0xffffffffu, sm, s);
    const float inv = 1.0f / sm;

    #pragma unroll
    for (int k2 = 0; k2 < 8; k2++) {
        int n = tid + k2 * 256;
        g_A16[rowoff + n] = __half_as_ushort(__float2half_rn(a[k2] * inv));
    }
}

// ---------------- kernel 4: (A @ V) * u  (fp16 single-term) -----------------
__global__ __launch_bounds__(256, 2)
void k_av()
{
    float acc[4][4][4] = {};
    const int b = blockIdx.z;
    const int rowBase = blockIdx.y * 128, colBase = blockIdx.x * 128;
    const size_t oa = (size_t)b * SEQ * SEQ;
    const size_t ov = (size_t)b * SEQ * INTER;
    mma_gemm_1t(g_A16 + oa, SEQ, g_v16 + ov, INTER,
                SEQ, rowBase, colBase, acc);
    EPI_SETUP();
    #pragma unroll
    for (int mi = 0; mi < 4; mi++)
        #pragma unroll
        for (int ng = 0; ng < 4; ng++) {
            int r0 = rowBase + wm * 64 + mi * 16 + er;
            int c0 = colBase + wn * 32 + ng * 8 + ec;
            #pragma unroll
            for (int h = 0; h < 2; h++) {
                int row = r0 + h * 8;
                size_t base = ((size_t)(b * SEQ + row)) * INTER + c0;
                __half2 u2 = *(const __half2*)&g_u16[base];
                g_t16[base]     = __half_as_ushort(
                    __float2half_rn(__half2float(__low2half(u2))  * acc[mi][ng][h * 2]));
                g_t16[base + 1] = __half_as_ushort(
                    __float2half_rn(__half2float(__high2half(u2)) * acc[mi][ng][h * 2 + 1]));
            }
        }
}

// ---------------- kernel 5: t @ Wo -> out  (fp16 single-term) ---------------
__global__ __launch_bounds__(256, 2)
void k_out(float* __restrict__ out)
{
    float acc[4][4][4] = {};
    const int rowBase = blockIdx.y * 128, colBase = blockIdx.x * 128;
    mma_gemm_1t(g_t16, INTER, g_Wo16, HID, INTER, rowBase, colBase, acc);
    EPI_SETUP();
    #pragma unroll
    for (int mi = 0; mi < 4; mi++)
        #pragma unroll
        for (int ng = 0; ng < 4; ng++) {
            int r0 = rowBase + wm * 64 + mi * 16 + er;
            int c0 = colBase + wn * 32 + ng * 8 + ec;
            *(float2*)&out[(size_t)r0 * HID + c0] =
                make_float2(acc[mi][ng][0], acc[mi][ng][1]);
            *(float2*)&out[(size_t)(r0 + 8) * HID + c0] =
                make_float2(acc[mi][ng][2], acc[mi][ng][3]);
        }
}

// ---------------- launch ----------------------------------------------------
extern "C" void kernel_launch(void* const* d_in, const int* in_sizes, int n_in,
                              void* d_out, int out_size)
{
    const float* h    = (const float*)d_in[0];
    const float* Wi   = (const float*)d_in[1];
    const float* Wo   = (const float*)d_in[2];
    const float* qg   = (const float*)d_in[3];
    const float* kg   = (const float*)d_in[4];
    const int*   mask = (const int*)d_in[5];
    float*       out  = (float*)d_out;

    cudaFuncSetAttribute(k_gemm1uv, cudaFuncAttributeMaxDynamicSharedMemorySize, GEMM_SMEM1);
    cudaFuncSetAttribute(k_gemm1qk, cudaFuncAttributeMaxDynamicSharedMemorySize, GEMM_SMEM);
    cudaFuncSetAttribute(k_qk,      cudaFuncAttributeMaxDynamicSharedMemorySize, GEMM_SMEM);
    cudaFuncSetAttribute(k_av,      cudaFuncAttributeMaxDynamicSharedMemorySize, GEMM_SMEM1);
    cudaFuncSetAttribute(k_out,     cudaFuncAttributeMaxDynamicSharedMemorySize, GEMM_SMEM1);

    k_split<<<(N4TOT + 255) / 256, 256>>>((const float4*)h, (const float4*)Wi,
                                          (const float4*)Wo);

    k_gemm1uv<<<dim3(2 * INTER / 128, MTOT / 128), 256, GEMM_SMEM1>>>();
    k_gemm1qk<<<dim3(1, MTOT / 128), 256, GEMM_SMEM>>>(qg, kg);
    k_qk<<<dim3(136, 1, BATCH), 256, GEMM_SMEM>>>();
    k_softmax<<<BATCH * SEQ, 256>>>(mask);
    k_av<<<dim3(INTER / 128, SEQ / 128, BATCH), 256, GEMM_SMEM1>>>();
    k_out<<<dim3(HID / 128, MTOT / 128), 256, GEMM_SMEM1>>>(out);
}

// round 15
// speedup vs baseline: 2.3404x; 1.0031x over previous
#include <cuda_runtime.h>
#include <cuda_bf16.h>
#include <cuda_fp16.h>
#include <math.h>

#define HID   768
#define INTER 1536
#define DK    128
#define BATCH 4
#define SEQ   2048
#define MTOT  (BATCH*SEQ)          // 8192
#define NCOLS (2*INTER+DK)         // 3200
#define LOG512F 6.2383246250395075f
#define GEMM_SMEM  (3*4*512*16)    // 96 KB: 3 stages x 4 tiles (bf16x3 path)
#define GEMM_SMEM1 (6*1024*16)     // 96 KB: 6 stages x 2 tiles (fp16 1-term, paired)

#define N4H  (MTOT*HID/4)
#define N4WI (HID*NCOLS/4)
#define N4WO (INTER*HID/4)
#define N4TOT (N4H+N4WI+N4WO)

typedef unsigned short u16;

// ---------------- scratch (device globals) ---------------------------------
__device__ u16   g_H16[(size_t)MTOT*HID];                               // fp16
__device__ u16   g_Hh[(size_t)MTOT*HID],   g_Hl[(size_t)MTOT*HID];     // bf16 (qk path)
__device__ u16   g_Wi16[(size_t)HID*NCOLS];                             // fp16 (uv path)
__device__ u16   g_Wih[(size_t)HID*NCOLS], g_Wil[(size_t)HID*NCOLS];   // bf16 hi/lo (qk path)
__device__ u16   g_Wo16[(size_t)INTER*HID];                             // fp16
__device__ u16   g_u16[(size_t)MTOT*INTER];                             // fp16 gate
__device__ u16   g_v16[(size_t)MTOT*INTER];                             // fp16 value
__device__ u16   g_qh[(size_t)MTOT*DK],    g_ql[(size_t)MTOT*DK];      // bf16
__device__ u16   g_kh[(size_t)MTOT*DK],    g_kl[(size_t)MTOT*DK];      // bf16
__device__ float g_A [(size_t)BATCH*SEQ*SEQ];
__device__ u16   g_A16[(size_t)BATCH*SEQ*SEQ];                          // fp16 probs
__device__ u16   g_t16[(size_t)MTOT*INTER];                             // fp16 gated

// ---------------- PTX helpers ----------------------------------------------
__device__ __forceinline__ void mma_bf16(float c[4], const unsigned a[4], const unsigned b[2]) {
    asm volatile(
        "mma.sync.aligned.m16n8k16.row.col.f32.bf16.bf16.f32 "
        "{%0,%1,%2,%3}, {%4,%5,%6,%7}, {%8,%9}, {%0,%1,%2,%3};\n"
        : "+f"(c[0]), "+f"(c[1]), "+f"(c[2]), "+f"(c[3])
        : "r"(a[0]), "r"(a[1]), "r"(a[2]), "r"(a[3]), "r"(b[0]), "r"(b[1]));
}
__device__ __forceinline__ void mma_f16(float c[4], const unsigned a[4], const unsigned b[2]) {
    asm volatile(
        "mma.sync.aligned.m16n8k16.row.col.f32.f16.f16.f32 "
        "{%0,%1,%2,%3}, {%4,%5,%6,%7}, {%8,%9}, {%0,%1,%2,%3};\n"
        : "+f"(c[0]), "+f"(c[1]), "+f"(c[2]), "+f"(c[3])
        : "r"(a[0]), "r"(a[1]), "r"(a[2]), "r"(a[3]), "r"(b[0]), "r"(b[1]));
}
__device__ __forceinline__ void ldsm4(unsigned r[4], unsigned addr) {
    asm volatile("ldmatrix.sync.aligned.m8n8.x4.shared.b16 {%0,%1,%2,%3}, [%4];\n"
        : "=r"(r[0]), "=r"(r[1]), "=r"(r[2]), "=r"(r[3]) : "r"(addr));
}
__device__ __forceinline__ void ldsm4t(unsigned r[4], unsigned addr) {
    asm volatile("ldmatrix.sync.aligned.m8n8.x4.trans.shared.b16 {%0,%1,%2,%3}, [%4];\n"
        : "=r"(r[0]), "=r"(r[1]), "=r"(r[2]), "=r"(r[3]) : "r"(addr));
}
__device__ __forceinline__ void cp16(void* dst, const void* src) {
    unsigned d = (unsigned)__cvta_generic_to_shared(dst);
    asm volatile("cp.async.cg.shared.global [%0], [%1], 16;\n" :: "r"(d), "l"(src));
}
__device__ __forceinline__ void splitf(float x, u16& h, u16& l) {     // bf16 hi/lo
    __nv_bfloat16 hb = __float2bfloat16(x);
    h = __bfloat16_as_ushort(hb);
    l = __bfloat16_as_ushort(__float2bfloat16(x - __bfloat162float(hb)));
}

// ---------------- fused input split kernel ----------------------------------
__global__ __launch_bounds__(256)
void k_split(const float4* __restrict__ H, const float4* __restrict__ Wi,
             const float4* __restrict__ Wo)
{
    int i = blockIdx.x * 256 + threadIdx.x;
    if (i >= N4TOT) return;
    ushort4 Hh, Ll, F;
    if (i < N4H) {
        float4 f = H[i];
        F.x = __half_as_ushort(__float2half_rn(f.x));
        F.y = __half_as_ushort(__float2half_rn(f.y));
        F.z = __half_as_ushort(__float2half_rn(f.z));
        F.w = __half_as_ushort(__float2half_rn(f.w));
        ((ushort4*)g_H16)[i] = F;
        splitf(f.x, Hh.x, Ll.x); splitf(f.y, Hh.y, Ll.y);
        splitf(f.z, Hh.z, Ll.z); splitf(f.w, Hh.w, Ll.w);
        ((ushort4*)g_Hh)[i] = Hh; ((ushort4*)g_Hl)[i] = Ll;
    } else if (i < N4H + N4WI) {
        int j = i - N4H;
        float4 f = Wi[j];
        F.x = __half_as_ushort(__float2half_rn(f.x));
        F.y = __half_as_ushort(__float2half_rn(f.y));
        F.z = __half_as_ushort(__float2half_rn(f.z));
        F.w = __half_as_ushort(__float2half_rn(f.w));
        ((ushort4*)g_Wi16)[j] = F;
        splitf(f.x, Hh.x, Ll.x); splitf(f.y, Hh.y, Ll.y);
        splitf(f.z, Hh.z, Ll.z); splitf(f.w, Hh.w, Ll.w);
        ((ushort4*)g_Wih)[j] = Hh; ((ushort4*)g_Wil)[j] = Ll;
    } else {
        int j = i - N4H - N4WI;
        float4 f = Wo[j];
        F.x = __half_as_ushort(__float2half_rn(f.x));
        F.y = __half_as_ushort(__float2half_rn(f.y));
        F.z = __half_as_ushort(__float2half_rn(f.z));
        F.w = __half_as_ushort(__float2half_rn(f.w));
        ((ushort4*)g_Wo16)[j] = F;
    }
}

// ---------------- tile stagers (cp.async, 256 threads) ----------------------
__device__ __forceinline__ void stage_tileA(uint4* dst, const u16* __restrict__ g,
                                            int ld, int tid) {
    #pragma unroll
    for (int r = 0; r < 2; r++) {
        int c = tid + r * 256;
        int row = c >> 2, kc = c & 3;
        cp16(dst + row * 4 + (kc ^ ((row >> 1) & 3)),
             g + (size_t)row * ld + kc * 8);
    }
}
__device__ __forceinline__ void stage_tileB(uint4* dst, const u16* __restrict__ g,
                                            int ld, int tid) {
    #pragma unroll
    for (int r = 0; r < 2; r++) {
        int c = tid + r * 256;
        int k = c >> 4, nc = c & 15;
        cp16(dst + k * 16 + (nc ^ (k & 7)),
             g + (size_t)k * ld + nc * 8);
    }
}

// ---------------- bf16x3 GEMM body (score path, 3-stage) --------------------
template<bool BT>
__device__ __forceinline__ void mma_gemm_pk(const u16* __restrict__ Ah, const u16* __restrict__ Al, int lda,
                                            const u16* __restrict__ Bh, const u16* __restrict__ Bl, int ldb,
                                            int K, int rowBase, int colBase,
                                            float acc[4][4][4])
{
    extern __shared__ __align__(16) uint4 smdyn[];
    const int tid = threadIdx.x;
    const int lane = tid & 31, w = tid >> 5;
    const int wm = w >> 2, wn = w & 3;
    const int g = lane >> 3, i = lane & 7;
    const int nsteps = K / 32;

    auto issue = [&](int step) {
        uint4* st = smdyn + (step % 3) * 2048;
        int k0 = step * 32;
        stage_tileA(st,        Ah + (size_t)rowBase * lda + k0, lda, tid);
        stage_tileA(st + 512,  Al + (size_t)rowBase * lda + k0, lda, tid);
        if (BT) {
            stage_tileA(st + 1024, Bh + (size_t)colBase * ldb + k0, ldb, tid);
            stage_tileA(st + 1536, Bl + (size_t)colBase * ldb + k0, ldb, tid);
        } else {
            stage_tileB(st + 1024, Bh + (size_t)k0 * ldb + colBase, ldb, tid);
            stage_tileB(st + 1536, Bl + (size_t)k0 * ldb + colBase, ldb, tid);
        }
        asm volatile("cp.async.commit_group;\n");
    };

    issue(0);
    if (nsteps > 1) issue(1);
    for (int step = 0; step < nsteps; step++) {
        if (step + 1 < nsteps)
            asm volatile("cp.async.wait_group 1;\n");
        else
            asm volatile("cp.async.wait_group 0;\n");
        __syncthreads();

        const uint4* st = smdyn + (step % 3) * 2048;
        const unsigned bAh = (unsigned)__cvta_generic_to_shared(st);
        const unsigned bAl = bAh + 8192;
        const unsigned bBh = bAh + 16384;
        const unsigned bBl = bAh + 24576;

        #pragma unroll
        for (int ks = 0; ks < 32; ks += 16) {
            unsigned aH[4][4], aL[4][4];
            #pragma unroll
            for (int mi = 0; mi < 4; mi++) {
                int mrow = wm * 64 + mi * 16 + (g & 1) * 8 + i;
                int ch = (ks >> 3) + (g >> 1);
                int off = mrow * 64 + ((ch ^ ((mrow >> 1) & 3)) << 4);
                ldsm4(aH[mi], bAh + off);
                ldsm4(aL[mi], bAl + off);
            }
            unsigned bH[4][2], bL[4][2];
            #pragma unroll
            for (int p = 0; p < 2; p++) {
                unsigned rh[4], rl[4];
                if (BT) {
                    int nrow = wn * 32 + p * 16 + (g >> 1) * 8 + i;
                    int ch = (ks >> 3) + (g & 1);
                    int off = nrow * 64 + ((ch ^ ((nrow >> 1) & 3)) << 4);
                    ldsm4(rh, bBh + off);
                    ldsm4(rl, bBl + off);
                } else {
                    int kr = ks + (g & 1) * 8 + i;
                    int nl = wn * 32 + p * 16 + (g >> 1) * 8;
                    int off = kr * 256 + ((((nl >> 3) ^ (kr & 7))) << 4);
                    ldsm4t(rh, bBh + off);
                    ldsm4t(rl, bBl + off);
                }
                bH[2*p][0] = rh[0]; bH[2*p][1] = rh[1];
                bH[2*p+1][0] = rh[2]; bH[2*p+1][1] = rh[3];
                bL[2*p][0] = rl[0]; bL[2*p][1] = rl[1];
                bL[2*p+1][0] = rl[2]; bL[2*p+1][1] = rl[3];
            }
            #pragma unroll
            for (int mi = 0; mi < 4; mi++)
                #pragma unroll
                for (int ng = 0; ng < 4; ng++)
                    mma_bf16(acc[mi][ng], aH[mi], bH[ng]);
            #pragma unroll
            for (int mi = 0; mi < 4; mi++)
                #pragma unroll
                for (int ng = 0; ng < 4; ng++)
                    mma_bf16(acc[mi][ng], aH[mi], bL[ng]);
            #pragma unroll
            for (int mi = 0; mi < 4; mi++)
                #pragma unroll
                for (int ng = 0; ng < 4; ng++)
                    mma_bf16(acc[mi][ng], aL[mi], bH[ng]);
        }
        if (step + 2 < nsteps) issue(step + 2);
    }
}

// ---------------- fp16 single-term GEMM body (6-stage, paired barriers) -----
// Requires K/32 even (true for all call sites: 24, 64, 48).
__device__ __forceinline__ void mma_gemm_1t(const u16* __restrict__ Aa, int lda,
                                            const u16* __restrict__ Bb, int ldb,
                                            int K, int rowBase, int colBase,
                                            float acc[4][4][4])
{
    extern __shared__ __align__(16) uint4 smdyn[];
    const int tid = threadIdx.x;
    const int lane = tid & 31, w = tid >> 5;
    const int wm = w >> 2, wn = w & 3;
    const int g = lane >> 3, i = lane & 7;
    const int nsteps = K / 32;

    auto issue = [&](int step) {
        uint4* st = smdyn + (step % 6) * 1024;
        int k0 = step * 32;
        stage_tileA(st,       Aa + (size_t)rowBase * lda + k0, lda, tid);
        stage_tileB(st + 512, Bb + (size_t)k0 * ldb + colBase, ldb, tid);
        asm volatile("cp.async.commit_group;\n");
    };

    issue(0); issue(1);
    if (nsteps > 2) issue(2);
    if (nsteps > 3) issue(3);

    for (int p = 0; p < nsteps; p += 2) {
        if (p + 4 <= nsteps)
            asm volatile("cp.async.wait_group 2;\n");
        else
            asm volatile("cp.async.wait_group 0;\n");
        __syncthreads();
        // refill the pair freed two iterations ago (all threads passed sync)
        if (p + 4 < nsteps) {
            issue(p + 4);
            if (p + 5 < nsteps) issue(p + 5);
        }
        #pragma unroll
        for (int sub = 0; sub < 2; sub++) {
            const uint4* st = smdyn + ((p + sub) % 6) * 1024;
            const unsigned bA = (unsigned)__cvta_generic_to_shared(st);
            const unsigned bB = bA + 8192;
            #pragma unroll
            for (int ks = 0; ks < 32; ks += 16) {
                unsigned aF[4][4];
                #pragma unroll
                for (int mi = 0; mi < 4; mi++) {
                    int mrow = wm * 64 + mi * 16 + (g & 1) * 8 + i;
                    int ch = (ks >> 3) + (g >> 1);
                    int off = mrow * 64 + ((ch ^ ((mrow >> 1) & 3)) << 4);
                    ldsm4(aF[mi], bA + off);
                }
                unsigned bF[4][2];
                #pragma unroll
                for (int pp = 0; pp < 2; pp++) {
                    unsigned rh[4];
                    int kr = ks + (g & 1) * 8 + i;
                    int nl = wn * 32 + pp * 16 + (g >> 1) * 8;
                    int off = kr * 256 + ((((nl >> 3) ^ (kr & 7))) << 4);
                    ldsm4t(rh, bB + off);
                    bF[2*pp][0] = rh[0]; bF[2*pp][1] = rh[1];
                    bF[2*pp+1][0] = rh[2]; bF[2*pp+1][1] = rh[3];
                }
                #pragma unroll
                for (int mi = 0; mi < 4; mi++)
                    #pragma unroll
                    for (int ng = 0; ng < 4; ng++)
                        mma_f16(acc[mi][ng], aF[mi], bF[ng]);
            }
        }
    }
}

#define EPI_SETUP() \
    const int lane = threadIdx.x & 31, w = threadIdx.x >> 5; \
    const int wm = w >> 2, wn = w & 3; \
    const int er = lane >> 2, ec = (lane & 3) * 2;

// ---------------- kernel 1a: GEMM1 u/v columns (fp16 1-term) ----------------
__global__ __launch_bounds__(256, 2)
void k_gemm1uv()
{
    float acc[4][4][4] = {};
    const int rowBase = blockIdx.y * 128, colBase = blockIdx.x * 128;
    mma_gemm_1t(g_H16, HID, g_Wi16, NCOLS, HID, rowBase, colBase, acc);
    EPI_SETUP();
    #pragma unroll
    for (int mi = 0; mi < 4; mi++)
        #pragma unroll
        for (int ng = 0; ng < 4; ng++) {
            int r0 = rowBase + wm * 64 + mi * 16 + er;
            int c0 = colBase + wn * 32 + ng * 8 + ec;
            #pragma unroll
            for (int h = 0; h < 2; h++) {
                int row = r0 + h * 8;
                #pragma unroll
                for (int j = 0; j < 2; j++) {
                    int col = c0 + j;
                    float x = acc[mi][ng][h * 2 + j];
                    float v = x / (1.0f + __expf(-x));  // SiLU
                    if (col < INTER)
                        g_u16[(size_t)row * INTER + col] =
                            __half_as_ushort(__float2half_rn(v));
                    else
                        g_v16[(size_t)row * INTER + (col - INTER)] =
                            __half_as_ushort(__float2half_rn(v));
                }
            }
        }
}

// ---------------- kernel 1b: GEMM1 qk columns (bf16x3) ----------------------
__global__ __launch_bounds__(256, 2)
void k_gemm1qk(const float* __restrict__ qg, const float* __restrict__ kg)
{
    float acc[4][4][4] = {};
    const int rowBase = blockIdx.y * 128, colBase = 2 * INTER;
    mma_gemm_pk<false>(g_Hh, g_Hl, HID, g_Wih, g_Wil, NCOLS, HID, rowBase, colBase, acc);
    EPI_SETUP();
    #pragma unroll
    for (int mi = 0; mi < 4; mi++)
        #pragma unroll
        for (int ng = 0; ng < 4; ng++) {
            int r0 = rowBase + wm * 64 + mi * 16 + er;
            int c0 = wn * 32 + ng * 8 + ec;
            #pragma unroll
            for (int h = 0; h < 2; h++) {
                int row = r0 + h * 8;
                #pragma unroll
                for (int j = 0; j < 2; j++) {
                    int c = c0 + j;
                    float x = acc[mi][ng][h * 2 + j];
                    float v = x / (1.0f + __expf(-x));  // SiLU
                    size_t idx = (size_t)row * DK + c;
                    float sq = qg[c] * kg[c] * 0.08838834764831845f;
                    splitf(v * sq, g_qh[idx], g_ql[idx]);
                    splitf(v,      g_kh[idx], g_kl[idx]);
                }
            }
        }
}

// ---------------- kernel 2: Q' @ K'^T, symmetric (lower triangle) -----------
__global__ __launch_bounds__(256, 2)
void k_qk()
{
    extern __shared__ __align__(16) uint4 smdyn[];
    float acc[4][4][4] = {};
    const int b = blockIdx.z;
    int t = blockIdx.x;
    int ty = (int)((__fsqrt_rn(8.f * t + 1.f) - 1.f) * 0.5f);
    while ((ty + 1) * (ty + 2) / 2 <= t) ty++;
    while (ty * (ty + 1) / 2 > t) ty--;
    int tx = t - ty * (ty + 1) / 2;
    const int rowBase = ty * 128, colBase = tx * 128;

    const size_t o = (size_t)b * SEQ * DK;
    mma_gemm_pk<true>(g_qh + o, g_ql + o, DK, g_kh + o, g_kl + o, DK,
                      DK, rowBase, colBase, acc);
    float* Ab = g_A + (size_t)b * SEQ * SEQ;

    __syncthreads();
    float* sT = (float*)smdyn;
    EPI_SETUP();
    #pragma unroll
    for (int mi = 0; mi < 4; mi++)
        #pragma unroll
        for (int ng = 0; ng < 4; ng++) {
            int r = wm * 64 + mi * 16 + er;
            int c = wn * 32 + ng * 8 + ec;
            sT[r * 129 + c]           = acc[mi][ng][0];
            sT[r * 129 + c + 1]       = acc[mi][ng][1];
            sT[(r + 8) * 129 + c]     = acc[mi][ng][2];
            sT[(r + 8) * 129 + c + 1] = acc[mi][ng][3];
        }
    __syncthreads();

    const int tid = threadIdx.x;
    const int r2 = tid >> 1, half = tid & 1;
    #pragma unroll
    for (int cc = 0; cc < 16; cc++) {
        int c = half * 64 + cc * 4;
        float4 v;
        v.x = sT[r2 * 129 + c];     v.y = sT[r2 * 129 + c + 1];
        v.z = sT[r2 * 129 + c + 2]; v.w = sT[r2 * 129 + c + 3];
        *(float4*)&Ab[(size_t)(rowBase + r2) * SEQ + colBase + c] = v;
    }
    if (ty != tx) {
        #pragma unroll
        for (int cc = 0; cc < 16; cc++) {
            int c = half * 64 + cc * 4;
            float4 v;
            v.x = sT[c * 129 + r2];       v.y = sT[(c + 1) * 129 + r2];
            v.z = sT[(c + 2) * 129 + r2]; v.w = sT[(c + 3) * 129 + r2];
            *(float4*)&Ab[(size_t)(colBase + r2) * SEQ + rowBase + c] = v;
        }
    }
}

// ---------------- kernel 3: masked softmax (inline mask count) --------------
__global__ __launch_bounds__(256)
void k_softmax(const int* __restrict__ mask)
{
    const int bm = blockIdx.x;
    const int b = bm >> 11;
    const int m = bm & (SEQ - 1);
    const int tid = threadIdx.x;
    const int lane = tid & 31, wrp = tid >> 5;

    __shared__ float redm[8], redc[8], reds[8];
    const size_t rowoff = (size_t)b * SEQ * SEQ + (size_t)m * SEQ;
    const float* row = g_A + rowoff;

    float a[8];
    float mx = -3.4e38f, cnt = 0.f;
    #pragma unroll
    for (int k2 = 0; k2 < 8; k2++) {
        int n = tid + k2 * 256;
        float x = row[n];
        int mv = mask[b * SEQ + n];
        cnt += (float)mv;
        if (mv == 0) x = -1e12f;
        a[k2] = x;
        mx = fmaxf(mx, x);
    }
    #pragma unroll
    for (int s = 16; s > 0; s >>= 1) {
        mx = fmaxf(mx, __shfl_xor_sync(0xffffffffu, mx, s));
        cnt += __shfl_xor_sync(0xffffffffu, cnt, s);
    }
    if (lane == 0) { redm[wrp] = mx; redc[wrp] = cnt; }
    __syncthreads();
    mx = redm[lane & 7]; cnt = redc[lane & 7];
    #pragma unroll
    for (int s = 4; s > 0; s >>= 1) {
        mx = fmaxf(mx, __shfl_xor_sync(0xffffffffu, mx, s));
        cnt += __shfl_xor_sync(0xffffffffu, cnt, s);
    }
    const float scale = logf(fmaxf(cnt, 1.0f)) * (1.0f / LOG512F);
    const float mxs = mx * scale;

    float sm = 0.f;
    #pragma unroll
    for (int k2 = 0; k2 < 8; k2++) {
        float e = __expf(a[k2] * scale - mxs);
        a[k2] = e;
        sm += e;
    }
    #pragma unroll
    for (int s = 16; s > 0; s >>= 1)
        sm += __shfl_xor_sync(0xffffffffu, sm, s);
    if (lane == 0) reds[wrp] = sm;
    __syncthreads();
    sm = reds[lane & 7];
    #pragma unroll
    for (int s = 4; s > 0; s >>= 1)
        sm += __shfl_xor_sync(0xffffffffu, sm, s);
    const float inv = 1.0f / sm;

    #pragma unroll
    for (int k2 = 0; k2 < 8; k2++) {
        int n = tid + k2 * 256;
        g_A16[rowoff + n] = __half_as_ushort(__float2half_rn(a[k2] * inv));
    }
}

// ---------------- kernel 4: (A @ V) * u  (fp16 single-term) -----------------
__global__ __launch_bounds__(256, 2)
void k_av()
{
    float acc[4][4][4] = {};
    const int b = blockIdx.z;
    const int rowBase = blockIdx.y * 128, colBase = blockIdx.x * 128;
    const size_t oa = (size_t)b * SEQ * SEQ;
    const size_t ov = (size_t)b * SEQ * INTER;
    mma_gemm_1t(g_A16 + oa, SEQ, g_v16 + ov, INTER,
                SEQ, rowBase, colBase, acc);
    EPI_SETUP();
    #pragma unroll
    for (int mi = 0; mi < 4; mi++)
        #pragma unroll
        for (int ng = 0; ng < 4; ng++) {
            int r0 = rowBase + wm * 64 + mi * 16 + er;
            int c0 = colBase + wn * 32 + ng * 8 + ec;
            #pragma unroll
            for (int h = 0; h < 2; h++) {
                int row = r0 + h * 8;
                size_t base = ((size_t)(b * SEQ + row)) * INTER + c0;
                __half2 u2 = *(const __half2*)&g_u16[base];
                g_t16[base]     = __half_as_ushort(
                    __float2half_rn(__half2float(__low2half(u2))  * acc[mi][ng][h * 2]));
                g_t16[base + 1] = __half_as_ushort(
                    __float2half_rn(__half2float(__high2half(u2)) * acc[mi][ng][h * 2 + 1]));
            }
        }
}

// ---------------- kernel 5: t @ Wo -> out  (fp16 single-term) ---------------
__global__ __launch_bounds__(256, 2)
void k_out(float* __restrict__ out)
{
    float acc[4][4][4] = {};
    const int rowBase = blockIdx.y * 128, colBase = blockIdx.x * 128;
    mma_gemm_1t(g_t16, INTER, g_Wo16, HID, INTER, rowBase, colBase, acc);
    EPI_SETUP();
    #pragma unroll
    for (int mi = 0; mi < 4; mi++)
        #pragma unroll
        for (int ng = 0; ng < 4; ng++) {
            int r0 = rowBase + wm * 64 + mi * 16 + er;
            int c0 = colBase + wn * 32 + ng * 8 + ec;
            *(float2*)&out[(size_t)r0 * HID + c0] =
                make_float2(acc[mi][ng][0], acc[mi][ng][1]);
            *(float2*)&out[(size_t)(r0 + 8) * HID + c0] =
                make_float2(acc[mi][ng][2], acc[mi][ng][3]);
        }
}

// ---------------- launch ----------------------------------------------------
extern "C" void kernel_launch(void* const* d_in, const int* in_sizes, int n_in,
                              void* d_out, int out_size)
{
    const float* h    = (const float*)d_in[0];
    const float* Wi   = (const float*)d_in[1];
    const float* Wo   = (const float*)d_in[2];
    const float* qg   = (const float*)d_in[3];
    const float* kg   = (const float*)d_in[4];
    const int*   mask = (const int*)d_in[5];
    float*       out  = (float*)d_out;

    cudaFuncSetAttribute(k_gemm1uv, cudaFuncAttributeMaxDynamicSharedMemorySize, GEMM_SMEM1);
    cudaFuncSetAttribute(k_gemm1qk, cudaFuncAttributeMaxDynamicSharedMemorySize, GEMM_SMEM);
    cudaFuncSetAttribute(k_qk,      cudaFuncAttributeMaxDynamicSharedMemorySize, GEMM_SMEM);
    cudaFuncSetAttribute(k_av,      cudaFuncAttributeMaxDynamicSharedMemorySize, GEMM_SMEM1);
    cudaFuncSetAttribute(k_out,     cudaFuncAttributeMaxDynamicSharedMemorySize, GEMM_SMEM1);

    k_split<<<(N4TOT + 255) / 256, 256>>>((const float4*)h, (const float4*)Wi,
                                          (const float4*)Wo);

    k_gemm1uv<<<dim3(2 * INTER / 128, MTOT / 128), 256, GEMM_SMEM1>>>();
    k_gemm1qk<<<dim3(1, MTOT / 128), 256, GEMM_SMEM>>>(qg, kg);
    k_qk<<<dim3(136, 1, BATCH), 256, GEMM_SMEM>>>();
    k_softmax<<<BATCH * SEQ, 256>>>(mask);
    k_av<<<dim3(INTER / 128, SEQ / 128, BATCH), 256, GEMM_SMEM1>>>();
    k_out<<<dim3(HID / 128, MTOT / 128), 256, GEMM_SMEM1>>>(out);
}

// round 16
// speedup vs baseline: 2.3409x; 1.0002x over previous
#include <cuda_runtime.h>
#include <cuda_bf16.h>
#include <cuda_fp16.h>
#include <math.h>

#define HID   768
#define INTER 1536
#define DK    128
#define BATCH 4
#define SEQ   2048
#define MTOT  (BATCH*SEQ)          // 8192
#define NCOLS (2*INTER+DK)         // 3200
#define LOG512F 6.2383246250395075f
#define GEMM_SMEM  (3*4*512*16)    // 96 KB: 3 stages x 4 tiles (bf16x3 pipelined)
#define GEMM_SMEM1 (6*1024*16)     // 96 KB: 6 stages x 2 tiles (fp16 1-term)
#define QK1_SMEM   (4*512*16)      // 32 KB: single-buffered bf16x3 (fp32-direct)

#define N4H  (MTOT*HID/4)
#define N4WI (HID*NCOLS/4)
#define N4WO (INTER*HID/4)
#define N4TOT (N4H+N4WI+N4WO)

typedef unsigned short u16;

// ---------------- scratch (device globals) ---------------------------------
__device__ u16   g_H16[(size_t)MTOT*HID];                               // fp16
__device__ u16   g_Wi16[(size_t)HID*NCOLS];                             // fp16
__device__ u16   g_Wo16[(size_t)INTER*HID];                             // fp16
__device__ u16   g_u16[(size_t)MTOT*INTER];                             // fp16 gate
__device__ u16   g_v16[(size_t)MTOT*INTER];                             // fp16 value
__device__ u16   g_qh[(size_t)MTOT*DK],    g_ql[(size_t)MTOT*DK];      // bf16
__device__ u16   g_kh[(size_t)MTOT*DK],    g_kl[(size_t)MTOT*DK];      // bf16
__device__ float g_A [(size_t)BATCH*SEQ*SEQ];
__device__ u16   g_A16[(size_t)BATCH*SEQ*SEQ];                          // fp16 probs
__device__ u16   g_t16[(size_t)MTOT*INTER];                             // fp16 gated

// ---------------- PTX helpers ----------------------------------------------
__device__ __forceinline__ void mma_bf16(float c[4], const unsigned a[4], const unsigned b[2]) {
    asm volatile(
        "mma.sync.aligned.m16n8k16.row.col.f32.bf16.bf16.f32 "
        "{%0,%1,%2,%3}, {%4,%5,%6,%7}, {%8,%9}, {%0,%1,%2,%3};\n"
        : "+f"(c[0]), "+f"(c[1]), "+f"(c[2]), "+f"(c[3])
        : "r"(a[0]), "r"(a[1]), "r"(a[2]), "r"(a[3]), "r"(b[0]), "r"(b[1]));
}
__device__ __forceinline__ void mma_f16(float c[4], const unsigned a[4], const unsigned b[2]) {
    asm volatile(
        "mma.sync.aligned.m16n8k16.row.col.f32.f16.f16.f32 "
        "{%0,%1,%2,%3}, {%4,%5,%6,%7}, {%8,%9}, {%0,%1,%2,%3};\n"
        : "+f"(c[0]), "+f"(c[1]), "+f"(c[2]), "+f"(c[3])
        : "r"(a[0]), "r"(a[1]), "r"(a[2]), "r"(a[3]), "r"(b[0]), "r"(b[1]));
}
__device__ __forceinline__ void ldsm4(unsigned r[4], unsigned addr) {
    asm volatile("ldmatrix.sync.aligned.m8n8.x4.shared.b16 {%0,%1,%2,%3}, [%4];\n"
        : "=r"(r[0]), "=r"(r[1]), "=r"(r[2]), "=r"(r[3]) : "r"(addr));
}
__device__ __forceinline__ void ldsm4t(unsigned r[4], unsigned addr) {
    asm volatile("ldmatrix.sync.aligned.m8n8.x4.trans.shared.b16 {%0,%1,%2,%3}, [%4];\n"
        : "=r"(r[0]), "=r"(r[1]), "=r"(r[2]), "=r"(r[3]) : "r"(addr));
}
__device__ __forceinline__ void cp16(void* dst, const void* src) {
    unsigned d = (unsigned)__cvta_generic_to_shared(dst);
    asm volatile("cp.async.cg.shared.global [%0], [%1], 16;\n" :: "r"(d), "l"(src));
}
__device__ __forceinline__ void splitf(float x, u16& h, u16& l) {     // bf16 hi/lo
    __nv_bfloat16 hb = __float2bfloat16(x);
    h = __bfloat16_as_ushort(hb);
    l = __bfloat16_as_ushort(__float2bfloat16(x - __bfloat162float(hb)));
}
__device__ __forceinline__ void pack8(const float f[8], uint4& H, uint4& L) {
    unsigned h[8], l[8];
    #pragma unroll
    for (int j = 0; j < 8; j++) {
        u16 hh, ll;
        splitf(f[j], hh, ll);
        h[j] = hh; l[j] = ll;
    }
    H.x = h[0] | (h[1] << 16); H.y = h[2] | (h[3] << 16);
    H.z = h[4] | (h[5] << 16); H.w = h[6] | (h[7] << 16);
    L.x = l[0] | (l[1] << 16); L.y = l[2] | (l[3] << 16);
    L.z = l[4] | (l[5] << 16); L.w = l[6] | (l[7] << 16);
}

// ---------------- tile stagers (cp.async, 256 threads) ----------------------
__device__ __forceinline__ void stage_tileA(uint4* dst, const u16* __restrict__ g,
                                            int ld, int tid) {
    #pragma unroll
    for (int r = 0; r < 2; r++) {
        int c = tid + r * 256;
        int row = c >> 2, kc = c & 3;
        cp16(dst + row * 4 + (kc ^ ((row >> 1) & 3)),
             g + (size_t)row * ld + kc * 8);
    }
}
__device__ __forceinline__ void stage_tileB(uint4* dst, const u16* __restrict__ g,
                                            int ld, int tid) {
    #pragma unroll
    for (int r = 0; r < 2; r++) {
        int c = tid + r * 256;
        int k = c >> 4, nc = c & 15;
        cp16(dst + k * 16 + (nc ^ (k & 7)),
             g + (size_t)k * ld + nc * 8);
    }
}

#define EPI_SETUP() \
    const int lane = threadIdx.x & 31, w = threadIdx.x >> 5; \
    const int wm = w >> 2, wn = w & 3; \
    const int er = lane >> 2, ec = (lane & 3) * 2;

// ---------------- bf16x3 GEMM body (qk matmul, 3-stage, BT) -----------------
__device__ __forceinline__ void mma_gemm_pk_bt(const u16* __restrict__ Ah, const u16* __restrict__ Al,
                                               const u16* __restrict__ Bh, const u16* __restrict__ Bl,
                                               int ld, int K, int rowBase, int colBase,
                                               float acc[4][4][4])
{
    extern __shared__ __align__(16) uint4 smdyn[];
    const int tid = threadIdx.x;
    const int lane = tid & 31, w = tid >> 5;
    const int wm = w >> 2, wn = w & 3;
    const int g = lane >> 3, i = lane & 7;
    const int nsteps = K / 32;

    auto issue = [&](int step) {
        uint4* st = smdyn + (step % 3) * 2048;
        int k0 = step * 32;
        stage_tileA(st,        Ah + (size_t)rowBase * ld + k0, ld, tid);
        stage_tileA(st + 512,  Al + (size_t)rowBase * ld + k0, ld, tid);
        stage_tileA(st + 1024, Bh + (size_t)colBase * ld + k0, ld, tid);
        stage_tileA(st + 1536, Bl + (size_t)colBase * ld + k0, ld, tid);
        asm volatile("cp.async.commit_group;\n");
    };

    issue(0);
    if (nsteps > 1) issue(1);
    for (int step = 0; step < nsteps; step++) {
        if (step + 1 < nsteps)
            asm volatile("cp.async.wait_group 1;\n");
        else
            asm volatile("cp.async.wait_group 0;\n");
        __syncthreads();

        const uint4* st = smdyn + (step % 3) * 2048;
        const unsigned bAh = (unsigned)__cvta_generic_to_shared(st);
        const unsigned bAl = bAh + 8192;
        const unsigned bBh = bAh + 16384;
        const unsigned bBl = bAh + 24576;

        #pragma unroll
        for (int ks = 0; ks < 32; ks += 16) {
            unsigned aH[4][4], aL[4][4];
            #pragma unroll
            for (int mi = 0; mi < 4; mi++) {
                int mrow = wm * 64 + mi * 16 + (g & 1) * 8 + i;
                int ch = (ks >> 3) + (g >> 1);
                int off = mrow * 64 + ((ch ^ ((mrow >> 1) & 3)) << 4);
                ldsm4(aH[mi], bAh + off);
                ldsm4(aL[mi], bAl + off);
            }
            unsigned bH[4][2], bL[4][2];
            #pragma unroll
            for (int p = 0; p < 2; p++) {
                unsigned rh[4], rl[4];
                int nrow = wn * 32 + p * 16 + (g >> 1) * 8 + i;
                int ch = (ks >> 3) + (g & 1);
                int off = nrow * 64 + ((ch ^ ((nrow >> 1) & 3)) << 4);
                ldsm4(rh, bBh + off);
                ldsm4(rl, bBl + off);
                bH[2*p][0] = rh[0]; bH[2*p][1] = rh[1];
                bH[2*p+1][0] = rh[2]; bH[2*p+1][1] = rh[3];
                bL[2*p][0] = rl[0]; bL[2*p][1] = rl[1];
                bL[2*p+1][0] = rl[2]; bL[2*p+1][1] = rl[3];
            }
            #pragma unroll
            for (int mi = 0; mi < 4; mi++)
                #pragma unroll
                for (int ng = 0; ng < 4; ng++)
                    mma_bf16(acc[mi][ng], aH[mi], bH[ng]);
            #pragma unroll
            for (int mi = 0; mi < 4; mi++)
                #pragma unroll
                for (int ng = 0; ng < 4; ng++)
                    mma_bf16(acc[mi][ng], aH[mi], bL[ng]);
            #pragma unroll
            for (int mi = 0; mi < 4; mi++)
                #pragma unroll
                for (int ng = 0; ng < 4; ng++)
                    mma_bf16(acc[mi][ng], aL[mi], bH[ng]);
        }
        if (step + 2 < nsteps) issue(step + 2);
    }
}

// ---------------- fp16 single-term GEMM body (6-stage) ----------------------
__device__ __forceinline__ void mma_gemm_1t(const u16* __restrict__ Aa, int lda,
                                            const u16* __restrict__ Bb, int ldb,
                                            int K, int rowBase, int colBase,
                                            float acc[4][4][4])
{
    extern __shared__ __align__(16) uint4 smdyn[];
    const int tid = threadIdx.x;
    const int lane = tid & 31, w = tid >> 5;
    const int wm = w >> 2, wn = w & 3;
    const int g = lane >> 3, i = lane & 7;
    const int nsteps = K / 32;

    auto issue = [&](int step) {
        uint4* st = smdyn + (step % 6) * 1024;
        int k0 = step * 32;
        stage_tileA(st,       Aa + (size_t)rowBase * lda + k0, lda, tid);
        stage_tileB(st + 512, Bb + (size_t)k0 * ldb + colBase, ldb, tid);
        asm volatile("cp.async.commit_group;\n");
    };

    issue(0); issue(1);
    if (nsteps > 2) issue(2);
    if (nsteps > 3) issue(3);

    for (int p = 0; p < nsteps; p += 2) {
        if (p + 4 <= nsteps)
            asm volatile("cp.async.wait_group 2;\n");
        else
            asm volatile("cp.async.wait_group 0;\n");
        __syncthreads();
        if (p + 4 < nsteps) {
            issue(p + 4);
            if (p + 5 < nsteps) issue(p + 5);
        }
        #pragma unroll
        for (int sub = 0; sub < 2; sub++) {
            const uint4* st = smdyn + ((p + sub) % 6) * 1024;
            const unsigned bA = (unsigned)__cvta_generic_to_shared(st);
            const unsigned bB = bA + 8192;
            #pragma unroll
            for (int ks = 0; ks < 32; ks += 16) {
                unsigned aF[4][4];
                #pragma unroll
                for (int mi = 0; mi < 4; mi++) {
                    int mrow = wm * 64 + mi * 16 + (g & 1) * 8 + i;
                    int ch = (ks >> 3) + (g >> 1);
                    int off = mrow * 64 + ((ch ^ ((mrow >> 1) & 3)) << 4);
                    ldsm4(aF[mi], bA + off);
                }
                unsigned bF[4][2];
                #pragma unroll
                for (int pp = 0; pp < 2; pp++) {
                    unsigned rh[4];
                    int kr = ks + (g & 1) * 8 + i;
                    int nl = wn * 32 + pp * 16 + (g >> 1) * 8;
                    int off = kr * 256 + ((((nl >> 3) ^ (kr & 7))) << 4);
                    ldsm4t(rh, bB + off);
                    bF[2*pp][0] = rh[0]; bF[2*pp][1] = rh[1];
                    bF[2*pp+1][0] = rh[2]; bF[2*pp+1][1] = rh[3];
                }
                #pragma unroll
                for (int mi = 0; mi < 4; mi++)
                    #pragma unroll
                    for (int ng = 0; ng < 4; ng++)
                        mma_f16(acc[mi][ng], aF[mi], bF[ng]);
            }
        }
    }
}

// ============ merged kernel A: gemm1qk (fp32-direct, bf16x3) || split =======
__global__ __launch_bounds__(256)
void k_qk1_split(const float4* __restrict__ Hf4, const float4* __restrict__ Wif4,
                 const float4* __restrict__ Wof4,
                 const float* __restrict__ qg, const float* __restrict__ kg)
{
    extern __shared__ __align__(16) uint4 smdyn[];
    const int tid = threadIdx.x;

    if (blockIdx.x < 64) {
        // ------- gemm1qk: rows [bid*128, +128), cols [2*INTER, +128), fp32 in
        const float* H  = (const float*)Hf4;
        const float* Wi = (const float*)Wif4;
        const int rowBase = blockIdx.x * 128;
        const int colBase = 2 * INTER;
        uint4* sAh = smdyn;        uint4* sAl = smdyn + 512;
        uint4* sBh = smdyn + 1024; uint4* sBl = smdyn + 1536;
        const int lane = tid & 31, wr = tid >> 5;
        const int wm = wr >> 2, wn = wr & 3;
        const int g = lane >> 3, ii = lane & 7;
        float acc[4][4][4] = {};

        for (int c = 0; c < HID / 32; c++) {
            int k0 = c * 32;
            __syncthreads();
            // stage A (H rows x 32 k, fp32 -> bf16 hi/lo, swizzled)
            #pragma unroll
            for (int r = 0; r < 2; r++) {
                int gi = tid + r * 256;
                int row = gi >> 2, kc = gi & 3;
                const float* p = H + (size_t)(rowBase + row) * HID + k0 + kc * 8;
                float4 f0 = *(const float4*)p, f1 = *(const float4*)(p + 4);
                float fa[8] = {f0.x, f0.y, f0.z, f0.w, f1.x, f1.y, f1.z, f1.w};
                uint4 Hv, Lv; pack8(fa, Hv, Lv);
                int cc = kc ^ ((row >> 1) & 3);
                sAh[row * 4 + cc] = Hv; sAl[row * 4 + cc] = Lv;
            }
            // stage B (Wi 32 k-rows x 128 n, fp32 -> bf16 hi/lo, swizzled)
            #pragma unroll
            for (int r = 0; r < 2; r++) {
                int gi = tid + r * 256;
                int k = gi >> 4, nc = gi & 15;
                const float* p = Wi + (size_t)(k0 + k) * NCOLS + colBase + nc * 8;
                float4 f0 = *(const float4*)p, f1 = *(const float4*)(p + 4);
                float fa[8] = {f0.x, f0.y, f0.z, f0.w, f1.x, f1.y, f1.z, f1.w};
                uint4 Hv, Lv; pack8(fa, Hv, Lv);
                int cc = nc ^ (k & 7);
                sBh[k * 16 + cc] = Hv; sBl[k * 16 + cc] = Lv;
            }
            __syncthreads();

            const unsigned bAh = (unsigned)__cvta_generic_to_shared(sAh);
            const unsigned bAl = bAh + 8192;
            const unsigned bBh = bAh + 16384;
            const unsigned bBl = bAh + 24576;
            #pragma unroll
            for (int ks = 0; ks < 32; ks += 16) {
                unsigned aH[4][4], aL[4][4];
                #pragma unroll
                for (int mi = 0; mi < 4; mi++) {
                    int mrow = wm * 64 + mi * 16 + (g & 1) * 8 + ii;
                    int ch = (ks >> 3) + (g >> 1);
                    int off = mrow * 64 + ((ch ^ ((mrow >> 1) & 3)) << 4);
                    ldsm4(aH[mi], bAh + off);
                    ldsm4(aL[mi], bAl + off);
                }
                unsigned bH[4][2], bL[4][2];
                #pragma unroll
                for (int p = 0; p < 2; p++) {
                    unsigned rh[4], rl[4];
                    int kr = ks + (g & 1) * 8 + ii;
                    int nl = wn * 32 + p * 16 + (g >> 1) * 8;
                    int off = kr * 256 + ((((nl >> 3) ^ (kr & 7))) << 4);
                    ldsm4t(rh, bBh + off);
                    ldsm4t(rl, bBl + off);
                    bH[2*p][0] = rh[0]; bH[2*p][1] = rh[1];
                    bH[2*p+1][0] = rh[2]; bH[2*p+1][1] = rh[3];
                    bL[2*p][0] = rl[0]; bL[2*p][1] = rl[1];
                    bL[2*p+1][0] = rl[2]; bL[2*p+1][1] = rl[3];
                }
                #pragma unroll
                for (int mi = 0; mi < 4; mi++)
                    #pragma unroll
                    for (int ng = 0; ng < 4; ng++)
                        mma_bf16(acc[mi][ng], aH[mi], bH[ng]);
                #pragma unroll
                for (int mi = 0; mi < 4; mi++)
                    #pragma unroll
                    for (int ng = 0; ng < 4; ng++)
                        mma_bf16(acc[mi][ng], aH[mi], bL[ng]);
                #pragma unroll
                for (int mi = 0; mi < 4; mi++)
                    #pragma unroll
                    for (int ng = 0; ng < 4; ng++)
                        mma_bf16(acc[mi][ng], aL[mi], bH[ng]);
            }
        }
        // epilogue: SiLU + q/k splits
        const int er = lane >> 2, ec = (lane & 3) * 2;
        #pragma unroll
        for (int mi = 0; mi < 4; mi++)
            #pragma unroll
            for (int ng = 0; ng < 4; ng++) {
                int r0 = rowBase + wm * 64 + mi * 16 + er;
                int c0 = wn * 32 + ng * 8 + ec;
                #pragma unroll
                for (int h = 0; h < 2; h++) {
                    int row = r0 + h * 8;
                    #pragma unroll
                    for (int j = 0; j < 2; j++) {
                        int cch = c0 + j;
                        float x = acc[mi][ng][h * 2 + j];
                        float v = x / (1.0f + __expf(-x));
                        size_t idx = (size_t)row * DK + cch;
                        float sq = qg[cch] * kg[cch] * 0.08838834764831845f;
                        splitf(v * sq, g_qh[idx], g_ql[idx]);
                        splitf(v,      g_kh[idx], g_kl[idx]);
                    }
                }
            }
    } else {
        // ------- split: fp32 -> fp16 for H, Wi, Wo
        int i = (blockIdx.x - 64) * 256 + tid;
        if (i >= N4TOT) return;
        ushort4 F;
        if (i < N4H) {
            float4 f = Hf4[i];
            F.x = __half_as_ushort(__float2half_rn(f.x));
            F.y = __half_as_ushort(__float2half_rn(f.y));
            F.z = __half_as_ushort(__float2half_rn(f.z));
            F.w = __half_as_ushort(__float2half_rn(f.w));
            ((ushort4*)g_H16)[i] = F;
        } else if (i < N4H + N4WI) {
            int j = i - N4H;
            float4 f = Wif4[j];
            F.x = __half_as_ushort(__float2half_rn(f.x));
            F.y = __half_as_ushort(__float2half_rn(f.y));
            F.z = __half_as_ushort(__float2half_rn(f.z));
            F.w = __half_as_ushort(__float2half_rn(f.w));
            ((ushort4*)g_Wi16)[j] = F;
        } else {
            int j = i - N4H - N4WI;
            float4 f = Wof4[j];
            F.x = __half_as_ushort(__float2half_rn(f.x));
            F.y = __half_as_ushort(__float2half_rn(f.y));
            F.z = __half_as_ushort(__float2half_rn(f.z));
            F.w = __half_as_ushort(__float2half_rn(f.w));
            ((ushort4*)g_Wo16)[j] = F;
        }
    }
}

// ============ merged kernel B: qk matmul (symmetric) || gemm1 u/v ===========
__global__ __launch_bounds__(256, 2)
void k_qkmm_uv()
{
    extern __shared__ __align__(16) uint4 smdyn[];
    if (blockIdx.x < 544) {
        // ------- qk: symmetric lower-triangle tile
        float acc[4][4][4] = {};
        const int b = blockIdx.x / 136;
        int t = blockIdx.x % 136;
        int ty = (int)((__fsqrt_rn(8.f * t + 1.f) - 1.f) * 0.5f);
        while ((ty + 1) * (ty + 2) / 2 <= t) ty++;
        while (ty * (ty + 1) / 2 > t) ty--;
        int tx = t - ty * (ty + 1) / 2;
        const int rowBase = ty * 128, colBase = tx * 128;

        const size_t o = (size_t)b * SEQ * DK;
        mma_gemm_pk_bt(g_qh + o, g_ql + o, g_kh + o, g_kl + o, DK,
                       DK, rowBase, colBase, acc);
        float* Ab = g_A + (size_t)b * SEQ * SEQ;

        __syncthreads();
        float* sT = (float*)smdyn;
        EPI_SETUP();
        #pragma unroll
        for (int mi = 0; mi < 4; mi++)
            #pragma unroll
            for (int ng = 0; ng < 4; ng++) {
                int r = wm * 64 + mi * 16 + er;
                int c = wn * 32 + ng * 8 + ec;
                sT[r * 129 + c]           = acc[mi][ng][0];
                sT[r * 129 + c + 1]       = acc[mi][ng][1];
                sT[(r + 8) * 129 + c]     = acc[mi][ng][2];
                sT[(r + 8) * 129 + c + 1] = acc[mi][ng][3];
            }
        __syncthreads();

        const int tid = threadIdx.x;
        const int r2 = tid >> 1, half = tid & 1;
        #pragma unroll
        for (int cc = 0; cc < 16; cc++) {
            int c = half * 64 + cc * 4;
            float4 v;
            v.x = sT[r2 * 129 + c];     v.y = sT[r2 * 129 + c + 1];
            v.z = sT[r2 * 129 + c + 2]; v.w = sT[r2 * 129 + c + 3];
            *(float4*)&Ab[(size_t)(rowBase + r2) * SEQ + colBase + c] = v;
        }
        if (ty != tx) {
            #pragma unroll
            for (int cc = 0; cc < 16; cc++) {
                int c = half * 64 + cc * 4;
                float4 v;
                v.x = sT[c * 129 + r2];       v.y = sT[(c + 1) * 129 + r2];
                v.z = sT[(c + 2) * 129 + r2]; v.w = sT[(c + 3) * 129 + r2];
                *(float4*)&Ab[(size_t)(colBase + r2) * SEQ + rowBase + c] = v;
            }
        }
    } else {
        // ------- gemm1 u/v columns (fp16 1-term)
        int e = blockIdx.x - 544;
        const int rowBase = (e / 24) * 128, colBase = (e % 24) * 128;
        float acc[4][4][4] = {};
        mma_gemm_1t(g_H16, HID, g_Wi16, NCOLS, HID, rowBase, colBase, acc);
        EPI_SETUP();
        #pragma unroll
        for (int mi = 0; mi < 4; mi++)
            #pragma unroll
            for (int ng = 0; ng < 4; ng++) {
                int r0 = rowBase + wm * 64 + mi * 16 + er;
                int c0 = colBase + wn * 32 + ng * 8 + ec;
                #pragma unroll
                for (int h = 0; h < 2; h++) {
                    int row = r0 + h * 8;
                    #pragma unroll
                    for (int j = 0; j < 2; j++) {
                        int col = c0 + j;
                        float x = acc[mi][ng][h * 2 + j];
                        float v = x / (1.0f + __expf(-x));
                        if (col < INTER)
                            g_u16[(size_t)row * INTER + col] =
                                __half_as_ushort(__float2half_rn(v));
                        else
                            g_v16[(size_t)row * INTER + (col - INTER)] =
                                __half_as_ushort(__float2half_rn(v));
                    }
                }
            }
    }
}

// ---------------- kernel 3: masked softmax (inline mask count) --------------
__global__ __launch_bounds__(256)
void k_softmax(const int* __restrict__ mask)
{
    const int bm = blockIdx.x;
    const int b = bm >> 11;
    const int m = bm & (SEQ - 1);
    const int tid = threadIdx.x;
    const int lane = tid & 31, wrp = tid >> 5;

    __shared__ float redm[8], redc[8], reds[8];
    const size_t rowoff = (size_t)b * SEQ * SEQ + (size_t)m * SEQ;
    const float* row = g_A + rowoff;

    float a[8];
    float mx = -3.4e38f, cnt = 0.f;
    #pragma unroll
    for (int k2 = 0; k2 < 8; k2++) {
        int n = tid + k2 * 256;
        float x = row[n];
        int mv = mask[b * SEQ + n];
        cnt += (float)mv;
        if (mv == 0) x = -1e12f;
        a[k2] = x;
        mx = fmaxf(mx, x);
    }
    #pragma unroll
    for (int s = 16; s > 0; s >>= 1) {
        mx = fmaxf(mx, __shfl_xor_sync(0xffffffffu, mx, s));
        cnt += __shfl_xor_sync(0xffffffffu, cnt, s);
    }
    if (lane == 0) { redm[wrp] = mx; redc[wrp] = cnt; }
    __syncthreads();
    mx = redm[lane & 7]; cnt = redc[lane & 7];
    #pragma unroll
    for (int s = 4; s > 0; s >>= 1) {
        mx = fmaxf(mx, __shfl_xor_sync(0xffffffffu, mx, s));
        cnt += __shfl_xor_sync(0xffffffffu, cnt, s);
    }
    const float scale = logf(fmaxf(cnt, 1.0f)) * (1.0f / LOG512F);
    const float mxs = mx * scale;

    float sm = 0.f;
    #pragma unroll
    for (int k2 = 0; k2 < 8; k2++) {
        float e = __expf(a[k2] * scale - mxs);
        a[k2] = e;
        sm += e;
    }
    #pragma unroll
    for (int s = 16; s > 0; s >>= 1)
        sm += __shfl_xor_sync(0xffffffffu, sm, s);
    if (lane == 0) reds[wrp] = sm;
    __syncthreads();
    sm = reds[lane & 7];
    #pragma unroll
    for (int s = 4; s > 0; s >>= 1)
        sm += __shfl_xor_sync(0xffffffffu, sm, s);
    const float inv = 1.0f / sm;

    #pragma unroll
    for (int k2 = 0; k2 < 8; k2++) {
        int n = tid + k2 * 256;
        g_A16[rowoff + n] = __half_as_ushort(__float2half_rn(a[k2] * inv));
    }
}

// ---------------- kernel 4: (A @ V) * u  (fp16 single-term) -----------------
__global__ __launch_bounds__(256, 2)
void k_av()
{
    float acc[4][4][4] = {};
    const int b = blockIdx.z;
    const int rowBase = blockIdx.y * 128, colBase = blockIdx.x * 128;
    const size_t oa = (size_t)b * SEQ * SEQ;
    const size_t ov = (size_t)b * SEQ * INTER;
    mma_gemm_1t(g_A16 + oa, SEQ, g_v16 + ov, INTER,
                SEQ, rowBase, colBase, acc);
    EPI_SETUP();
    #pragma unroll
    for (int mi = 0; mi < 4; mi++)
        #pragma unroll
        for (int ng = 0; ng < 4; ng++) {
            int r0 = rowBase + wm * 64 + mi * 16 + er;
            int c0 = colBase + wn * 32 + ng * 8 + ec;
            #pragma unroll
            for (int h = 0; h < 2; h++) {
                int row = r0 + h * 8;
                size_t base = ((size_t)(b * SEQ + row)) * INTER + c0;
                __half2 u2 = *(const __half2*)&g_u16[base];
                g_t16[base]     = __half_as_ushort(
                    __float2half_rn(__half2float(__low2half(u2))  * acc[mi][ng][h * 2]));
                g_t16[base + 1] = __half_as_ushort(
                    __float2half_rn(__half2float(__high2half(u2)) * acc[mi][ng][h * 2 + 1]));
            }
        }
}

// ---------------- kernel 5: t @ Wo -> out  (fp16 single-term) ---------------
__global__ __launch_bounds__(256, 2)
void k_out(float* __restrict__ out)
{
    float acc[4][4][4] = {};
    const int rowBase = blockIdx.y * 128, colBase = blockIdx.x * 128;
    mma_gemm_1t(g_t16, INTER, g_Wo16, HID, INTER, rowBase, colBase, acc);
    EPI_SETUP();
    #pragma unroll
    for (int mi = 0; mi < 4; mi++)
        #pragma unroll
        for (int ng = 0; ng < 4; ng++) {
            int r0 = rowBase + wm * 64 + mi * 16 + er;
            int c0 = colBase + wn * 32 + ng * 8 + ec;
            *(float2*)&out[(size_t)r0 * HID + c0] =
                make_float2(acc[mi][ng][0], acc[mi][ng][1]);
            *(float2*)&out[(size_t)(r0 + 8) * HID + c0] =
                make_float2(acc[mi][ng][2], acc[mi][ng][3]);
        }
}

// ---------------- launch ----------------------------------------------------
extern "C" void kernel_launch(void* const* d_in, const int* in_sizes, int n_in,
                              void* d_out, int out_size)
{
    const float* h    = (const float*)d_in[0];
    const float* Wi   = (const float*)d_in[1];
    const float* Wo   = (const float*)d_in[2];
    const float* qg   = (const float*)d_in[3];
    const float* kg   = (const float*)d_in[4];
    const int*   mask = (const int*)d_in[5];
    float*       out  = (float*)d_out;

    cudaFuncSetAttribute(k_qkmm_uv, cudaFuncAttributeMaxDynamicSharedMemorySize, GEMM_SMEM);
    cudaFuncSetAttribute(k_av,      cudaFuncAttributeMaxDynamicSharedMemorySize, GEMM_SMEM1);
    cudaFuncSetAttribute(k_out,     cudaFuncAttributeMaxDynamicSharedMemorySize, GEMM_SMEM1);

    const int splitBlocks = (N4TOT + 255) / 256;
    k_qk1_split<<<64 + splitBlocks, 256, QK1_SMEM>>>(
        (const float4*)h, (const float4*)Wi, (const float4*)Wo, qg, kg);

    k_qkmm_uv<<<544 + 1536, 256, GEMM_SMEM>>>();
    k_softmax<<<BATCH * SEQ, 256>>>(mask);
    k_av<<<dim3(INTER / 128, SEQ / 128, BATCH), 256, GEMM_SMEM1>>>();
    k_out<<<dim3(HID / 128, MTOT / 128), 256, GEMM_SMEM1>>>(out);
}